// round 6
// baseline (speedup 1.0000x reference)
#include <cuda_runtime.h>
#include <math.h>
#include <stdint.h>

#define BQ 128
#define SS 30
#define HH 768
#define II 3072
#define LL 12
#define NHD 12
#define HD 64
#define EE 15
#define DD 14
#define RR 29
#define LRK 8
#define TN (BQ*SS)        // 3840 tokens
#define ELR (EE*LRK)      // 120
#define SCALF 2.0f

// ---------------- scratch (device globals; no allocation) ----------------
__device__ float g_h[TN*HH];
__device__ float g_nx[TN*HH];
__device__ float g_q[TN*HH];
__device__ float g_k[TN*HH];
__device__ float g_v[TN*HH];
__device__ float g_ctx[TN*HH];
__device__ float g_att[TN*HH];
__device__ float g_res1[TN*HH];
__device__ float g_nres[TN*HH];
__device__ float g_hid[TN*II];
__device__ float g_bout[TN*HH];
__device__ float g_u[TN*ELR];
__device__ float g_vv[TN*ELR];
__device__ float g_t[TN*ELR];
__device__ float g_M[EE*LRK*LRK];
__device__ float g_gate[BQ*DD];

__device__ __forceinline__ float gelu_f(float x) {
    return 0.5f * x * (1.0f + erff(x * 0.70710678118654752f));
}

__device__ __forceinline__ uint32_t f2tf32(float x) {
    uint32_t r;
    asm("cvt.rna.tf32.f32 %0, %1;" : "=r"(r) : "f"(x));
    return r;
}

// ---------------- embed ----------------
__global__ void embed_kernel(const float* __restrict__ rf, const float* __restrict__ cls) {
    int idx = blockIdx.x * 256 + threadIdx.x;
    if (idx >= TN * HH) return;
    int t = idx / HH, j = idx - t * HH;
    int s = t % SS, b = t / SS;
    g_h[idx] = (s == 0) ? cls[j] : rf[(b * RR + (s - 1)) * HH + j];
}

// ---------------- LayerNorm (H=768), optional fused residual add ----------------
__global__ void ln_kernel(const float* __restrict__ a, const float* __restrict__ b,
                          float* __restrict__ res_out, float* __restrict__ norm_out,
                          const float* __restrict__ g, const float* __restrict__ bb,
                          float eps) {
    int t = blockIdx.x;
    int tid = threadIdx.x;
    const float* xa = a + (size_t)t * HH;
    const float* xb = b ? b + (size_t)t * HH : nullptr;
    __shared__ float s1[256], s2[256];
    float xv[3];
    float acc = 0.f, sq = 0.f;
#pragma unroll
    for (int i = 0; i < 3; i++) {
        int j = tid + i * 256;
        float v = xa[j];
        if (xb) v += xb[j];
        xv[i] = v; acc += v; sq += v * v;
        if (res_out) res_out[(size_t)t * HH + j] = v;
    }
    s1[tid] = acc; s2[tid] = sq;
    __syncthreads();
    for (int o = 128; o > 0; o >>= 1) {
        if (tid < o) { s1[tid] += s1[tid + o]; s2[tid] += s2[tid + o]; }
        __syncthreads();
    }
    float mean = s1[0] * (1.0f / 768.0f);
    float var = s2[0] * (1.0f / 768.0f) - mean * mean;
    float r = rsqrtf(var + eps);
#pragma unroll
    for (int i = 0; i < 3; i++) {
        int j = tid + i * 256;
        norm_out[(size_t)t * HH + j] = (xv[i] - mean) * r * g[j] + bb[j];
    }
}

// ---------------- 3xTF32 tensor-core GEMM (error-compensated) ----------------
// C[M,N] = A[M,K] @ W[N,K]^T (+bias)(gelu)(+add)
// BM=128, BN=128, BK=16. 256 threads = 8 warps (2x4), warp tile 64x32.
// Operand split: x = hi + lo (tf32 each); acc += Ah*Wh + Ah*Wl + Al*Wh.
#define PADS 20
__global__ void __launch_bounds__(256, 1)
t3gemm_kernel(const float* __restrict__ A, const float* __restrict__ W,
              const float* __restrict__ bias, const float* __restrict__ add,
              float* __restrict__ C, int N, int K, int act) {
    __shared__ uint32_t Ah[128 * PADS];
    __shared__ uint32_t Al[128 * PADS];
    __shared__ uint32_t Wh[128 * PADS];
    __shared__ uint32_t Wl[128 * PADS];
    int bm = blockIdx.y * 128, bn = blockIdx.x * 128;
    int tid = threadIdx.x;
    int warp = tid >> 5, lane = tid & 31;
    int wm = warp >> 2, wn = warp & 3;       // 2x4 warps
    int gid = lane >> 2, tig = lane & 3;

    int lrow = tid >> 2;                     // 0..63
    int lcol = (tid & 3) << 2;               // 0,4,8,12
    const float* Ap0 = A + (size_t)(bm + lrow) * K + lcol;
    const float* Ap1 = A + (size_t)(bm + lrow + 64) * K + lcol;
    const float* Wp0 = W + (size_t)(bn + lrow) * K + lcol;
    const float* Wp1 = W + (size_t)(bn + lrow + 64) * K + lcol;

    float acc[4][4][4];
#pragma unroll
    for (int i = 0; i < 4; i++)
#pragma unroll
        for (int j = 0; j < 4; j++)
#pragma unroll
            for (int r = 0; r < 4; r++) acc[i][j][r] = 0.f;

    float4 ra0 = *(const float4*)(Ap0);
    float4 ra1 = *(const float4*)(Ap1);
    float4 rw0 = *(const float4*)(Wp0);
    float4 rw1 = *(const float4*)(Wp1);

    for (int k0 = 0; k0 < K; k0 += 16) {
        // split + store current tile
        {
            float va[4];
            uint32_t* dh; uint32_t* dl;
#define SPLIT_STORE(vec)                                                   \
            va[0] = vec.x; va[1] = vec.y; va[2] = vec.z; va[3] = vec.w;    \
            _Pragma("unroll")                                              \
            for (int qq = 0; qq < 4; qq++) {                               \
                uint32_t hi = f2tf32(va[qq]);                              \
                float hif = __uint_as_float(hi);                           \
                uint32_t lo = f2tf32(va[qq] - hif);                        \
                dh[qq] = hi; dl[qq] = lo;                                  \
            }
            dh = &Ah[lrow * PADS + lcol]; dl = &Al[lrow * PADS + lcol];
            SPLIT_STORE(ra0)
            dh = &Ah[(lrow + 64) * PADS + lcol]; dl = &Al[(lrow + 64) * PADS + lcol];
            SPLIT_STORE(ra1)
            dh = &Wh[lrow * PADS + lcol]; dl = &Wl[lrow * PADS + lcol];
            SPLIT_STORE(rw0)
            dh = &Wh[(lrow + 64) * PADS + lcol]; dl = &Wl[(lrow + 64) * PADS + lcol];
            SPLIT_STORE(rw1)
#undef SPLIT_STORE
        }
        __syncthreads();
        if (k0 + 16 < K) {
            ra0 = *(const float4*)(Ap0 + k0 + 16);
            ra1 = *(const float4*)(Ap1 + k0 + 16);
            rw0 = *(const float4*)(Wp0 + k0 + 16);
            rw1 = *(const float4*)(Wp1 + k0 + 16);
        }
#pragma unroll
        for (int ks = 0; ks < 2; ks++) {
            int kb = ks * 8;
            uint32_t afh[4][4], afl[4][4];
            uint32_t bfh[4][2], bfl[4][2];
#pragma unroll
            for (int mt = 0; mt < 4; mt++) {
                int r0 = (wm * 64 + mt * 16 + gid) * PADS + kb + tig;
                afh[mt][0] = Ah[r0];             afl[mt][0] = Al[r0];
                afh[mt][1] = Ah[r0 + 8 * PADS];  afl[mt][1] = Al[r0 + 8 * PADS];
                afh[mt][2] = Ah[r0 + 4];         afl[mt][2] = Al[r0 + 4];
                afh[mt][3] = Ah[r0 + 8 * PADS + 4]; afl[mt][3] = Al[r0 + 8 * PADS + 4];
            }
#pragma unroll
            for (int nt = 0; nt < 4; nt++) {
                int n0 = (wn * 32 + nt * 8 + gid) * PADS + kb + tig;
                bfh[nt][0] = Wh[n0];     bfl[nt][0] = Wl[n0];
                bfh[nt][1] = Wh[n0 + 4]; bfl[nt][1] = Wl[n0 + 4];
            }
#define MMA(AF, BF, mt, nt)                                                    \
            asm volatile(                                                      \
                "mma.sync.aligned.m16n8k8.row.col.f32.tf32.tf32.f32 "          \
                "{%0,%1,%2,%3}, {%4,%5,%6,%7}, {%8,%9}, {%0,%1,%2,%3};"        \
                : "+f"(acc[mt][nt][0]), "+f"(acc[mt][nt][1]),                  \
                  "+f"(acc[mt][nt][2]), "+f"(acc[mt][nt][3])                   \
                : "r"(AF[mt][0]), "r"(AF[mt][1]), "r"(AF[mt][2]), "r"(AF[mt][3]),\
                  "r"(BF[nt][0]), "r"(BF[nt][1]));
#pragma unroll
            for (int mt = 0; mt < 4; mt++)
#pragma unroll
                for (int nt = 0; nt < 4; nt++) {
                    MMA(afl, bfh, mt, nt)
                    MMA(afh, bfl, mt, nt)
                    MMA(afh, bfh, mt, nt)
                }
#undef MMA
        }
        __syncthreads();
    }

    // epilogue
#pragma unroll
    for (int mt = 0; mt < 4; mt++) {
#pragma unroll
        for (int nt = 0; nt < 4; nt++) {
            int row0 = bm + wm * 64 + mt * 16 + gid;
            int col = bn + wn * 32 + nt * 8 + 2 * tig;
#pragma unroll
            for (int half = 0; half < 2; half++) {
                int row = row0 + half * 8;
                float v0 = acc[mt][nt][half * 2 + 0];
                float v1 = acc[mt][nt][half * 2 + 1];
                if (bias) { v0 += bias[col]; v1 += bias[col + 1]; }
                if (act) { v0 = gelu_f(v0); v1 = gelu_f(v1); }
                if (add) {
                    v0 += add[(size_t)row * N + col];
                    v1 += add[(size_t)row * N + col + 1];
                }
                *(float2*)&C[(size_t)row * N + col] = make_float2(v0, v1);
            }
        }
    }
}

// ---------------- fp32 SGEMM with optional split-K (skinny LoRA, N=120) ----------------
// If nsplit > 1: grid.z = nsplit, C must be pre-zeroed; accumulate via atomicAdd.
__global__ void gemm_kernel(const float* __restrict__ A, const float* __restrict__ W,
                            float* __restrict__ C, int N, int K, int nsplit) {
    __shared__ float As[16][64];
    __shared__ float Bs[16][64];
    int bm = blockIdx.y * 64, bn = blockIdx.x * 64;
    int kchunk = K / nsplit;
    int kbeg = blockIdx.z * kchunk;
    int kend = kbeg + kchunk;
    int tid = threadIdx.x;
    int tx = tid & 15, ty = tid >> 4;
    int lr = tid >> 2;
    int lc = (tid & 3) << 2;
    float acc[4][4] = {};
    const float* Aptr = A + (size_t)(bm + lr) * K + lc;
    int wrow = bn + lr;
    const float* Wptr = W + (size_t)wrow * K + lc;
    for (int k0 = kbeg; k0 < kend; k0 += 16) {
        float4 a4 = *(const float4*)(Aptr + k0);
        float4 b4 = (wrow < N) ? *(const float4*)(Wptr + k0) : make_float4(0.f, 0.f, 0.f, 0.f);
        As[lc + 0][lr] = a4.x; As[lc + 1][lr] = a4.y; As[lc + 2][lr] = a4.z; As[lc + 3][lr] = a4.w;
        Bs[lc + 0][lr] = b4.x; Bs[lc + 1][lr] = b4.y; Bs[lc + 2][lr] = b4.z; Bs[lc + 3][lr] = b4.w;
        __syncthreads();
#pragma unroll
        for (int kk = 0; kk < 16; kk++) {
            float4 ra = *(const float4*)&As[kk][ty << 2];
            float4 rb = *(const float4*)&Bs[kk][tx << 2];
            float raa[4] = {ra.x, ra.y, ra.z, ra.w};
            float rbb[4] = {rb.x, rb.y, rb.z, rb.w};
#pragma unroll
            for (int i = 0; i < 4; i++)
#pragma unroll
                for (int j = 0; j < 4; j++)
                    acc[i][j] += raa[i] * rbb[j];
        }
        __syncthreads();
    }
#pragma unroll
    for (int i = 0; i < 4; i++) {
        int m = bm + (ty << 2) + i;
#pragma unroll
        for (int j = 0; j < 4; j++) {
            int n = bn + (tx << 2) + j;
            if (n < N) {
                if (nsplit > 1) atomicAdd(&C[(size_t)m * N + n], acc[i][j]);
                else C[(size_t)m * N + n] = acc[i][j];
            }
        }
    }
}

// ---------------- attention: one block per (batch, head) ----------------
__global__ void attn_kernel() {
    int bh = blockIdx.x;
    int b = bh / NHD, hh = bh - b * NHD;
    __shared__ float sq[SS][HD], sk[SS][HD], sv[SS][HD], sc[SS][SS + 1];
    int tid = threadIdx.x;
    int base = b * SS;
    for (int i = tid; i < SS * HD; i += 256) {
        int s = i >> 6, d = i & 63;
        int gi = (base + s) * HH + hh * HD + d;
        sq[s][d] = g_q[gi]; sk[s][d] = g_k[gi]; sv[s][d] = g_v[gi];
    }
    __syncthreads();
    for (int i = tid; i < SS * SS; i += 256) {
        int r = i / SS, c = i - r * SS;
        float s = 0.f;
#pragma unroll
        for (int d = 0; d < HD; d++) s += sq[r][d] * sk[c][d];
        sc[r][c] = s * 0.125f;
    }
    __syncthreads();
    if (tid < SS) {
        float mx = -1e30f;
        for (int c = 0; c < SS; c++) mx = fmaxf(mx, sc[tid][c]);
        float sm = 0.f;
        for (int c = 0; c < SS; c++) { float e = expf(sc[tid][c] - mx); sc[tid][c] = e; sm += e; }
        float inv = 1.0f / sm;
        for (int c = 0; c < SS; c++) sc[tid][c] *= inv;
    }
    __syncthreads();
    for (int i = tid; i < SS * HD; i += 256) {
        int s = i >> 6, d = i & 63;
        float o = 0.f;
#pragma unroll
        for (int c = 0; c < SS; c++) o += sc[s][c] * sv[c][d];
        g_ctx[(base + s) * HH + hh * HD + d] = o;
    }
}

// ---------------- per-disease classifiers -> gate[b,d] ----------------
__global__ void cls_kernel(const float* __restrict__ mask,
                           const float* __restrict__ cw1, const float* __restrict__ cb1,
                           const float* __restrict__ clg, const float* __restrict__ clb,
                           const float* __restrict__ cw2, const float* __restrict__ cb2) {
    int b = blockIdx.x, d = blockIdx.y;
    int tid = threadIdx.x;
    __shared__ float pooled[HH];
    __shared__ float h1[384];
    __shared__ float r1[256], r2[256];
    float cnt = 0.f;
    for (int r = 0; r < RR; r++) cnt += (mask[r * DD + d] > 0.f) ? 1.f : 0.f;
    float inv = 1.0f / fmaxf(cnt, 1.0f);
    for (int j = tid; j < HH; j += 256) {
        float s = 0.f;
        for (int r = 0; r < RR; r++)
            if (mask[r * DD + d] > 0.f) s += g_att[(b * SS + 1 + r) * HH + j];
        pooled[j] = s * inv;
    }
    __syncthreads();
    for (int k = tid; k < 384; k += 256) {
        const float* wrow = cw1 + ((size_t)d * 384 + k) * HH;
        float s = 0.f;
        for (int j = 0; j < HH; j++) s += pooled[j] * wrow[j];
        h1[k] = s + cb1[d * 384 + k];
    }
    __syncthreads();
    float a = 0.f, sq = 0.f;
    for (int k = tid; k < 384; k += 256) { float v = h1[k]; a += v; sq += v * v; }
    r1[tid] = a; r2[tid] = sq;
    __syncthreads();
    for (int o = 128; o > 0; o >>= 1) {
        if (tid < o) { r1[tid] += r1[tid + o]; r2[tid] += r2[tid + o]; }
        __syncthreads();
    }
    float mean = r1[0] * (1.0f / 384.0f);
    float var = r2[0] * (1.0f / 384.0f) - mean * mean;
    float rn = rsqrtf(var + 1e-5f);
    __syncthreads();
    float p = 0.f;
    for (int k = tid; k < 384; k += 256) {
        float v = (h1[k] - mean) * rn * clg[d * 384 + k] + clb[d * 384 + k];
        v = gelu_f(v);
        p += v * cw2[d * 384 + k];
    }
    r1[tid] = p;
    __syncthreads();
    for (int o = 128; o > 0; o >>= 1) {
        if (tid < o) r1[tid] += r1[tid + o];
        __syncthreads();
    }
    if (tid == 0) {
        float pred = r1[0] + cb2[d];
        g_gate[b * DD + d] = (cnt > 0.f && pred > 0.f) ? 1.f : 0.f;
    }
}

// ---------------- M[e] = Bu_e^T @ Ad_e^T ----------------
__global__ void m_kernel(const float* __restrict__ bu, const float* __restrict__ ad) {
    int e = blockIdx.x;
    int r = threadIdx.x >> 3, c = threadIdx.x & 7;
    const float* bup = bu + (size_t)e * II * LRK;
    const float* adp = ad + ((size_t)e * LRK + c) * II;
    float s = 0.f;
    for (int i = 0; i < II; i++) s += bup[i * LRK + r] * adp[i];
    g_M[(e * LRK + r) * LRK + c] = s;
}

// ---------------- t = v + SCAL * u @ M ----------------
__global__ void t_kernel() {
    int token = blockIdx.x;
    int er = threadIdx.x;
    int e = er >> 3, r = er & 7;
    __shared__ float su[ELR];
    su[er] = g_u[token * ELR + er];
    __syncthreads();
    float s = 0.f;
#pragma unroll
    for (int q = 0; q < LRK; q++) s += su[e * LRK + q] * g_M[(e * LRK + q) * LRK + r];
    g_t[token * ELR + er] = g_vv[token * ELR + er] + SCALF * s;
}

// ---------------- expert mix ----------------
__global__ void comb_kernel(const float* __restrict__ bd, const float* __restrict__ mask) {
    int token = blockIdx.x;
    int b = token / SS, s = token - b * SS;
    int tid = threadIdx.x;
    __shared__ float r1[256], r2[256];
    __shared__ float sw[16];
    if (tid < EE) {
        float a;
        if (tid == 14) a = 1.f;
        else a = (s > 0 && mask[(s - 1) * DD + tid] > 0.f) ? g_gate[b * DD + tid] : 0.f;
        sw[tid] = a;
    }
    __syncthreads();
    float nact = 0.f;
#pragma unroll
    for (int e = 0; e < EE; e++) nact += sw[e];
    float wt = 1.0f / fmaxf(nact, 1.0f);
    float bo0[3], acc[3] = {0.f, 0.f, 0.f};
#pragma unroll
    for (int i = 0; i < 3; i++) bo0[i] = g_bout[token * HH + tid + i * 256];
    for (int e = 0; e < EE; e++) {
        if (sw[e] == 0.f) continue;
        float t8[8];
        const float* tp = g_t + token * ELR + e * LRK;
#pragma unroll
        for (int r = 0; r < 8; r++) t8[r] = tp[r];
        float o[3];
        float a = 0.f, sq = 0.f;
#pragma unroll
        for (int i = 0; i < 3; i++) {
            int j = tid + i * 256;
            const float* bdp = bd + ((size_t)e * HH + j) * LRK;
            float dv = 0.f;
#pragma unroll
            for (int r = 0; r < 8; r++) dv += t8[r] * bdp[r];
            float ov = bo0[i] + SCALF * dv;
            o[i] = ov; a += ov; sq += ov * ov;
        }
        r1[tid] = a; r2[tid] = sq;
        __syncthreads();
        for (int off = 128; off > 0; off >>= 1) {
            if (tid < off) { r1[tid] += r1[tid + off]; r2[tid] += r2[tid + off]; }
            __syncthreads();
        }
        float mean = r1[0] * (1.0f / 768.0f);
        float var = r2[0] * (1.0f / 768.0f) - mean * mean;
        float rn = rsqrtf(var + 1e-5f);
#pragma unroll
        for (int i = 0; i < 3; i++) acc[i] += wt * (o[i] - mean) * rn;
        __syncthreads();
    }
#pragma unroll
    for (int i = 0; i < 3; i++) {
        int j = tid + i * 256;
        g_h[token * HH + j] = acc[i] + g_res1[token * HH + j];
    }
}

// ---------------- host launcher ----------------
extern "C" void kernel_launch(void* const* d_in, const int* in_sizes, int n_in,
                              void* d_out, int out_size) {
    const float* rf   = (const float*)d_in[0];
    const float* cls  = (const float*)d_in[1];
    const float* ln1g = (const float*)d_in[2];
    const float* ln1b = (const float*)d_in[3];
    const float* ln2g = (const float*)d_in[4];
    const float* ln2b = (const float*)d_in[5];
    const float* wq   = (const float*)d_in[6];
    const float* bq   = (const float*)d_in[7];
    const float* wk   = (const float*)d_in[8];
    const float* bk   = (const float*)d_in[9];
    const float* wv   = (const float*)d_in[10];
    const float* bv   = (const float*)d_in[11];
    const float* wo   = (const float*)d_in[12];
    const float* bo   = (const float*)d_in[13];
    const float* wi   = (const float*)d_in[14];
    const float* bi   = (const float*)d_in[15];
    const float* wof  = (const float*)d_in[16];
    const float* bof  = (const float*)d_in[17];
    const float* lnfg = (const float*)d_in[18];
    const float* lnfb = (const float*)d_in[19];
    const float* au   = (const float*)d_in[20];
    const float* bu   = (const float*)d_in[21];
    const float* ad   = (const float*)d_in[22];
    const float* bd   = (const float*)d_in[23];
    const float* cw1  = (const float*)d_in[24];
    const float* cb1  = (const float*)d_in[25];
    const float* clg  = (const float*)d_in[26];
    const float* clb  = (const float*)d_in[27];
    const float* cw2  = (const float*)d_in[28];
    const float* cb2  = (const float*)d_in[29];
    const float* maskp= (const float*)d_in[30];
    float* out = (float*)d_out;

    float *h, *nx, *q, *k, *v, *ctx, *att, *res1, *nres, *hid, *bout;
    float *u, *vv;
    cudaGetSymbolAddress((void**)&h,    g_h);
    cudaGetSymbolAddress((void**)&nx,   g_nx);
    cudaGetSymbolAddress((void**)&q,    g_q);
    cudaGetSymbolAddress((void**)&k,    g_k);
    cudaGetSymbolAddress((void**)&v,    g_v);
    cudaGetSymbolAddress((void**)&ctx,  g_ctx);
    cudaGetSymbolAddress((void**)&att,  g_att);
    cudaGetSymbolAddress((void**)&res1, g_res1);
    cudaGetSymbolAddress((void**)&nres, g_nres);
    cudaGetSymbolAddress((void**)&hid,  g_hid);
    cudaGetSymbolAddress((void**)&bout, g_bout);
    cudaGetSymbolAddress((void**)&u,    g_u);
    cudaGetSymbolAddress((void**)&vv,   g_vv);

    dim3 t768(HH / 128, TN / 128);      // 6 x 30
    dim3 t3072(II / 128, TN / 128);     // 24 x 30
    dim3 gu(2, TN / 64, 2);             // N=120->2 col blocks, split-K 2 (K=768)
    dim3 gv(2, TN / 64, 4);             // split-K 4 (K=3072)
    int nel = TN * HH;
    int nblk = (nel + 255) / 256;

    embed_kernel<<<nblk, 256>>>(rf, cls);

    for (int i = 0; i < LL; i++) {
        ln_kernel<<<TN, 256>>>(h, nullptr, nullptr, nx, ln1g + i * HH, ln1b + i * HH, 1e-12f);
        t3gemm_kernel<<<t768, 256>>>(nx, wq + (size_t)i * HH * HH, bq + i * HH, nullptr, q, HH, HH, 0);
        t3gemm_kernel<<<t768, 256>>>(nx, wk + (size_t)i * HH * HH, bk + i * HH, nullptr, k, HH, HH, 0);
        t3gemm_kernel<<<t768, 256>>>(nx, wv + (size_t)i * HH * HH, bv + i * HH, nullptr, v, HH, HH, 0);
        attn_kernel<<<BQ * NHD, 256>>>();
        t3gemm_kernel<<<t768, 256>>>(ctx, wo + (size_t)i * HH * HH, bo + i * HH, nullptr, att, HH, HH, 0);
        ln_kernel<<<TN, 256>>>(att, h, res1, nres, ln2g + i * HH, ln2b + i * HH, 1e-12f);
        t3gemm_kernel<<<t3072, 256>>>(nres, wi + (size_t)i * II * HH, bi + i * II, nullptr, hid, II, HH, 1);
        if (i & 1) {
            t3gemm_kernel<<<t768, 256>>>(hid, wof + (size_t)i * HH * II, bof + i * HH, res1, h, HH, II, 0);
        } else {
            int ei = i / 2;
            t3gemm_kernel<<<t768, 256>>>(hid, wof + (size_t)i * HH * II, bof + i * HH, nullptr, bout, HH, II, 0);
            dim3 gc(BQ, DD);
            cls_kernel<<<gc, 256>>>(maskp,
                                    cw1 + (size_t)ei * DD * 384 * HH,
                                    cb1 + (size_t)ei * DD * 384,
                                    clg + (size_t)ei * DD * 384,
                                    clb + (size_t)ei * DD * 384,
                                    cw2 + (size_t)ei * DD * 384,
                                    cb2 + (size_t)ei * DD);
            m_kernel<<<EE, 64>>>(bu + (size_t)ei * EE * II * LRK,
                                 ad + (size_t)ei * EE * LRK * II);
            cudaMemsetAsync(u, 0, (size_t)TN * ELR * sizeof(float));
            cudaMemsetAsync(vv, 0, (size_t)TN * ELR * sizeof(float));
            gemm_kernel<<<gu, 256>>>(nres, au + (size_t)ei * EE * LRK * HH, u, ELR, HH, 2);
            gemm_kernel<<<gv, 256>>>(hid, ad + (size_t)ei * EE * LRK * II, vv, ELR, II, 4);
            t_kernel<<<TN, ELR>>>();
            comb_kernel<<<TN, 256>>>(bd + (size_t)ei * EE * HH * LRK, maskp);
        }
    }
    ln_kernel<<<TN, 256>>>(h, nullptr, nullptr, out, lnfg, lnfb, 1e-12f);
}

// round 9
// speedup vs baseline: 1.6902x; 1.6902x over previous
#include <cuda_runtime.h>
#include <cuda_bf16.h>
#include <math.h>
#include <stdint.h>

#define BQ 128
#define SS 30
#define HH 768
#define II 3072
#define LL 12
#define NHD 12
#define HD 64
#define EE 15
#define DD 14
#define RR 29
#define LRK 8
#define TN (BQ*SS)        // 3840 tokens
#define ELR (EE*LRK)      // 120
#define SCALF 2.0f

// ---------------- scratch (device globals; no allocation) ----------------
__device__ float g_h[TN*HH];
__device__ float g_nx[TN*HH];
__device__ float g_q[TN*HH];
__device__ float g_k[TN*HH];
__device__ float g_v[TN*HH];
__device__ float g_ctx[TN*HH];
__device__ float g_att[TN*HH];
__device__ float g_res1[TN*HH];
__device__ float g_nres[TN*HH];
__device__ float g_hid[TN*II];
__device__ float g_bout[TN*HH];
__device__ float g_u[TN*ELR];
__device__ float g_vv[TN*ELR];
__device__ float g_t[TN*ELR];
__device__ float g_M[EE*LRK*LRK];
__device__ float g_gate[BQ*DD];

// bf16 hi/lo activation buffers
__device__ __nv_bfloat16 g_nxh[TN*HH],   g_nxl[TN*HH];
__device__ __nv_bfloat16 g_nresh[TN*HH], g_nresl[TN*HH];
__device__ __nv_bfloat16 g_ctxh[TN*HH],  g_ctxl[TN*HH];
__device__ __nv_bfloat16 g_hidh[TN*II],  g_hidl[TN*II];

// bf16 hi/lo weight buffers (split once per launch)
#define WSZ (LL*HH*HH)
#define WISZ (LL*II*HH)
__device__ __nv_bfloat16 g_wqh[WSZ],  g_wql[WSZ];
__device__ __nv_bfloat16 g_wkh[WSZ],  g_wkl[WSZ];
__device__ __nv_bfloat16 g_wvh[WSZ],  g_wvl[WSZ];
__device__ __nv_bfloat16 g_woh[WSZ],  g_wol[WSZ];
__device__ __nv_bfloat16 g_wih[WISZ], g_wil[WISZ];
__device__ __nv_bfloat16 g_wofh[WISZ], g_wofl[WISZ];

__device__ __forceinline__ float gelu_f(float x) {
    return 0.5f * x * (1.0f + erff(x * 0.70710678118654752f));
}

__device__ __forceinline__ uint32_t smaddr(const void* p) {
    uint32_t a;
    asm("{ .reg .u64 t; cvta.to.shared.u64 t, %1; cvt.u32.u64 %0, t; }" : "=r"(a) : "l"(p));
    return a;
}

#define LDSM4(r, a)                                                        \
    asm volatile("ldmatrix.sync.aligned.m8n8.x4.shared.b16 {%0,%1,%2,%3}, [%4];" \
        : "=r"((r)[0]), "=r"((r)[1]), "=r"((r)[2]), "=r"((r)[3]) : "r"(a))

#define MMABF(d, a, b)                                                     \
    asm volatile("mma.sync.aligned.m16n8k16.row.col.f32.bf16.bf16.f32 "    \
        "{%0,%1,%2,%3}, {%4,%5,%6,%7}, {%8,%9}, {%0,%1,%2,%3};"            \
        : "+f"((d)[0]), "+f"((d)[1]), "+f"((d)[2]), "+f"((d)[3])           \
        : "r"((a)[0]), "r"((a)[1]), "r"((a)[2]), "r"((a)[3]),              \
          "r"((b)[0]), "r"((b)[1]))

// ---------------- weight split ----------------
__global__ void wsplit_kernel(const float* __restrict__ w,
                              __nv_bfloat16* __restrict__ wh,
                              __nv_bfloat16* __restrict__ wl, int n) {
    int i = blockIdx.x * 256 + threadIdx.x;
    int stride = gridDim.x * 256;
    for (; i < n; i += stride) {
        float x = w[i];
        __nv_bfloat16 hv = __float2bfloat16_rn(x);
        wh[i] = hv;
        wl[i] = __float2bfloat16_rn(x - __bfloat162float(hv));
    }
}

// ---------------- embed ----------------
__global__ void embed_kernel(const float* __restrict__ rf, const float* __restrict__ cls) {
    int idx = blockIdx.x * 256 + threadIdx.x;
    if (idx >= TN * HH) return;
    int t = idx / HH, j = idx - t * HH;
    int s = t % SS, b = t / SS;
    g_h[idx] = (s == 0) ? cls[j] : rf[(b * RR + (s - 1)) * HH + j];
}

// ---------------- LayerNorm (H=768), fused residual + bf16 split out ----------------
__global__ void ln_kernel(const float* __restrict__ a, const float* __restrict__ b,
                          float* __restrict__ res_out, float* __restrict__ norm_out,
                          __nv_bfloat16* __restrict__ oh, __nv_bfloat16* __restrict__ ol,
                          const float* __restrict__ g, const float* __restrict__ bb,
                          float eps) {
    int t = blockIdx.x;
    int tid = threadIdx.x;
    const float* xa = a + (size_t)t * HH;
    const float* xb = b ? b + (size_t)t * HH : nullptr;
    __shared__ float s1[256], s2[256];
    float xv[3];
    float acc = 0.f, sq = 0.f;
#pragma unroll
    for (int i = 0; i < 3; i++) {
        int j = tid + i * 256;
        float v = xa[j];
        if (xb) v += xb[j];
        xv[i] = v; acc += v; sq += v * v;
        if (res_out) res_out[(size_t)t * HH + j] = v;
    }
    s1[tid] = acc; s2[tid] = sq;
    __syncthreads();
    for (int o = 128; o > 0; o >>= 1) {
        if (tid < o) { s1[tid] += s1[tid + o]; s2[tid] += s2[tid + o]; }
        __syncthreads();
    }
    float mean = s1[0] * (1.0f / 768.0f);
    float var = s2[0] * (1.0f / 768.0f) - mean * mean;
    float r = rsqrtf(var + eps);
#pragma unroll
    for (int i = 0; i < 3; i++) {
        int j = tid + i * 256;
        float y = (xv[i] - mean) * r * g[j] + bb[j];
        norm_out[(size_t)t * HH + j] = y;
        if (oh) {
            __nv_bfloat16 hv = __float2bfloat16_rn(y);
            oh[(size_t)t * HH + j] = hv;
            ol[(size_t)t * HH + j] = __float2bfloat16_rn(y - __bfloat162float(hv));
        }
    }
}

// ---------------- bf16 2-term split GEMM (mma.sync m16n8k16) ----------------
// C[M,N] = A[M,K] @ W[N,K]^T (+bias)(gelu)(+add), A,W given as bf16 hi/lo pairs.
// BM=64, BN=128, BK=32, 256 threads = 8 warps (2m x 4n), warp tile 32x32.
#define BKB 32
#define PITCH 80
#define SMA (64*PITCH)
#define SMW (128*PITCH)
#define STGSZ (2*SMA+2*SMW)
#define SMEMB (2*STGSZ)
__global__ void __launch_bounds__(256, 2)
bgemm_kernel(const __nv_bfloat16* __restrict__ Ah, const __nv_bfloat16* __restrict__ Al,
             const __nv_bfloat16* __restrict__ Wph, const __nv_bfloat16* __restrict__ Wpl,
             const float* __restrict__ bias, const float* __restrict__ add,
             float* __restrict__ C,
             __nv_bfloat16* __restrict__ OH, __nv_bfloat16* __restrict__ OL,
             int N, int K, int act) {
    extern __shared__ char sm[];
    uint32_t sbase = smaddr(sm);
    int tid = threadIdx.x, lane = tid & 31, warp = tid >> 5;
    int bm = blockIdx.y * 64, bn = blockIdx.x * 128;
    int wm = warp >> 2, wn = warp & 3;

    // per-thread cp.async assignments: 1536 16B copies / 256 threads = 6 each
    const __nv_bfloat16* src[6];
    uint32_t dst0[6];
#pragma unroll
    for (int i = 0; i < 6; i++) {
        int c = tid + i * 256;
        int buf, idx;
        if (c < 512) { buf = c >> 8; idx = c & 255; }
        else { buf = 2 + ((c - 512) >> 9); idx = (c - 512) & 511; }
        int row = idx >> 2;
        int seg = idx & 3;
        uint32_t soff = (buf == 0) ? 0u : (buf == 1) ? (uint32_t)SMA
                       : (buf == 2) ? (uint32_t)(2 * SMA) : (uint32_t)(2 * SMA + SMW);
        const __nv_bfloat16* g = (buf == 0) ? Ah : (buf == 1) ? Al : (buf == 2) ? Wph : Wpl;
        int grow = (buf < 2) ? (bm + row) : (bn + row);
        src[i] = g + (size_t)grow * K + seg * 8;
        dst0[i] = sbase + soff + (uint32_t)(row * PITCH + seg * 16);
    }
    int NCH = K / BKB;
#pragma unroll
    for (int i = 0; i < 6; i++)
        asm volatile("cp.async.cg.shared.global [%0], [%1], 16;" :: "r"(dst0[i]), "l"(src[i]));
    asm volatile("cp.async.commit_group;" ::: "memory");

    float acc[2][4][4];
#pragma unroll
    for (int mt = 0; mt < 2; mt++)
#pragma unroll
        for (int nt = 0; nt < 4; nt++)
#pragma unroll
            for (int r = 0; r < 4; r++) acc[mt][nt][r] = 0.f;

    for (int kc = 0; kc < NCH; kc++) {
        int s = kc & 1;
        if (kc + 1 < NCH) {
            uint32_t so = (uint32_t)(((kc + 1) & 1) * STGSZ);
#pragma unroll
            for (int i = 0; i < 6; i++)
                asm volatile("cp.async.cg.shared.global [%0], [%1], 16;"
                    :: "r"(dst0[i] + so), "l"(src[i] + (size_t)(kc + 1) * BKB));
            asm volatile("cp.async.commit_group;" ::: "memory");
            asm volatile("cp.async.wait_group 1;" ::: "memory");
        } else {
            asm volatile("cp.async.wait_group 0;" ::: "memory");
        }
        __syncthreads();
        uint32_t sb = sbase + (uint32_t)(s * STGSZ);
#pragma unroll
        for (int ks = 0; ks < 2; ks++) {
            uint32_t ah[2][4], alf[2][4], bh[4][2], bl[4][2];
#pragma unroll
            for (int mt = 0; mt < 2; mt++) {
                uint32_t ra = sb + (uint32_t)((wm * 32 + mt * 16 + (lane & 15)) * PITCH
                                              + ks * 32 + ((lane >> 4) << 4));
                LDSM4(ah[mt], ra);
                LDSM4(alf[mt], ra + SMA);
            }
#pragma unroll
            for (int np = 0; np < 2; np++) {
                uint32_t rb = sb + (uint32_t)(2 * SMA
                              + (wn * 32 + np * 16 + ((lane >> 4) << 3) + (lane & 7)) * PITCH
                              + ks * 32 + (((lane >> 3) & 1) << 4));
                uint32_t t0[4];
                LDSM4(t0, rb);
                bh[np * 2][0] = t0[0]; bh[np * 2][1] = t0[1];
                bh[np * 2 + 1][0] = t0[2]; bh[np * 2 + 1][1] = t0[3];
                LDSM4(t0, rb + SMW);
                bl[np * 2][0] = t0[0]; bl[np * 2][1] = t0[1];
                bl[np * 2 + 1][0] = t0[2]; bl[np * 2 + 1][1] = t0[3];
            }
#pragma unroll
            for (int mt = 0; mt < 2; mt++)
#pragma unroll
                for (int nt = 0; nt < 4; nt++) {
                    MMABF(acc[mt][nt], alf[mt], bh[nt]);
                    MMABF(acc[mt][nt], ah[mt], bl[nt]);
                    MMABF(acc[mt][nt], ah[mt], bh[nt]);
                }
        }
        __syncthreads();
    }

    // epilogue
#pragma unroll
    for (int mt = 0; mt < 2; mt++) {
#pragma unroll
        for (int nt = 0; nt < 4; nt++) {
            int col = bn + wn * 32 + nt * 8 + (lane & 3) * 2;
            float bv0 = 0.f, bv1 = 0.f;
            if (bias) { bv0 = bias[col]; bv1 = bias[col + 1]; }
#pragma unroll
            for (int hf = 0; hf < 2; hf++) {
                int row = bm + wm * 32 + mt * 16 + (lane >> 2) + hf * 8;
                float v0 = acc[mt][nt][hf * 2 + 0] + bv0;
                float v1 = acc[mt][nt][hf * 2 + 1] + bv1;
                if (act) { v0 = gelu_f(v0); v1 = gelu_f(v1); }
                if (add) {
                    v0 += add[(size_t)row * N + col];
                    v1 += add[(size_t)row * N + col + 1];
                }
                *(float2*)&C[(size_t)row * N + col] = make_float2(v0, v1);
                if (OH) {
                    __nv_bfloat16 h0 = __float2bfloat16_rn(v0);
                    __nv_bfloat16 h1 = __float2bfloat16_rn(v1);
                    __nv_bfloat16 l0 = __float2bfloat16_rn(v0 - __bfloat162float(h0));
                    __nv_bfloat16 l1 = __float2bfloat16_rn(v1 - __bfloat162float(h1));
                    *(__nv_bfloat162*)&OH[(size_t)row * N + col] = __nv_bfloat162(h0, h1);
                    *(__nv_bfloat162*)&OL[(size_t)row * N + col] = __nv_bfloat162(l0, l1);
                }
            }
        }
    }
}

// ---------------- fp32 SGEMM with optional split-K (skinny LoRA, N=120) ----------------
__global__ void gemm_kernel(const float* __restrict__ A, const float* __restrict__ W,
                            float* __restrict__ C, int N, int K, int nsplit) {
    __shared__ float As[16][64];
    __shared__ float Bs[16][64];
    int bm = blockIdx.y * 64, bn = blockIdx.x * 64;
    int kchunk = K / nsplit;
    int kbeg = blockIdx.z * kchunk;
    int kend = kbeg + kchunk;
    int tid = threadIdx.x;
    int tx = tid & 15, ty = tid >> 4;
    int lr = tid >> 2;
    int lc = (tid & 3) << 2;
    float acc[4][4] = {};
    const float* Aptr = A + (size_t)(bm + lr) * K + lc;
    int wrow = bn + lr;
    const float* Wptr = W + (size_t)wrow * K + lc;
    for (int k0 = kbeg; k0 < kend; k0 += 16) {
        float4 a4 = *(const float4*)(Aptr + k0);
        float4 b4 = (wrow < N) ? *(const float4*)(Wptr + k0) : make_float4(0.f, 0.f, 0.f, 0.f);
        As[lc + 0][lr] = a4.x; As[lc + 1][lr] = a4.y; As[lc + 2][lr] = a4.z; As[lc + 3][lr] = a4.w;
        Bs[lc + 0][lr] = b4.x; Bs[lc + 1][lr] = b4.y; Bs[lc + 2][lr] = b4.z; Bs[lc + 3][lr] = b4.w;
        __syncthreads();
#pragma unroll
        for (int kk = 0; kk < 16; kk++) {
            float4 ra = *(const float4*)&As[kk][ty << 2];
            float4 rb = *(const float4*)&Bs[kk][tx << 2];
            float raa[4] = {ra.x, ra.y, ra.z, ra.w};
            float rbb[4] = {rb.x, rb.y, rb.z, rb.w};
#pragma unroll
            for (int i = 0; i < 4; i++)
#pragma unroll
                for (int j = 0; j < 4; j++)
                    acc[i][j] += raa[i] * rbb[j];
        }
        __syncthreads();
    }
#pragma unroll
    for (int i = 0; i < 4; i++) {
        int m = bm + (ty << 2) + i;
#pragma unroll
        for (int j = 0; j < 4; j++) {
            int n = bn + (tx << 2) + j;
            if (n < N) {
                if (nsplit > 1) atomicAdd(&C[(size_t)m * N + n], acc[i][j]);
                else C[(size_t)m * N + n] = acc[i][j];
            }
        }
    }
}

// ---------------- attention: one block per (batch, head); emits ctx + bf16 split ----------------
__global__ void attn_kernel() {
    int bh = blockIdx.x;
    int b = bh / NHD, hh = bh - b * NHD;
    __shared__ float sq[SS][HD], sk[SS][HD], sv[SS][HD], sc[SS][SS + 1];
    int tid = threadIdx.x;
    int base = b * SS;
    for (int i = tid; i < SS * HD; i += 256) {
        int s = i >> 6, d = i & 63;
        int gi = (base + s) * HH + hh * HD + d;
        sq[s][d] = g_q[gi]; sk[s][d] = g_k[gi]; sv[s][d] = g_v[gi];
    }
    __syncthreads();
    for (int i = tid; i < SS * SS; i += 256) {
        int r = i / SS, c = i - r * SS;
        float s = 0.f;
#pragma unroll
        for (int d = 0; d < HD; d++) s += sq[r][d] * sk[c][d];
        sc[r][c] = s * 0.125f;
    }
    __syncthreads();
    if (tid < SS) {
        float mx = -1e30f;
        for (int c = 0; c < SS; c++) mx = fmaxf(mx, sc[tid][c]);
        float sm = 0.f;
        for (int c = 0; c < SS; c++) { float e = expf(sc[tid][c] - mx); sc[tid][c] = e; sm += e; }
        float inv = 1.0f / sm;
        for (int c = 0; c < SS; c++) sc[tid][c] *= inv;
    }
    __syncthreads();
    for (int i = tid; i < SS * HD; i += 256) {
        int s = i >> 6, d = i & 63;
        float o = 0.f;
#pragma unroll
        for (int c = 0; c < SS; c++) o += sc[s][c] * sv[c][d];
        int gi = (base + s) * HH + hh * HD + d;
        g_ctx[gi] = o;
        __nv_bfloat16 hv = __float2bfloat16_rn(o);
        g_ctxh[gi] = hv;
        g_ctxl[gi] = __float2bfloat16_rn(o - __bfloat162float(hv));
    }
}

// ---------------- per-disease classifiers -> gate[b,d] ----------------
__global__ void cls_kernel(const float* __restrict__ mask,
                           const float* __restrict__ cw1, const float* __restrict__ cb1,
                           const float* __restrict__ clg, const float* __restrict__ clb,
                           const float* __restrict__ cw2, const float* __restrict__ cb2) {
    int b = blockIdx.x, d = blockIdx.y;
    int tid = threadIdx.x;
    __shared__ float pooled[HH];
    __shared__ float h1[384];
    __shared__ float r1[256], r2[256];
    float cnt = 0.f;
    for (int r = 0; r < RR; r++) cnt += (mask[r * DD + d] > 0.f) ? 1.f : 0.f;
    float inv = 1.0f / fmaxf(cnt, 1.0f);
    for (int j = tid; j < HH; j += 256) {
        float s = 0.f;
        for (int r = 0; r < RR; r++)
            if (mask[r * DD + d] > 0.f) s += g_att[(b * SS + 1 + r) * HH + j];
        pooled[j] = s * inv;
    }
    __syncthreads();
    for (int k = tid; k < 384; k += 256) {
        const float* wrow = cw1 + ((size_t)d * 384 + k) * HH;
        float s = 0.f;
        for (int j = 0; j < HH; j++) s += pooled[j] * wrow[j];
        h1[k] = s + cb1[d * 384 + k];
    }
    __syncthreads();
    float a = 0.f, sq = 0.f;
    for (int k = tid; k < 384; k += 256) { float v = h1[k]; a += v; sq += v * v; }
    r1[tid] = a; r2[tid] = sq;
    __syncthreads();
    for (int o = 128; o > 0; o >>= 1) {
        if (tid < o) { r1[tid] += r1[tid + o]; r2[tid] += r2[tid + o]; }
        __syncthreads();
    }
    float mean = r1[0] * (1.0f / 384.0f);
    float var = r2[0] * (1.0f / 384.0f) - mean * mean;
    float rn = rsqrtf(var + 1e-5f);
    __syncthreads();
    float p = 0.f;
    for (int k = tid; k < 384; k += 256) {
        float v = (h1[k] - mean) * rn * clg[d * 384 + k] + clb[d * 384 + k];
        v = gelu_f(v);
        p += v * cw2[d * 384 + k];
    }
    r1[tid] = p;
    __syncthreads();
    for (int o = 128; o > 0; o >>= 1) {
        if (tid < o) r1[tid] += r1[tid + o];
        __syncthreads();
    }
    if (tid == 0) {
        float pred = r1[0] + cb2[d];
        g_gate[b * DD + d] = (cnt > 0.f && pred > 0.f) ? 1.f : 0.f;
    }
}

// ---------------- M[e] = Bu_e^T @ Ad_e^T  (block per (e, col)) ----------------
__global__ void m_kernel(const float* __restrict__ bu, const float* __restrict__ ad) {
    int e = blockIdx.x, c = blockIdx.y;
    int tid = threadIdx.x;
    float s[LRK] = {};
    const float* bup = bu + (size_t)e * II * LRK;
    const float* adp = ad + ((size_t)e * LRK + c) * II;
    for (int i = tid; i < II; i += 256) {
        float a = adp[i];
        const float* bp = bup + (size_t)i * LRK;
#pragma unroll
        for (int r = 0; r < LRK; r++) s[r] += bp[r] * a;
    }
    __shared__ float red[256];
    for (int r = 0; r < LRK; r++) {
        red[tid] = s[r];
        __syncthreads();
        for (int o = 128; o > 0; o >>= 1) {
            if (tid < o) red[tid] += red[tid + o];
            __syncthreads();
        }
        if (tid == 0) g_M[(e * LRK + r) * LRK + c] = red[0];
        __syncthreads();
    }
}

// ---------------- t = v + SCAL * u @ M ----------------
__global__ void t_kernel() {
    int token = blockIdx.x;
    int er = threadIdx.x;
    int e = er >> 3, r = er & 7;
    __shared__ float su[ELR];
    su[er] = g_u[token * ELR + er];
    __syncthreads();
    float s = 0.f;
#pragma unroll
    for (int q = 0; q < LRK; q++) s += su[e * LRK + q] * g_M[(e * LRK + q) * LRK + r];
    g_t[token * ELR + er] = g_vv[token * ELR + er] + SCALF * s;
}

// ---------------- expert mix ----------------
__global__ void comb_kernel(const float* __restrict__ bd, const float* __restrict__ mask) {
    int token = blockIdx.x;
    int b = token / SS, s = token - b * SS;
    int tid = threadIdx.x;
    __shared__ float r1[256], r2[256];
    __shared__ float sw[16];
    if (tid < EE) {
        float a;
        if (tid == 14) a = 1.f;
        else a = (s > 0 && mask[(s - 1) * DD + tid] > 0.f) ? g_gate[b * DD + tid] : 0.f;
        sw[tid] = a;
    }
    __syncthreads();
    float nact = 0.f;
#pragma unroll
    for (int e = 0; e < EE; e++) nact += sw[e];
    float wt = 1.0f / fmaxf(nact, 1.0f);
    float bo0[3], acc[3] = {0.f, 0.f, 0.f};
#pragma unroll
    for (int i = 0; i < 3; i++) bo0[i] = g_bout[token * HH + tid + i * 256];
    for (int e = 0; e < EE; e++) {
        if (sw[e] == 0.f) continue;
        float t8[8];
        const float* tp = g_t + token * ELR + e * LRK;
#pragma unroll
        for (int r = 0; r < 8; r++) t8[r] = tp[r];
        float o[3];
        float a = 0.f, sq = 0.f;
#pragma unroll
        for (int i = 0; i < 3; i++) {
            int j = tid + i * 256;
            const float* bdp = bd + ((size_t)e * HH + j) * LRK;
            float dv = 0.f;
#pragma unroll
            for (int r = 0; r < 8; r++) dv += t8[r] * bdp[r];
            float ov = bo0[i] + SCALF * dv;
            o[i] = ov; a += ov; sq += ov * ov;
        }
        r1[tid] = a; r2[tid] = sq;
        __syncthreads();
        for (int off = 128; off > 0; off >>= 1) {
            if (tid < off) { r1[tid] += r1[tid + off]; r2[tid] += r2[tid + off]; }
            __syncthreads();
        }
        float mean = r1[0] * (1.0f / 768.0f);
        float var = r2[0] * (1.0f / 768.0f) - mean * mean;
        float rn = rsqrtf(var + 1e-5f);
#pragma unroll
        for (int i = 0; i < 3; i++) acc[i] += wt * (o[i] - mean) * rn;
        __syncthreads();
    }
#pragma unroll
    for (int i = 0; i < 3; i++) {
        int j = tid + i * 256;
        g_h[token * HH + j] = acc[i] + g_res1[token * HH + j];
    }
}

// ---------------- host launcher ----------------
extern "C" void kernel_launch(void* const* d_in, const int* in_sizes, int n_in,
                              void* d_out, int out_size) {
    const float* rf   = (const float*)d_in[0];
    const float* cls  = (const float*)d_in[1];
    const float* ln1g = (const float*)d_in[2];
    const float* ln1b = (const float*)d_in[3];
    const float* ln2g = (const float*)d_in[4];
    const float* ln2b = (const float*)d_in[5];
    const float* wq   = (const float*)d_in[6];
    const float* bq   = (const float*)d_in[7];
    const float* wk   = (const float*)d_in[8];
    const float* bk   = (const float*)d_in[9];
    const float* wv   = (const float*)d_in[10];
    const float* bv   = (const float*)d_in[11];
    const float* wo   = (const float*)d_in[12];
    const float* bo   = (const float*)d_in[13];
    const float* wi   = (const float*)d_in[14];
    const float* bi   = (const float*)d_in[15];
    const float* wof  = (const float*)d_in[16];
    const float* bof  = (const float*)d_in[17];
    const float* lnfg = (const float*)d_in[18];
    const float* lnfb = (const float*)d_in[19];
    const float* au   = (const float*)d_in[20];
    const float* bu   = (const float*)d_in[21];
    const float* ad   = (const float*)d_in[22];
    const float* bd   = (const float*)d_in[23];
    const float* cw1  = (const float*)d_in[24];
    const float* cb1  = (const float*)d_in[25];
    const float* clg  = (const float*)d_in[26];
    const float* clb  = (const float*)d_in[27];
    const float* cw2  = (const float*)d_in[28];
    const float* cb2  = (const float*)d_in[29];
    const float* maskp= (const float*)d_in[30];
    float* out = (float*)d_out;

    float *h, *nx, *q, *k, *v, *ctx, *att, *res1, *nres, *hid, *bout, *u, *vv;
    cudaGetSymbolAddress((void**)&h,    g_h);
    cudaGetSymbolAddress((void**)&nx,   g_nx);
    cudaGetSymbolAddress((void**)&q,    g_q);
    cudaGetSymbolAddress((void**)&k,    g_k);
    cudaGetSymbolAddress((void**)&v,    g_v);
    cudaGetSymbolAddress((void**)&ctx,  g_ctx);
    cudaGetSymbolAddress((void**)&att,  g_att);
    cudaGetSymbolAddress((void**)&res1, g_res1);
    cudaGetSymbolAddress((void**)&nres, g_nres);
    cudaGetSymbolAddress((void**)&hid,  g_hid);
    cudaGetSymbolAddress((void**)&bout, g_bout);
    cudaGetSymbolAddress((void**)&u,    g_u);
    cudaGetSymbolAddress((void**)&vv,   g_vv);

    __nv_bfloat16 *nxh, *nxl, *nresh, *nresl, *ctxh, *ctxl, *hidh, *hidl;
    __nv_bfloat16 *wqh, *wql, *wkh, *wkl, *wvh, *wvl, *woh, *wol, *wih, *wil, *wofh, *wofl;
    cudaGetSymbolAddress((void**)&nxh,   g_nxh);
    cudaGetSymbolAddress((void**)&nxl,   g_nxl);
    cudaGetSymbolAddress((void**)&nresh, g_nresh);
    cudaGetSymbolAddress((void**)&nresl, g_nresl);
    cudaGetSymbolAddress((void**)&ctxh,  g_ctxh);
    cudaGetSymbolAddress((void**)&ctxl,  g_ctxl);
    cudaGetSymbolAddress((void**)&hidh,  g_hidh);
    cudaGetSymbolAddress((void**)&hidl,  g_hidl);
    cudaGetSymbolAddress((void**)&wqh,   g_wqh);
    cudaGetSymbolAddress((void**)&wql,   g_wql);
    cudaGetSymbolAddress((void**)&wkh,   g_wkh);
    cudaGetSymbolAddress((void**)&wkl,   g_wkl);
    cudaGetSymbolAddress((void**)&wvh,   g_wvh);
    cudaGetSymbolAddress((void**)&wvl,   g_wvl);
    cudaGetSymbolAddress((void**)&woh,   g_woh);
    cudaGetSymbolAddress((void**)&wol,   g_wol);
    cudaGetSymbolAddress((void**)&wih,   g_wih);
    cudaGetSymbolAddress((void**)&wil,   g_wil);
    cudaGetSymbolAddress((void**)&wofh,  g_wofh);
    cudaGetSymbolAddress((void**)&wofl,  g_wofl);

    cudaFuncSetAttribute(bgemm_kernel, cudaFuncAttributeMaxDynamicSharedMemorySize, SMEMB);

    // weight splits (once per launch)
    wsplit_kernel<<<4096, 256>>>(wq,  wqh,  wql,  WSZ);
    wsplit_kernel<<<4096, 256>>>(wk,  wkh,  wkl,  WSZ);
    wsplit_kernel<<<4096, 256>>>(wv,  wvh,  wvl,  WSZ);
    wsplit_kernel<<<4096, 256>>>(wo,  woh,  wol,  WSZ);
    wsplit_kernel<<<8192, 256>>>(wi,  wih,  wil,  WISZ);
    wsplit_kernel<<<8192, 256>>>(wof, wofh, wofl, WISZ);

    dim3 b768(HH / 128, TN / 64);       // 6 x 60
    dim3 b3072(II / 128, TN / 64);      // 24 x 60
    dim3 gu(2, TN / 64, 2);
    dim3 gv(2, TN / 64, 4);
    int nel = TN * HH;
    int nblk = (nel + 255) / 256;

    embed_kernel<<<nblk, 256>>>(rf, cls);

    for (int i = 0; i < LL; i++) {
        size_t woff  = (size_t)i * HH * HH;
        size_t wioff = (size_t)i * II * HH;
        ln_kernel<<<TN, 256>>>(h, nullptr, nullptr, nx, nxh, nxl,
                               ln1g + i * HH, ln1b + i * HH, 1e-12f);
        bgemm_kernel<<<b768, 256, SMEMB>>>(nxh, nxl, wqh + woff, wql + woff, bq + i * HH,
                                           nullptr, q, nullptr, nullptr, HH, HH, 0);
        bgemm_kernel<<<b768, 256, SMEMB>>>(nxh, nxl, wkh + woff, wkl + woff, bk + i * HH,
                                           nullptr, k, nullptr, nullptr, HH, HH, 0);
        bgemm_kernel<<<b768, 256, SMEMB>>>(nxh, nxl, wvh + woff, wvl + woff, bv + i * HH,
                                           nullptr, v, nullptr, nullptr, HH, HH, 0);
        attn_kernel<<<BQ * NHD, 256>>>();
        bgemm_kernel<<<b768, 256, SMEMB>>>(ctxh, ctxl, woh + woff, wol + woff, bo + i * HH,
                                           nullptr, att, nullptr, nullptr, HH, HH, 0);
        ln_kernel<<<TN, 256>>>(att, h, res1, nres, nresh, nresl,
                               ln2g + i * HH, ln2b + i * HH, 1e-12f);
        bgemm_kernel<<<b3072, 256, SMEMB>>>(nresh, nresl, wih + wioff, wil + wioff, bi + i * II,
                                            nullptr, hid, hidh, hidl, II, HH, 1);
        if (i & 1) {
            bgemm_kernel<<<b768, 256, SMEMB>>>(hidh, hidl, wofh + wioff, wofl + wioff, bof + i * HH,
                                               res1, h, nullptr, nullptr, HH, II, 0);
        } else {
            int ei = i / 2;
            bgemm_kernel<<<b768, 256, SMEMB>>>(hidh, hidl, wofh + wioff, wofl + wioff, bof + i * HH,
                                               nullptr, bout, nullptr, nullptr, HH, II, 0);
            dim3 gc(BQ, DD);
            cls_kernel<<<gc, 256>>>(maskp,
                                    cw1 + (size_t)ei * DD * 384 * HH,
                                    cb1 + (size_t)ei * DD * 384,
                                    clg + (size_t)ei * DD * 384,
                                    clb + (size_t)ei * DD * 384,
                                    cw2 + (size_t)ei * DD * 384,
                                    cb2 + (size_t)ei * DD);
            dim3 gm(EE, LRK);
            m_kernel<<<gm, 256>>>(bu + (size_t)ei * EE * II * LRK,
                                  ad + (size_t)ei * EE * LRK * II);
            cudaMemsetAsync(u, 0, (size_t)TN * ELR * sizeof(float));
            cudaMemsetAsync(vv, 0, (size_t)TN * ELR * sizeof(float));
            gemm_kernel<<<gu, 256>>>(nres, au + (size_t)ei * EE * LRK * HH, u, ELR, HH, 2);
            gemm_kernel<<<gv, 256>>>(hid, ad + (size_t)ei * EE * LRK * II, vv, ELR, II, 4);
            t_kernel<<<TN, ELR>>>();
            comb_kernel<<<TN, 256>>>(bd + (size_t)ei * EE * HH * LRK, maskp);
        }
    }
    ln_kernel<<<TN, 256>>>(h, nullptr, nullptr, out, nullptr, nullptr, lnfg, lnfb, 1e-12f);
}

// round 10
// speedup vs baseline: 1.7864x; 1.0569x over previous
#include <cuda_runtime.h>
#include <cuda_bf16.h>
#include <math.h>
#include <stdint.h>

#define BQ 128
#define SS 30
#define HH 768
#define II 3072
#define LL 12
#define NHD 12
#define HD 64
#define EE 15
#define DD 14
#define RR 29
#define LRK 8
#define TN (BQ*SS)        // 3840 tokens
#define ELR (EE*LRK)      // 120
#define SCALF 2.0f

// ---------------- scratch (device globals; no allocation) ----------------
__device__ float g_h[TN*HH];
__device__ float g_q[TN*HH];
__device__ float g_k[TN*HH];
__device__ float g_v[TN*HH];
__device__ float g_att[TN*HH];
__device__ float g_res1[TN*HH];
__device__ float g_nres[TN*HH];
__device__ float g_hid[TN*II];
__device__ float g_bout[TN*HH];
__device__ float g_u[TN*ELR];
__device__ float g_vv[TN*ELR];
__device__ float g_t[TN*ELR];
__device__ float g_M[EE*LRK*LRK];
__device__ float g_gate[BQ*DD];

// bf16 hi/lo activation buffers
__device__ __nv_bfloat16 g_nxh[TN*HH],   g_nxl[TN*HH];
__device__ __nv_bfloat16 g_nresh[TN*HH], g_nresl[TN*HH];
__device__ __nv_bfloat16 g_ctxh[TN*HH],  g_ctxl[TN*HH];
__device__ __nv_bfloat16 g_hidh[TN*II],  g_hidl[TN*II];

// bf16 hi/lo weight buffers (split once per launch)
#define WSZ (LL*HH*HH)
#define WISZ (LL*II*HH)
__device__ __nv_bfloat16 g_wqh[WSZ],  g_wql[WSZ];
__device__ __nv_bfloat16 g_wkh[WSZ],  g_wkl[WSZ];
__device__ __nv_bfloat16 g_wvh[WSZ],  g_wvl[WSZ];
__device__ __nv_bfloat16 g_woh[WSZ],  g_wol[WSZ];
__device__ __nv_bfloat16 g_wih[WISZ], g_wil[WISZ];
__device__ __nv_bfloat16 g_wofh[WISZ], g_wofl[WISZ];

__device__ __forceinline__ float gelu_f(float x) {
    return 0.5f * x * (1.0f + erff(x * 0.70710678118654752f));
}

__device__ __forceinline__ uint32_t smaddr(const void* p) {
    uint32_t a;
    asm("{ .reg .u64 t; cvta.to.shared.u64 t, %1; cvt.u32.u64 %0, t; }" : "=r"(a) : "l"(p));
    return a;
}

#define LDSM4(r, a)                                                        \
    asm volatile("ldmatrix.sync.aligned.m8n8.x4.shared.b16 {%0,%1,%2,%3}, [%4];" \
        : "=r"((r)[0]), "=r"((r)[1]), "=r"((r)[2]), "=r"((r)[3]) : "r"(a))

#define MMABF(d, a, b)                                                     \
    asm volatile("mma.sync.aligned.m16n8k16.row.col.f32.bf16.bf16.f32 "    \
        "{%0,%1,%2,%3}, {%4,%5,%6,%7}, {%8,%9}, {%0,%1,%2,%3};"            \
        : "+f"((d)[0]), "+f"((d)[1]), "+f"((d)[2]), "+f"((d)[3])           \
        : "r"((a)[0]), "r"((a)[1]), "r"((a)[2]), "r"((a)[3]),              \
          "r"((b)[0]), "r"((b)[1]))

// ---------------- weight split (all 6 tensors, one launch) ----------------
#define WTOT (4*WSZ + 2*WISZ)
__global__ void wsplit_all_kernel(const float* __restrict__ wq, const float* __restrict__ wk,
                                  const float* __restrict__ wv, const float* __restrict__ wo,
                                  const float* __restrict__ wi, const float* __restrict__ wof) {
    int stride = gridDim.x * 256;
    for (long long i = blockIdx.x * 256 + threadIdx.x; i < WTOT; i += stride) {
        const float* s; __nv_bfloat16 *dh, *dl; long long j;
        if (i < (long long)WSZ)            { s = wq;  dh = g_wqh;  dl = g_wql;  j = i; }
        else if (i < 2LL*WSZ)              { s = wk;  dh = g_wkh;  dl = g_wkl;  j = i - WSZ; }
        else if (i < 3LL*WSZ)              { s = wv;  dh = g_wvh;  dl = g_wvl;  j = i - 2LL*WSZ; }
        else if (i < 4LL*WSZ)              { s = wo;  dh = g_woh;  dl = g_wol;  j = i - 3LL*WSZ; }
        else if (i < 4LL*WSZ + WISZ)       { s = wi;  dh = g_wih;  dl = g_wil;  j = i - 4LL*WSZ; }
        else                               { s = wof; dh = g_wofh; dl = g_wofl; j = i - 4LL*WSZ - WISZ; }
        float x = s[j];
        __nv_bfloat16 hv = __float2bfloat16_rn(x);
        dh[j] = hv;
        dl[j] = __float2bfloat16_rn(x - __bfloat162float(hv));
    }
}

// ---------------- embed ----------------
__global__ void embed_kernel(const float* __restrict__ rf, const float* __restrict__ cls) {
    int idx = blockIdx.x * 256 + threadIdx.x;
    if (idx >= TN * HH) return;
    int t = idx / HH, j = idx - t * HH;
    int s = t % SS, b = t / SS;
    g_h[idx] = (s == 0) ? cls[j] : rf[(b * RR + (s - 1)) * HH + j];
}

// ---------------- LayerNorm (H=768), optional residual / fp32 out / bf16 split out ----------------
__global__ void ln_kernel(const float* __restrict__ a, const float* __restrict__ b,
                          float* __restrict__ res_out, float* __restrict__ norm_out,
                          __nv_bfloat16* __restrict__ oh, __nv_bfloat16* __restrict__ ol,
                          const float* __restrict__ g, const float* __restrict__ bb,
                          float eps) {
    int t = blockIdx.x;
    int tid = threadIdx.x;
    const float* xa = a + (size_t)t * HH;
    const float* xb = b ? b + (size_t)t * HH : nullptr;
    __shared__ float s1[256], s2[256];
    float xv[3];
    float acc = 0.f, sq = 0.f;
#pragma unroll
    for (int i = 0; i < 3; i++) {
        int j = tid + i * 256;
        float v = xa[j];
        if (xb) v += xb[j];
        xv[i] = v; acc += v; sq += v * v;
        if (res_out) res_out[(size_t)t * HH + j] = v;
    }
    s1[tid] = acc; s2[tid] = sq;
    __syncthreads();
    for (int o = 128; o > 0; o >>= 1) {
        if (tid < o) { s1[tid] += s1[tid + o]; s2[tid] += s2[tid + o]; }
        __syncthreads();
    }
    float mean = s1[0] * (1.0f / 768.0f);
    float var = s2[0] * (1.0f / 768.0f) - mean * mean;
    float r = rsqrtf(var + eps);
#pragma unroll
    for (int i = 0; i < 3; i++) {
        int j = tid + i * 256;
        float y = (xv[i] - mean) * r * g[j] + bb[j];
        if (norm_out) norm_out[(size_t)t * HH + j] = y;
        if (oh) {
            __nv_bfloat16 hv = __float2bfloat16_rn(y);
            oh[(size_t)t * HH + j] = hv;
            ol[(size_t)t * HH + j] = __float2bfloat16_rn(y - __bfloat162float(hv));
        }
    }
}

// ---------------- bf16 2-term split GEMM (mma.sync m16n8k16) ----------------
// C[M,N] = A[M,K] @ W[N,K]^T (+bias)(gelu)(+add), A,W as bf16 hi/lo pairs.
// BM=64, BN=128, BK=64, 256 threads = 8 warps (2m x 4n), warp tile 32x32.
#define BKB 64
#define PITCH 144                 // bytes per smem row: 128 data + 16 pad
#define SMA (64*PITCH)            // 9216
#define SMW (128*PITCH)           // 18432
#define STGSZ (2*SMA+2*SMW)       // 55296
#define SMEMB (2*STGSZ)           // 110592
__device__ __forceinline__ void bgemm_body(
    const __nv_bfloat16* __restrict__ Ah, const __nv_bfloat16* __restrict__ Al,
    const __nv_bfloat16* __restrict__ Wph, const __nv_bfloat16* __restrict__ Wpl,
    const float* __restrict__ bias, const float* __restrict__ add,
    float* __restrict__ C,
    __nv_bfloat16* __restrict__ OH, __nv_bfloat16* __restrict__ OL,
    int N, int K, int act, char* sm, int bm, int bn) {
    uint32_t sbase = smaddr(sm);
    int tid = threadIdx.x, lane = tid & 31, warp = tid >> 5;
    int wm = warp >> 2, wn = warp & 3;

    // per-thread cp.async assignments: 3072 16B copies / 256 threads = 12 each
    const __nv_bfloat16* src[12];
    uint32_t dst0[12];
#pragma unroll
    for (int i = 0; i < 12; i++) {
        int c = tid + i * 256;
        int buf = c >> 9;                 // A-hi/A-lo at 512 each? no: see below
        int idx;
        if (c < 512) { buf = 0; idx = c; }
        else if (c < 1024) { buf = 1; idx = c - 512; }
        else if (c < 2048) { buf = 2; idx = c - 1024; }
        else { buf = 3; idx = c - 2048; }
        int row = idx >> 3;
        int seg = idx & 7;
        uint32_t soff = (buf == 0) ? 0u : (buf == 1) ? (uint32_t)SMA
                       : (buf == 2) ? (uint32_t)(2 * SMA) : (uint32_t)(2 * SMA + SMW);
        const __nv_bfloat16* g = (buf == 0) ? Ah : (buf == 1) ? Al : (buf == 2) ? Wph : Wpl;
        int grow = (buf < 2) ? (bm + row) : (bn + row);
        src[i] = g + (size_t)grow * K + seg * 8;
        dst0[i] = sbase + soff + (uint32_t)(row * PITCH + seg * 16);
    }
    int NCH = K / BKB;
#pragma unroll
    for (int i = 0; i < 12; i++)
        asm volatile("cp.async.cg.shared.global [%0], [%1], 16;" :: "r"(dst0[i]), "l"(src[i]));
    asm volatile("cp.async.commit_group;" ::: "memory");

    float acc[2][4][4];
#pragma unroll
    for (int mt = 0; mt < 2; mt++)
#pragma unroll
        for (int nt = 0; nt < 4; nt++)
#pragma unroll
            for (int r = 0; r < 4; r++) acc[mt][nt][r] = 0.f;

    for (int kc = 0; kc < NCH; kc++) {
        int s = kc & 1;
        if (kc + 1 < NCH) {
            uint32_t so = (uint32_t)(((kc + 1) & 1) * STGSZ);
#pragma unroll
            for (int i = 0; i < 12; i++)
                asm volatile("cp.async.cg.shared.global [%0], [%1], 16;"
                    :: "r"(dst0[i] + so), "l"(src[i] + (size_t)(kc + 1) * BKB));
            asm volatile("cp.async.commit_group;" ::: "memory");
            asm volatile("cp.async.wait_group 1;" ::: "memory");
        } else {
            asm volatile("cp.async.wait_group 0;" ::: "memory");
        }
        __syncthreads();
        uint32_t sb = sbase + (uint32_t)(s * STGSZ);
#pragma unroll
        for (int ks = 0; ks < 4; ks++) {
            uint32_t ah[2][4], alf[2][4], bh[4][2], bl[4][2];
#pragma unroll
            for (int mt = 0; mt < 2; mt++) {
                uint32_t ra = sb + (uint32_t)((wm * 32 + mt * 16 + (lane & 15)) * PITCH
                                              + ks * 32 + ((lane >> 4) << 4));
                LDSM4(ah[mt], ra);
                LDSM4(alf[mt], ra + SMA);
            }
#pragma unroll
            for (int np = 0; np < 2; np++) {
                uint32_t rb = sb + (uint32_t)(2 * SMA
                              + (wn * 32 + np * 16 + ((lane >> 4) << 3) + (lane & 7)) * PITCH
                              + ks * 32 + (((lane >> 3) & 1) << 4));
                uint32_t t0[4];
                LDSM4(t0, rb);
                bh[np * 2][0] = t0[0]; bh[np * 2][1] = t0[1];
                bh[np * 2 + 1][0] = t0[2]; bh[np * 2 + 1][1] = t0[3];
                LDSM4(t0, rb + SMW);
                bl[np * 2][0] = t0[0]; bl[np * 2][1] = t0[1];
                bl[np * 2 + 1][0] = t0[2]; bl[np * 2 + 1][1] = t0[3];
            }
#pragma unroll
            for (int mt = 0; mt < 2; mt++)
#pragma unroll
                for (int nt = 0; nt < 4; nt++) {
                    MMABF(acc[mt][nt], alf[mt], bh[nt]);
                    MMABF(acc[mt][nt], ah[mt], bl[nt]);
                    MMABF(acc[mt][nt], ah[mt], bh[nt]);
                }
        }
        __syncthreads();
    }

    // epilogue
#pragma unroll
    for (int mt = 0; mt < 2; mt++) {
#pragma unroll
        for (int nt = 0; nt < 4; nt++) {
            int col = bn + wn * 32 + nt * 8 + (lane & 3) * 2;
            float bv0 = 0.f, bv1 = 0.f;
            if (bias) { bv0 = bias[col]; bv1 = bias[col + 1]; }
#pragma unroll
            for (int hf = 0; hf < 2; hf++) {
                int row = bm + wm * 32 + mt * 16 + (lane >> 2) + hf * 8;
                float v0 = acc[mt][nt][hf * 2 + 0] + bv0;
                float v1 = acc[mt][nt][hf * 2 + 1] + bv1;
                if (act) { v0 = gelu_f(v0); v1 = gelu_f(v1); }
                if (add) {
                    v0 += add[(size_t)row * N + col];
                    v1 += add[(size_t)row * N + col + 1];
                }
                if (C) *(float2*)&C[(size_t)row * N + col] = make_float2(v0, v1);
                if (OH) {
                    __nv_bfloat16 h0 = __float2bfloat16_rn(v0);
                    __nv_bfloat16 h1 = __float2bfloat16_rn(v1);
                    __nv_bfloat16 l0 = __float2bfloat16_rn(v0 - __bfloat162float(h0));
                    __nv_bfloat16 l1 = __float2bfloat16_rn(v1 - __bfloat162float(h1));
                    *(__nv_bfloat162*)&OH[(size_t)row * N + col] = __nv_bfloat162(h0, h1);
                    *(__nv_bfloat162*)&OL[(size_t)row * N + col] = __nv_bfloat162(l0, l1);
                }
            }
        }
    }
}

__global__ void __launch_bounds__(256, 2)
bgemm_kernel(const __nv_bfloat16* __restrict__ Ah, const __nv_bfloat16* __restrict__ Al,
             const __nv_bfloat16* __restrict__ Wph, const __nv_bfloat16* __restrict__ Wpl,
             const float* __restrict__ bias, const float* __restrict__ add,
             float* __restrict__ C,
             __nv_bfloat16* __restrict__ OH, __nv_bfloat16* __restrict__ OL,
             int N, int K, int act) {
    extern __shared__ char sm[];
    bgemm_body(Ah, Al, Wph, Wpl, bias, add, C, OH, OL, N, K, act, sm,
               blockIdx.y * 64, blockIdx.x * 128);
}

struct QKV3 {
    const __nv_bfloat16 *wh0, *wl0, *wh1, *wl1, *wh2, *wl2;
    const float *b0, *b1, *b2;
    float *c0, *c1, *c2;
};

__global__ void __launch_bounds__(256, 2)
bgemm_qkv_kernel(const __nv_bfloat16* __restrict__ Ah, const __nv_bfloat16* __restrict__ Al,
                 QKV3 p, int N, int K) {
    extern __shared__ char sm[];
    int z = blockIdx.z;
    const __nv_bfloat16* wh = (z == 0) ? p.wh0 : (z == 1) ? p.wh1 : p.wh2;
    const __nv_bfloat16* wl = (z == 0) ? p.wl0 : (z == 1) ? p.wl1 : p.wl2;
    const float* bias = (z == 0) ? p.b0 : (z == 1) ? p.b1 : p.b2;
    float* C = (z == 0) ? p.c0 : (z == 1) ? p.c1 : p.c2;
    bgemm_body(Ah, Al, wh, wl, bias, nullptr, C, nullptr, nullptr, N, K, 0, sm,
               blockIdx.y * 64, blockIdx.x * 128);
}

// ---------------- fp32 SGEMM with optional split-K (skinny LoRA, N=120) ----------------
__global__ void gemm_kernel(const float* __restrict__ A, const float* __restrict__ W,
                            float* __restrict__ C, int N, int K, int nsplit) {
    __shared__ float As[16][64];
    __shared__ float Bs[16][64];
    int bm = blockIdx.y * 64, bn = blockIdx.x * 64;
    int kchunk = K / nsplit;
    int kbeg = blockIdx.z * kchunk;
    int kend = kbeg + kchunk;
    int tid = threadIdx.x;
    int tx = tid & 15, ty = tid >> 4;
    int lr = tid >> 2;
    int lc = (tid & 3) << 2;
    float acc[4][4] = {};
    const float* Aptr = A + (size_t)(bm + lr) * K + lc;
    int wrow = bn + lr;
    const float* Wptr = W + (size_t)wrow * K + lc;
    for (int k0 = kbeg; k0 < kend; k0 += 16) {
        float4 a4 = *(const float4*)(Aptr + k0);
        float4 b4 = (wrow < N) ? *(const float4*)(Wptr + k0) : make_float4(0.f, 0.f, 0.f, 0.f);
        As[lc + 0][lr] = a4.x; As[lc + 1][lr] = a4.y; As[lc + 2][lr] = a4.z; As[lc + 3][lr] = a4.w;
        Bs[lc + 0][lr] = b4.x; Bs[lc + 1][lr] = b4.y; Bs[lc + 2][lr] = b4.z; Bs[lc + 3][lr] = b4.w;
        __syncthreads();
#pragma unroll
        for (int kk = 0; kk < 16; kk++) {
            float4 ra = *(const float4*)&As[kk][ty << 2];
            float4 rb = *(const float4*)&Bs[kk][tx << 2];
            float raa[4] = {ra.x, ra.y, ra.z, ra.w};
            float rbb[4] = {rb.x, rb.y, rb.z, rb.w};
#pragma unroll
            for (int i = 0; i < 4; i++)
#pragma unroll
                for (int j = 0; j < 4; j++)
                    acc[i][j] += raa[i] * rbb[j];
        }
        __syncthreads();
    }
#pragma unroll
    for (int i = 0; i < 4; i++) {
        int m = bm + (ty << 2) + i;
#pragma unroll
        for (int j = 0; j < 4; j++) {
            int n = bn + (tx << 2) + j;
            if (n < N) {
                if (nsplit > 1) atomicAdd(&C[(size_t)m * N + n], acc[i][j]);
                else C[(size_t)m * N + n] = acc[i][j];
            }
        }
    }
}

// ---------------- attention: one block per (batch, head); emits bf16 split ctx ----------------
__global__ void attn_kernel() {
    int bh = blockIdx.x;
    int b = bh / NHD, hh = bh - b * NHD;
    __shared__ float sq[SS][HD], sk[SS][HD], sv[SS][HD], sc[SS][SS + 1];
    int tid = threadIdx.x;
    int base = b * SS;
    for (int i = tid; i < SS * HD; i += 256) {
        int s = i >> 6, d = i & 63;
        int gi = (base + s) * HH + hh * HD + d;
        sq[s][d] = g_q[gi]; sk[s][d] = g_k[gi]; sv[s][d] = g_v[gi];
    }
    __syncthreads();
    for (int i = tid; i < SS * SS; i += 256) {
        int r = i / SS, c = i - r * SS;
        float s = 0.f;
#pragma unroll
        for (int d = 0; d < HD; d++) s += sq[r][d] * sk[c][d];
        sc[r][c] = s * 0.125f;
    }
    __syncthreads();
    if (tid < SS) {
        float mx = -1e30f;
        for (int c = 0; c < SS; c++) mx = fmaxf(mx, sc[tid][c]);
        float sm = 0.f;
        for (int c = 0; c < SS; c++) { float e = expf(sc[tid][c] - mx); sc[tid][c] = e; sm += e; }
        float inv = 1.0f / sm;
        for (int c = 0; c < SS; c++) sc[tid][c] *= inv;
    }
    __syncthreads();
    for (int i = tid; i < SS * HD; i += 256) {
        int s = i >> 6, d = i & 63;
        float o = 0.f;
#pragma unroll
        for (int c = 0; c < SS; c++) o += sc[s][c] * sv[c][d];
        int gi = (base + s) * HH + hh * HD + d;
        __nv_bfloat16 hv = __float2bfloat16_rn(o);
        g_ctxh[gi] = hv;
        g_ctxl[gi] = __float2bfloat16_rn(o - __bfloat162float(hv));
    }
}

// ---------------- per-disease classifiers -> gate[b,d] ----------------
__global__ void cls_kernel(const float* __restrict__ mask,
                           const float* __restrict__ cw1, const float* __restrict__ cb1,
                           const float* __restrict__ clg, const float* __restrict__ clb,
                           const float* __restrict__ cw2, const float* __restrict__ cb2) {
    int b = blockIdx.x, d = blockIdx.y;
    int tid = threadIdx.x;
    __shared__ float pooled[HH];
    __shared__ float h1[384];
    __shared__ float r1[256], r2[256];
    float cnt = 0.f;
    for (int r = 0; r < RR; r++) cnt += (mask[r * DD + d] > 0.f) ? 1.f : 0.f;
    float inv = 1.0f / fmaxf(cnt, 1.0f);
    for (int j = tid; j < HH; j += 256) {
        float s = 0.f;
        for (int r = 0; r < RR; r++)
            if (mask[r * DD + d] > 0.f) s += g_att[(b * SS + 1 + r) * HH + j];
        pooled[j] = s * inv;
    }
    __syncthreads();
    for (int k = tid; k < 384; k += 256) {
        const float* wrow = cw1 + ((size_t)d * 384 + k) * HH;
        float s = 0.f;
        for (int j = 0; j < HH; j++) s += pooled[j] * wrow[j];
        h1[k] = s + cb1[d * 384 + k];
    }
    __syncthreads();
    float a = 0.f, sq = 0.f;
    for (int k = tid; k < 384; k += 256) { float v = h1[k]; a += v; sq += v * v; }
    r1[tid] = a; r2[tid] = sq;
    __syncthreads();
    for (int o = 128; o > 0; o >>= 1) {
        if (tid < o) { r1[tid] += r1[tid + o]; r2[tid] += r2[tid + o]; }
        __syncthreads();
    }
    float mean = r1[0] * (1.0f / 384.0f);
    float var = r2[0] * (1.0f / 384.0f) - mean * mean;
    float rn = rsqrtf(var + 1e-5f);
    __syncthreads();
    float p = 0.f;
    for (int k = tid; k < 384; k += 256) {
        float v = (h1[k] - mean) * rn * clg[d * 384 + k] + clb[d * 384 + k];
        v = gelu_f(v);
        p += v * cw2[d * 384 + k];
    }
    r1[tid] = p;
    __syncthreads();
    for (int o = 128; o > 0; o >>= 1) {
        if (tid < o) r1[tid] += r1[tid + o];
        __syncthreads();
    }
    if (tid == 0) {
        float pred = r1[0] + cb2[d];
        g_gate[b * DD + d] = (cnt > 0.f && pred > 0.f) ? 1.f : 0.f;
    }
}

// ---------------- M[e] = Bu_e^T @ Ad_e^T  (block per (e, col)) ----------------
__global__ void m_kernel(const float* __restrict__ bu, const float* __restrict__ ad) {
    int e = blockIdx.x, c = blockIdx.y;
    int tid = threadIdx.x;
    float s[LRK] = {};
    const float* bup = bu + (size_t)e * II * LRK;
    const float* adp = ad + ((size_t)e * LRK + c) * II;
    for (int i = tid; i < II; i += 256) {
        float a = adp[i];
        const float* bp = bup + (size_t)i * LRK;
#pragma unroll
        for (int r = 0; r < LRK; r++) s[r] += bp[r] * a;
    }
    __shared__ float red[256];
    for (int r = 0; r < LRK; r++) {
        red[tid] = s[r];
        __syncthreads();
        for (int o = 128; o > 0; o >>= 1) {
            if (tid < o) red[tid] += red[tid + o];
            __syncthreads();
        }
        if (tid == 0) g_M[(e * LRK + r) * LRK + c] = red[0];
        __syncthreads();
    }
}

// ---------------- t = v + SCAL * u @ M ----------------
__global__ void t_kernel() {
    int token = blockIdx.x;
    int er = threadIdx.x;
    int e = er >> 3, r = er & 7;
    __shared__ float su[ELR];
    su[er] = g_u[token * ELR + er];
    __syncthreads();
    float s = 0.f;
#pragma unroll
    for (int q = 0; q < LRK; q++) s += su[e * LRK + q] * g_M[(e * LRK + q) * LRK + r];
    g_t[token * ELR + er] = g_vv[token * ELR + er] + SCALF * s;
}

// ---------------- expert mix ----------------
__global__ void comb_kernel(const float* __restrict__ bd, const float* __restrict__ mask) {
    int token = blockIdx.x;
    int b = token / SS, s = token - b * SS;
    int tid = threadIdx.x;
    __shared__ float r1[256], r2[256];
    __shared__ float sw[16];
    if (tid < EE) {
        float a;
        if (tid == 14) a = 1.f;
        else a = (s > 0 && mask[(s - 1) * DD + tid] > 0.f) ? g_gate[b * DD + tid] : 0.f;
        sw[tid] = a;
    }
    __syncthreads();
    float nact = 0.f;
#pragma unroll
    for (int e = 0; e < EE; e++) nact += sw[e];
    float wt = 1.0f / fmaxf(nact, 1.0f);
    float bo0[3], acc[3] = {0.f, 0.f, 0.f};
#pragma unroll
    for (int i = 0; i < 3; i++) bo0[i] = g_bout[token * HH + tid + i * 256];
    for (int e = 0; e < EE; e++) {
        if (sw[e] == 0.f) continue;
        float t8[8];
        const float* tp = g_t + token * ELR + e * LRK;
#pragma unroll
        for (int r = 0; r < 8; r++) t8[r] = tp[r];
        float o[3];
        float a = 0.f, sq = 0.f;
#pragma unroll
        for (int i = 0; i < 3; i++) {
            int j = tid + i * 256;
            const float* bdp = bd + ((size_t)e * HH + j) * LRK;
            float dv = 0.f;
#pragma unroll
            for (int r = 0; r < 8; r++) dv += t8[r] * bdp[r];
            float ov = bo0[i] + SCALF * dv;
            o[i] = ov; a += ov; sq += ov * ov;
        }
        r1[tid] = a; r2[tid] = sq;
        __syncthreads();
        for (int off = 128; off > 0; off >>= 1) {
            if (tid < off) { r1[tid] += r1[tid + off]; r2[tid] += r2[tid + off]; }
            __syncthreads();
        }
        float mean = r1[0] * (1.0f / 768.0f);
        float var = r2[0] * (1.0f / 768.0f) - mean * mean;
        float rn = rsqrtf(var + 1e-5f);
#pragma unroll
        for (int i = 0; i < 3; i++) acc[i] += wt * (o[i] - mean) * rn;
        __syncthreads();
    }
#pragma unroll
    for (int i = 0; i < 3; i++) {
        int j = tid + i * 256;
        g_h[token * HH + j] = acc[i] + g_res1[token * HH + j];
    }
}

// ---------------- host launcher ----------------
extern "C" void kernel_launch(void* const* d_in, const int* in_sizes, int n_in,
                              void* d_out, int out_size) {
    const float* rf   = (const float*)d_in[0];
    const float* cls  = (const float*)d_in[1];
    const float* ln1g = (const float*)d_in[2];
    const float* ln1b = (const float*)d_in[3];
    const float* ln2g = (const float*)d_in[4];
    const float* ln2b = (const float*)d_in[5];
    const float* wq   = (const float*)d_in[6];
    const float* bq   = (const float*)d_in[7];
    const float* wk   = (const float*)d_in[8];
    const float* bk   = (const float*)d_in[9];
    const float* wv   = (const float*)d_in[10];
    const float* bv   = (const float*)d_in[11];
    const float* wo   = (const float*)d_in[12];
    const float* bo   = (const float*)d_in[13];
    const float* wi   = (const float*)d_in[14];
    const float* bi   = (const float*)d_in[15];
    const float* wof  = (const float*)d_in[16];
    const float* bof  = (const float*)d_in[17];
    const float* lnfg = (const float*)d_in[18];
    const float* lnfb = (const float*)d_in[19];
    const float* au   = (const float*)d_in[20];
    const float* bu   = (const float*)d_in[21];
    const float* ad   = (const float*)d_in[22];
    const float* bd   = (const float*)d_in[23];
    const float* cw1  = (const float*)d_in[24];
    const float* cb1  = (const float*)d_in[25];
    const float* clg  = (const float*)d_in[26];
    const float* clb  = (const float*)d_in[27];
    const float* cw2  = (const float*)d_in[28];
    const float* cb2  = (const float*)d_in[29];
    const float* maskp= (const float*)d_in[30];
    float* out = (float*)d_out;

    float *h, *q, *k, *v, *att, *res1, *nres, *hid, *bout, *u, *vv;
    cudaGetSymbolAddress((void**)&h,    g_h);
    cudaGetSymbolAddress((void**)&q,    g_q);
    cudaGetSymbolAddress((void**)&k,    g_k);
    cudaGetSymbolAddress((void**)&v,    g_v);
    cudaGetSymbolAddress((void**)&att,  g_att);
    cudaGetSymbolAddress((void**)&res1, g_res1);
    cudaGetSymbolAddress((void**)&nres, g_nres);
    cudaGetSymbolAddress((void**)&hid,  g_hid);
    cudaGetSymbolAddress((void**)&bout, g_bout);
    cudaGetSymbolAddress((void**)&u,    g_u);
    cudaGetSymbolAddress((void**)&vv,   g_vv);

    __nv_bfloat16 *nxh, *nxl, *nresh, *nresl, *ctxh, *ctxl, *hidh, *hidl;
    __nv_bfloat16 *wqh, *wql, *wkh, *wkl, *wvh, *wvl, *woh, *wol, *wih, *wil, *wofh, *wofl;
    cudaGetSymbolAddress((void**)&nxh,   g_nxh);
    cudaGetSymbolAddress((void**)&nxl,   g_nxl);
    cudaGetSymbolAddress((void**)&nresh, g_nresh);
    cudaGetSymbolAddress((void**)&nresl, g_nresl);
    cudaGetSymbolAddress((void**)&ctxh,  g_ctxh);
    cudaGetSymbolAddress((void**)&ctxl,  g_ctxl);
    cudaGetSymbolAddress((void**)&hidh,  g_hidh);
    cudaGetSymbolAddress((void**)&hidl,  g_hidl);
    cudaGetSymbolAddress((void**)&wqh,   g_wqh);
    cudaGetSymbolAddress((void**)&wql,   g_wql);
    cudaGetSymbolAddress((void**)&wkh,   g_wkh);
    cudaGetSymbolAddress((void**)&wkl,   g_wkl);
    cudaGetSymbolAddress((void**)&wvh,   g_wvh);
    cudaGetSymbolAddress((void**)&wvl,   g_wvl);
    cudaGetSymbolAddress((void**)&woh,   g_woh);
    cudaGetSymbolAddress((void**)&wol,   g_wol);
    cudaGetSymbolAddress((void**)&wih,   g_wih);
    cudaGetSymbolAddress((void**)&wil,   g_wil);
    cudaGetSymbolAddress((void**)&wofh,  g_wofh);
    cudaGetSymbolAddress((void**)&wofl,  g_wofl);

    cudaFuncSetAttribute(bgemm_kernel, cudaFuncAttributeMaxDynamicSharedMemorySize, SMEMB);
    cudaFuncSetAttribute(bgemm_qkv_kernel, cudaFuncAttributeMaxDynamicSharedMemorySize, SMEMB);

    wsplit_all_kernel<<<16384, 256>>>(wq, wk, wv, wo, wi, wof);

    dim3 b768(HH / 128, TN / 64);        // 6 x 60
    dim3 bqkv(HH / 128, TN / 64, 3);     // 6 x 60 x 3
    dim3 b3072(II / 128, TN / 64);       // 24 x 60
    dim3 gu(2, TN / 64, 2);
    dim3 gv(2, TN / 64, 4);
    int nel = TN * HH;
    int nblk = (nel + 255) / 256;

    embed_kernel<<<nblk, 256>>>(rf, cls);

    for (int i = 0; i < LL; i++) {
        size_t woff  = (size_t)i * HH * HH;
        size_t wioff = (size_t)i * II * HH;
        int even = ((i & 1) == 0);
        ln_kernel<<<TN, 256>>>(h, nullptr, nullptr, nullptr, nxh, nxl,
                               ln1g + i * HH, ln1b + i * HH, 1e-12f);
        QKV3 p;
        p.wh0 = wqh + woff; p.wl0 = wql + woff;
        p.wh1 = wkh + woff; p.wl1 = wkl + woff;
        p.wh2 = wvh + woff; p.wl2 = wvl + woff;
        p.b0 = bq + i * HH; p.b1 = bk + i * HH; p.b2 = bv + i * HH;
        p.c0 = q; p.c1 = k; p.c2 = v;
        bgemm_qkv_kernel<<<bqkv, 256, SMEMB>>>(nxh, nxl, p, HH, HH);
        attn_kernel<<<BQ * NHD, 256>>>();
        bgemm_kernel<<<b768, 256, SMEMB>>>(ctxh, ctxl, woh + woff, wol + woff, bo + i * HH,
                                           nullptr, att, nullptr, nullptr, HH, HH, 0);
        ln_kernel<<<TN, 256>>>(att, h, res1, even ? nres : nullptr, nresh, nresl,
                               ln2g + i * HH, ln2b + i * HH, 1e-12f);
        bgemm_kernel<<<b3072, 256, SMEMB>>>(nresh, nresl, wih + wioff, wil + wioff, bi + i * II,
                                            nullptr, even ? hid : nullptr, hidh, hidl, II, HH, 1);
        if (!even) {
            bgemm_kernel<<<b768, 256, SMEMB>>>(hidh, hidl, wofh + wioff, wofl + wioff, bof + i * HH,
                                               res1, h, nullptr, nullptr, HH, II, 0);
        } else {
            int ei = i / 2;
            bgemm_kernel<<<b768, 256, SMEMB>>>(hidh, hidl, wofh + wioff, wofl + wioff, bof + i * HH,
                                               nullptr, bout, nullptr, nullptr, HH, II, 0);
            dim3 gc(BQ, DD);
            cls_kernel<<<gc, 256>>>(maskp,
                                    cw1 + (size_t)ei * DD * 384 * HH,
                                    cb1 + (size_t)ei * DD * 384,
                                    clg + (size_t)ei * DD * 384,
                                    clb + (size_t)ei * DD * 384,
                                    cw2 + (size_t)ei * DD * 384,
                                    cb2 + (size_t)ei * DD);
            dim3 gm(EE, LRK);
            m_kernel<<<gm, 256>>>(bu + (size_t)ei * EE * II * LRK,
                                  ad + (size_t)ei * EE * LRK * II);
            cudaMemsetAsync(u, 0, (size_t)TN * ELR * sizeof(float));
            cudaMemsetAsync(vv, 0, (size_t)TN * ELR * sizeof(float));
            gemm_kernel<<<gu, 256>>>(nres, au + (size_t)ei * EE * LRK * HH, u, ELR, HH, 2);
            gemm_kernel<<<gv, 256>>>(hid, ad + (size_t)ei * EE * LRK * II, vv, ELR, II, 4);
            t_kernel<<<TN, ELR>>>();
            comb_kernel<<<TN, 256>>>(bd + (size_t)ei * EE * HH * LRK, maskp);
        }
    }
    ln_kernel<<<TN, 256>>>(h, nullptr, nullptr, out, nullptr, nullptr, lnfg, lnfb, 1e-12f);
}

// round 11
// speedup vs baseline: 2.9465x; 1.6494x over previous
#include <cuda_runtime.h>
#include <cuda_bf16.h>
#include <math.h>
#include <stdint.h>

#define BQ 128
#define SS 30
#define HH 768
#define II 3072
#define LL 12
#define NHD 12
#define HD 64
#define EE 15
#define DD 14
#define RR 29
#define LRK 8
#define TN (BQ*SS)        // 3840 tokens
#define ELR (EE*LRK)      // 120
#define SCALF 2.0f

// ---------------- scratch (device globals; no allocation) ----------------
__device__ float g_h[TN*HH];
__device__ float g_q[TN*HH];
__device__ float g_k[TN*HH];
__device__ float g_v[TN*HH];
__device__ float g_att[TN*HH];
__device__ float g_res1[TN*HH];
__device__ float g_nres[TN*HH];
__device__ float g_hid[TN*II];
__device__ float g_bout[TN*HH];
__device__ float g_u[TN*ELR];
__device__ float g_vv[TN*ELR];
__device__ float g_M[EE*LRK*LRK];
__device__ float g_gate[BQ*DD];

// bf16 hi/lo activation buffers
__device__ __nv_bfloat16 g_nxh[TN*HH],   g_nxl[TN*HH];
__device__ __nv_bfloat16 g_nresh[TN*HH], g_nresl[TN*HH];
__device__ __nv_bfloat16 g_ctxh[TN*HH],  g_ctxl[TN*HH];
__device__ __nv_bfloat16 g_hidh[TN*II],  g_hidl[TN*II];

// bf16 hi/lo weight buffers (split once per launch)
#define WSZ (LL*HH*HH)
#define WISZ (LL*II*HH)
__device__ __nv_bfloat16 g_wqh[WSZ],  g_wql[WSZ];
__device__ __nv_bfloat16 g_wkh[WSZ],  g_wkl[WSZ];
__device__ __nv_bfloat16 g_wvh[WSZ],  g_wvl[WSZ];
__device__ __nv_bfloat16 g_woh[WSZ],  g_wol[WSZ];
__device__ __nv_bfloat16 g_wih[WISZ], g_wil[WISZ];
__device__ __nv_bfloat16 g_wofh[WISZ], g_wofl[WISZ];

__device__ __forceinline__ float gelu_f(float x) {
    return 0.5f * x * (1.0f + erff(x * 0.70710678118654752f));
}

__device__ __forceinline__ uint32_t smaddr(const void* p) {
    uint32_t a;
    asm("{ .reg .u64 t; cvta.to.shared.u64 t, %1; cvt.u32.u64 %0, t; }" : "=r"(a) : "l"(p));
    return a;
}

#define LDSM4(r, a)                                                        \
    asm volatile("ldmatrix.sync.aligned.m8n8.x4.shared.b16 {%0,%1,%2,%3}, [%4];" \
        : "=r"((r)[0]), "=r"((r)[1]), "=r"((r)[2]), "=r"((r)[3]) : "r"(a))

#define MMABF(d, a, b)                                                     \
    asm volatile("mma.sync.aligned.m16n8k16.row.col.f32.bf16.bf16.f32 "    \
        "{%0,%1,%2,%3}, {%4,%5,%6,%7}, {%8,%9}, {%0,%1,%2,%3};"            \
        : "+f"((d)[0]), "+f"((d)[1]), "+f"((d)[2]), "+f"((d)[3])           \
        : "r"((a)[0]), "r"((a)[1]), "r"((a)[2]), "r"((a)[3]),              \
          "r"((b)[0]), "r"((b)[1]))

// ---------------- weight split (all 6 tensors, one launch) ----------------
#define WTOT (4*WSZ + 2*WISZ)
__global__ void wsplit_all_kernel(const float* __restrict__ wq, const float* __restrict__ wk,
                                  const float* __restrict__ wv, const float* __restrict__ wo,
                                  const float* __restrict__ wi, const float* __restrict__ wof) {
    int stride = gridDim.x * 256;
    for (long long i = blockIdx.x * 256 + threadIdx.x; i < WTOT; i += stride) {
        const float* s; __nv_bfloat16 *dh, *dl; long long j;
        if (i < (long long)WSZ)            { s = wq;  dh = g_wqh;  dl = g_wql;  j = i; }
        else if (i < 2LL*WSZ)              { s = wk;  dh = g_wkh;  dl = g_wkl;  j = i - WSZ; }
        else if (i < 3LL*WSZ)              { s = wv;  dh = g_wvh;  dl = g_wvl;  j = i - 2LL*WSZ; }
        else if (i < 4LL*WSZ)              { s = wo;  dh = g_woh;  dl = g_wol;  j = i - 3LL*WSZ; }
        else if (i < 4LL*WSZ + WISZ)       { s = wi;  dh = g_wih;  dl = g_wil;  j = i - 4LL*WSZ; }
        else                               { s = wof; dh = g_wofh; dl = g_wofl; j = i - 4LL*WSZ - WISZ; }
        float x = s[j];
        __nv_bfloat16 hv = __float2bfloat16_rn(x);
        dh[j] = hv;
        dl[j] = __float2bfloat16_rn(x - __bfloat162float(hv));
    }
}

// ---------------- embed ----------------
__global__ void embed_kernel(const float* __restrict__ rf, const float* __restrict__ cls) {
    int idx = blockIdx.x * 256 + threadIdx.x;
    if (idx >= TN * HH) return;
    int t = idx / HH, j = idx - t * HH;
    int s = t % SS, b = t / SS;
    g_h[idx] = (s == 0) ? cls[j] : rf[(b * RR + (s - 1)) * HH + j];
}

// ---------------- LayerNorm: warp per token, shuffle reductions ----------------
// grid = TN/8, block = 256 (8 warps). res = a (+b); outputs optional.
__global__ void ln_kernel(const float* __restrict__ a, const float* __restrict__ b,
                          float* __restrict__ res_out, float* __restrict__ norm_out,
                          __nv_bfloat16* __restrict__ oh, __nv_bfloat16* __restrict__ ol,
                          const float* __restrict__ g, const float* __restrict__ bb,
                          float eps) {
    int tid = threadIdx.x, lane = tid & 31, w = tid >> 5;
    int t = blockIdx.x * 8 + w;
    const float4* xa = (const float4*)(a + (size_t)t * HH);
    const float4* xb = b ? (const float4*)(b + (size_t)t * HH) : nullptr;
    float4 xv[6];
    float s = 0.f, sq = 0.f;
#pragma unroll
    for (int i = 0; i < 6; i++) {
        int f = lane + 32 * i;
        float4 v = xa[f];
        if (xb) { float4 u = xb[f]; v.x += u.x; v.y += u.y; v.z += u.z; v.w += u.w; }
        xv[i] = v;
        s += v.x + v.y + v.z + v.w;
        sq += v.x * v.x + v.y * v.y + v.z * v.z + v.w * v.w;
        if (res_out) ((float4*)(res_out + (size_t)t * HH))[f] = v;
    }
#pragma unroll
    for (int o = 16; o; o >>= 1) {
        s += __shfl_xor_sync(0xFFFFFFFFu, s, o);
        sq += __shfl_xor_sync(0xFFFFFFFFu, sq, o);
    }
    float mean = s * (1.0f / 768.0f);
    float var = sq * (1.0f / 768.0f) - mean * mean;
    float r = rsqrtf(var + eps);
#pragma unroll
    for (int i = 0; i < 6; i++) {
        int f = lane + 32 * i;
        float4 gv = ((const float4*)g)[f];
        float4 bv = ((const float4*)bb)[f];
        float y0 = (xv[i].x - mean) * r * gv.x + bv.x;
        float y1 = (xv[i].y - mean) * r * gv.y + bv.y;
        float y2 = (xv[i].z - mean) * r * gv.z + bv.z;
        float y3 = (xv[i].w - mean) * r * gv.w + bv.w;
        if (norm_out)
            ((float4*)(norm_out + (size_t)t * HH))[f] = make_float4(y0, y1, y2, y3);
        if (oh) {
            __nv_bfloat16 h0 = __float2bfloat16_rn(y0), h1 = __float2bfloat16_rn(y1);
            __nv_bfloat16 h2 = __float2bfloat16_rn(y2), h3 = __float2bfloat16_rn(y3);
            __nv_bfloat162* ohp = (__nv_bfloat162*)(oh + (size_t)t * HH);
            __nv_bfloat162* olp = (__nv_bfloat162*)(ol + (size_t)t * HH);
            ohp[2 * f] = __nv_bfloat162(h0, h1);
            ohp[2 * f + 1] = __nv_bfloat162(h2, h3);
            olp[2 * f] = __nv_bfloat162(__float2bfloat16_rn(y0 - __bfloat162float(h0)),
                                        __float2bfloat16_rn(y1 - __bfloat162float(h1)));
            olp[2 * f + 1] = __nv_bfloat162(__float2bfloat16_rn(y2 - __bfloat162float(h2)),
                                            __float2bfloat16_rn(y3 - __bfloat162float(h3)));
        }
    }
}

// ---------------- bf16 2-term split GEMM (mma.sync m16n8k16) ----------------
#define BKB 64
#define PITCH 144
#define SMA (64*PITCH)
#define SMW (128*PITCH)
#define STGSZ (2*SMA+2*SMW)
#define SMEMB (2*STGSZ)
__device__ __forceinline__ void bgemm_body(
    const __nv_bfloat16* __restrict__ Ah, const __nv_bfloat16* __restrict__ Al,
    const __nv_bfloat16* __restrict__ Wph, const __nv_bfloat16* __restrict__ Wpl,
    const float* __restrict__ bias, const float* __restrict__ add,
    float* __restrict__ C,
    __nv_bfloat16* __restrict__ OH, __nv_bfloat16* __restrict__ OL,
    int N, int K, int act, char* sm, int bm, int bn) {
    uint32_t sbase = smaddr(sm);
    int tid = threadIdx.x, lane = tid & 31, warp = tid >> 5;
    int wm = warp >> 2, wn = warp & 3;

    const __nv_bfloat16* src[12];
    uint32_t dst0[12];
#pragma unroll
    for (int i = 0; i < 12; i++) {
        int c = tid + i * 256;
        int buf, idx;
        if (c < 512) { buf = 0; idx = c; }
        else if (c < 1024) { buf = 1; idx = c - 512; }
        else if (c < 2048) { buf = 2; idx = c - 1024; }
        else { buf = 3; idx = c - 2048; }
        int row = idx >> 3;
        int seg = idx & 7;
        uint32_t soff = (buf == 0) ? 0u : (buf == 1) ? (uint32_t)SMA
                       : (buf == 2) ? (uint32_t)(2 * SMA) : (uint32_t)(2 * SMA + SMW);
        const __nv_bfloat16* g = (buf == 0) ? Ah : (buf == 1) ? Al : (buf == 2) ? Wph : Wpl;
        int grow = (buf < 2) ? (bm + row) : (bn + row);
        src[i] = g + (size_t)grow * K + seg * 8;
        dst0[i] = sbase + soff + (uint32_t)(row * PITCH + seg * 16);
    }
    int NCH = K / BKB;
#pragma unroll
    for (int i = 0; i < 12; i++)
        asm volatile("cp.async.cg.shared.global [%0], [%1], 16;" :: "r"(dst0[i]), "l"(src[i]));
    asm volatile("cp.async.commit_group;" ::: "memory");

    float acc[2][4][4];
#pragma unroll
    for (int mt = 0; mt < 2; mt++)
#pragma unroll
        for (int nt = 0; nt < 4; nt++)
#pragma unroll
            for (int r = 0; r < 4; r++) acc[mt][nt][r] = 0.f;

    for (int kc = 0; kc < NCH; kc++) {
        int s = kc & 1;
        if (kc + 1 < NCH) {
            uint32_t so = (uint32_t)(((kc + 1) & 1) * STGSZ);
#pragma unroll
            for (int i = 0; i < 12; i++)
                asm volatile("cp.async.cg.shared.global [%0], [%1], 16;"
                    :: "r"(dst0[i] + so), "l"(src[i] + (size_t)(kc + 1) * BKB));
            asm volatile("cp.async.commit_group;" ::: "memory");
            asm volatile("cp.async.wait_group 1;" ::: "memory");
        } else {
            asm volatile("cp.async.wait_group 0;" ::: "memory");
        }
        __syncthreads();
        uint32_t sb = sbase + (uint32_t)(s * STGSZ);
#pragma unroll
        for (int ks = 0; ks < 4; ks++) {
            uint32_t ah[2][4], alf[2][4], bh[4][2], bl[4][2];
#pragma unroll
            for (int mt = 0; mt < 2; mt++) {
                uint32_t ra = sb + (uint32_t)((wm * 32 + mt * 16 + (lane & 15)) * PITCH
                                              + ks * 32 + ((lane >> 4) << 4));
                LDSM4(ah[mt], ra);
                LDSM4(alf[mt], ra + SMA);
            }
#pragma unroll
            for (int np = 0; np < 2; np++) {
                uint32_t rb = sb + (uint32_t)(2 * SMA
                              + (wn * 32 + np * 16 + ((lane >> 4) << 3) + (lane & 7)) * PITCH
                              + ks * 32 + (((lane >> 3) & 1) << 4));
                uint32_t t0[4];
                LDSM4(t0, rb);
                bh[np * 2][0] = t0[0]; bh[np * 2][1] = t0[1];
                bh[np * 2 + 1][0] = t0[2]; bh[np * 2 + 1][1] = t0[3];
                LDSM4(t0, rb + SMW);
                bl[np * 2][0] = t0[0]; bl[np * 2][1] = t0[1];
                bl[np * 2 + 1][0] = t0[2]; bl[np * 2 + 1][1] = t0[3];
            }
#pragma unroll
            for (int mt = 0; mt < 2; mt++)
#pragma unroll
                for (int nt = 0; nt < 4; nt++) {
                    MMABF(acc[mt][nt], alf[mt], bh[nt]);
                    MMABF(acc[mt][nt], ah[mt], bl[nt]);
                    MMABF(acc[mt][nt], ah[mt], bh[nt]);
                }
        }
        __syncthreads();
    }

#pragma unroll
    for (int mt = 0; mt < 2; mt++) {
#pragma unroll
        for (int nt = 0; nt < 4; nt++) {
            int col = bn + wn * 32 + nt * 8 + (lane & 3) * 2;
            float bv0 = 0.f, bv1 = 0.f;
            if (bias) { bv0 = bias[col]; bv1 = bias[col + 1]; }
#pragma unroll
            for (int hf = 0; hf < 2; hf++) {
                int row = bm + wm * 32 + mt * 16 + (lane >> 2) + hf * 8;
                float v0 = acc[mt][nt][hf * 2 + 0] + bv0;
                float v1 = acc[mt][nt][hf * 2 + 1] + bv1;
                if (act) { v0 = gelu_f(v0); v1 = gelu_f(v1); }
                if (add) {
                    v0 += add[(size_t)row * N + col];
                    v1 += add[(size_t)row * N + col + 1];
                }
                if (C) *(float2*)&C[(size_t)row * N + col] = make_float2(v0, v1);
                if (OH) {
                    __nv_bfloat16 h0 = __float2bfloat16_rn(v0);
                    __nv_bfloat16 h1 = __float2bfloat16_rn(v1);
                    __nv_bfloat16 l0 = __float2bfloat16_rn(v0 - __bfloat162float(h0));
                    __nv_bfloat16 l1 = __float2bfloat16_rn(v1 - __bfloat162float(h1));
                    *(__nv_bfloat162*)&OH[(size_t)row * N + col] = __nv_bfloat162(h0, h1);
                    *(__nv_bfloat162*)&OL[(size_t)row * N + col] = __nv_bfloat162(l0, l1);
                }
            }
        }
    }
}

__global__ void __launch_bounds__(256, 2)
bgemm_kernel(const __nv_bfloat16* __restrict__ Ah, const __nv_bfloat16* __restrict__ Al,
             const __nv_bfloat16* __restrict__ Wph, const __nv_bfloat16* __restrict__ Wpl,
             const float* __restrict__ bias, const float* __restrict__ add,
             float* __restrict__ C,
             __nv_bfloat16* __restrict__ OH, __nv_bfloat16* __restrict__ OL,
             int N, int K, int act) {
    extern __shared__ char sm[];
    bgemm_body(Ah, Al, Wph, Wpl, bias, add, C, OH, OL, N, K, act, sm,
               blockIdx.y * 64, blockIdx.x * 128);
}

struct QKV3 {
    const __nv_bfloat16 *wh0, *wl0, *wh1, *wl1, *wh2, *wl2;
    const float *b0, *b1, *b2;
    float *c0, *c1, *c2;
};

__global__ void __launch_bounds__(256, 2)
bgemm_qkv_kernel(const __nv_bfloat16* __restrict__ Ah, const __nv_bfloat16* __restrict__ Al,
                 QKV3 p, int N, int K) {
    extern __shared__ char sm[];
    int z = blockIdx.z;
    const __nv_bfloat16* wh = (z == 0) ? p.wh0 : (z == 1) ? p.wh1 : p.wh2;
    const __nv_bfloat16* wl = (z == 0) ? p.wl0 : (z == 1) ? p.wl1 : p.wl2;
    const float* bias = (z == 0) ? p.b0 : (z == 1) ? p.b1 : p.b2;
    float* C = (z == 0) ? p.c0 : (z == 1) ? p.c1 : p.c2;
    bgemm_body(Ah, Al, wh, wl, bias, nullptr, C, nullptr, nullptr, N, K, 0, sm,
               blockIdx.y * 64, blockIdx.x * 128);
}

// ---------------- fp32 SGEMM with optional split-K (skinny LoRA, N=120) ----------------
__global__ void gemm_kernel(const float* __restrict__ A, const float* __restrict__ W,
                            float* __restrict__ C, int N, int K, int nsplit) {
    __shared__ float As[16][64];
    __shared__ float Bs[16][64];
    int bm = blockIdx.y * 64, bn = blockIdx.x * 64;
    int kchunk = K / nsplit;
    int kbeg = blockIdx.z * kchunk;
    int kend = kbeg + kchunk;
    int tid = threadIdx.x;
    int tx = tid & 15, ty = tid >> 4;
    int lr = tid >> 2;
    int lc = (tid & 3) << 2;
    float acc[4][4] = {};
    const float* Aptr = A + (size_t)(bm + lr) * K + lc;
    int wrow = bn + lr;
    const float* Wptr = W + (size_t)wrow * K + lc;
    for (int k0 = kbeg; k0 < kend; k0 += 16) {
        float4 a4 = *(const float4*)(Aptr + k0);
        float4 b4 = (wrow < N) ? *(const float4*)(Wptr + k0) : make_float4(0.f, 0.f, 0.f, 0.f);
        As[lc + 0][lr] = a4.x; As[lc + 1][lr] = a4.y; As[lc + 2][lr] = a4.z; As[lc + 3][lr] = a4.w;
        Bs[lc + 0][lr] = b4.x; Bs[lc + 1][lr] = b4.y; Bs[lc + 2][lr] = b4.z; Bs[lc + 3][lr] = b4.w;
        __syncthreads();
#pragma unroll
        for (int kk = 0; kk < 16; kk++) {
            float4 ra = *(const float4*)&As[kk][ty << 2];
            float4 rb = *(const float4*)&Bs[kk][tx << 2];
            float raa[4] = {ra.x, ra.y, ra.z, ra.w};
            float rbb[4] = {rb.x, rb.y, rb.z, rb.w};
#pragma unroll
            for (int i = 0; i < 4; i++)
#pragma unroll
                for (int j = 0; j < 4; j++)
                    acc[i][j] += raa[i] * rbb[j];
        }
        __syncthreads();
    }
#pragma unroll
    for (int i = 0; i < 4; i++) {
        int m = bm + (ty << 2) + i;
#pragma unroll
        for (int j = 0; j < 4; j++) {
            int n = bn + (tx << 2) + j;
            if (n < N) {
                if (nsplit > 1) atomicAdd(&C[(size_t)m * N + n], acc[i][j]);
                else C[(size_t)m * N + n] = acc[i][j];
            }
        }
    }
}

// ---------------- attention: one block per (batch, head); emits bf16 split ctx ----------------
__global__ void attn_kernel() {
    int bh = blockIdx.x;
    int b = bh / NHD, hh = bh - b * NHD;
    __shared__ float sq[SS][HD], sk[SS][HD], sv[SS][HD], sc[SS][SS + 1];
    int tid = threadIdx.x;
    int base = b * SS;
    for (int i = tid; i < SS * HD; i += 256) {
        int s = i >> 6, d = i & 63;
        int gi = (base + s) * HH + hh * HD + d;
        sq[s][d] = g_q[gi]; sk[s][d] = g_k[gi]; sv[s][d] = g_v[gi];
    }
    __syncthreads();
    for (int i = tid; i < SS * SS; i += 256) {
        int r = i / SS, c = i - r * SS;
        float s = 0.f;
#pragma unroll
        for (int d = 0; d < HD; d++) s += sq[r][d] * sk[c][d];
        sc[r][c] = s * 0.125f;
    }
    __syncthreads();
    if (tid < SS) {
        float mx = -1e30f;
        for (int c = 0; c < SS; c++) mx = fmaxf(mx, sc[tid][c]);
        float sm = 0.f;
        for (int c = 0; c < SS; c++) { float e = expf(sc[tid][c] - mx); sc[tid][c] = e; sm += e; }
        float inv = 1.0f / sm;
        for (int c = 0; c < SS; c++) sc[tid][c] *= inv;
    }
    __syncthreads();
    for (int i = tid; i < SS * HD; i += 256) {
        int s = i >> 6, d = i & 63;
        float o = 0.f;
#pragma unroll
        for (int c = 0; c < SS; c++) o += sc[s][c] * sv[c][d];
        int gi = (base + s) * HH + hh * HD + d;
        __nv_bfloat16 hv = __float2bfloat16_rn(o);
        g_ctxh[gi] = hv;
        g_ctxl[gi] = __float2bfloat16_rn(o - __bfloat162float(hv));
    }
}

// ---------------- per-disease classifiers -> gate[b,d] ----------------
__global__ void cls_kernel(const float* __restrict__ mask,
                           const float* __restrict__ cw1, const float* __restrict__ cb1,
                           const float* __restrict__ clg, const float* __restrict__ clb,
                           const float* __restrict__ cw2, const float* __restrict__ cb2) {
    int b = blockIdx.x, d = blockIdx.y;
    int tid = threadIdx.x, lane = tid & 31, w = tid >> 5;
    __shared__ __align__(16) float pooled[HH];
    __shared__ float h1[384];
    __shared__ float r1[256], r2[256];
    float cnt = 0.f;
    for (int r = 0; r < RR; r++) cnt += (mask[r * DD + d] > 0.f) ? 1.f : 0.f;
    float inv = 1.0f / fmaxf(cnt, 1.0f);
    for (int j = tid; j < HH; j += 256) {
        float s = 0.f;
        for (int r = 0; r < RR; r++)
            if (mask[r * DD + d] > 0.f) s += g_att[(b * SS + 1 + r) * HH + j];
        pooled[j] = s * inv;
    }
    __syncthreads();
    // phase 2: warp-cooperative, coalesced cw1 reads
    for (int k = w; k < 384; k += 8) {
        const float4* row = (const float4*)(cw1 + ((size_t)d * 384 + k) * HH);
        const float4* pp = (const float4*)pooled;
        float s = 0.f;
#pragma unroll
        for (int i = 0; i < 6; i++) {
            int f = lane + 32 * i;
            float4 a = row[f];
            float4 p = pp[f];
            s += a.x * p.x + a.y * p.y + a.z * p.z + a.w * p.w;
        }
#pragma unroll
        for (int o = 16; o; o >>= 1) s += __shfl_xor_sync(0xFFFFFFFFu, s, o);
        if (lane == 0) h1[k] = s + cb1[d * 384 + k];
    }
    __syncthreads();
    float a = 0.f, sq = 0.f;
    for (int k = tid; k < 384; k += 256) { float v = h1[k]; a += v; sq += v * v; }
    r1[tid] = a; r2[tid] = sq;
    __syncthreads();
    for (int o = 128; o > 0; o >>= 1) {
        if (tid < o) { r1[tid] += r1[tid + o]; r2[tid] += r2[tid + o]; }
        __syncthreads();
    }
    float mean = r1[0] * (1.0f / 384.0f);
    float var = r2[0] * (1.0f / 384.0f) - mean * mean;
    float rn = rsqrtf(var + 1e-5f);
    __syncthreads();
    float p = 0.f;
    for (int k = tid; k < 384; k += 256) {
        float v = (h1[k] - mean) * rn * clg[d * 384 + k] + clb[d * 384 + k];
        v = gelu_f(v);
        p += v * cw2[d * 384 + k];
    }
    r1[tid] = p;
    __syncthreads();
    for (int o = 128; o > 0; o >>= 1) {
        if (tid < o) r1[tid] += r1[tid + o];
        __syncthreads();
    }
    if (tid == 0) {
        float pred = r1[0] + cb2[d];
        g_gate[b * DD + d] = (cnt > 0.f && pred > 0.f) ? 1.f : 0.f;
    }
}

// ---------------- M[e] = Bu_e^T @ Ad_e^T  (block per (e, col)) ----------------
__global__ void m_kernel(const float* __restrict__ bu, const float* __restrict__ ad) {
    int e = blockIdx.x, c = blockIdx.y;
    int tid = threadIdx.x;
    float s[LRK] = {};
    const float* bup = bu + (size_t)e * II * LRK;
    const float* adp = ad + ((size_t)e * LRK + c) * II;
    for (int i = tid; i < II; i += 256) {
        float a = adp[i];
        const float* bp = bup + (size_t)i * LRK;
#pragma unroll
        for (int r = 0; r < LRK; r++) s[r] += bp[r] * a;
    }
    __shared__ float red[256];
    for (int r = 0; r < LRK; r++) {
        red[tid] = s[r];
        __syncthreads();
        for (int o = 128; o > 0; o >>= 1) {
            if (tid < o) red[tid] += red[tid + o];
            __syncthreads();
        }
        if (tid == 0) g_M[(e * LRK + r) * LRK + c] = red[0];
        __syncthreads();
    }
}

// ---------------- expert mix: warp per token, t computed inline ----------------
// grid = TN/8, block = 256 (8 warps). Uniform all-expert loop (wgt=0 skip-free)
// so all 8 warps read identical bd lines -> L1 reuse.
__global__ void comb_kernel(const float* __restrict__ bd, const float* __restrict__ mask) {
    int tid = threadIdx.x, lane = tid & 31, w = tid >> 5;
    int token = blockIdx.x * 8 + w;
    int b = token / SS, s = token - b * SS;
    __shared__ __align__(16) float sU[8][ELR];
    __shared__ __align__(16) float sT[8][ELR];

    // load u into warp-private smem
#pragma unroll
    for (int k = 0; k < 4; k++) {
        int er = lane + 32 * k;
        if (er < ELR) sU[w][er] = g_u[(size_t)token * ELR + er];
    }
    __syncwarp();
    // t = vv + SCAL * u @ M
#pragma unroll
    for (int k = 0; k < 4; k++) {
        int er = lane + 32 * k;
        if (er < ELR) {
            int e = er >> 3, r = er & 7;
            float acc = 0.f;
#pragma unroll
            for (int q = 0; q < LRK; q++)
                acc += sU[w][e * LRK + q] * g_M[(e * LRK + q) * LRK + r];
            sT[w][er] = g_vv[(size_t)token * ELR + er] + SCALF * acc;
        }
    }
    __syncwarp();

    // gate weights (computed redundantly per lane; cheap)
    float sw[EE];
    float nact = 0.f;
#pragma unroll
    for (int e = 0; e < DD; e++) {
        float a = (s > 0 && mask[(s - 1) * DD + e] > 0.f) ? g_gate[b * DD + e] : 0.f;
        sw[e] = a; nact += a;
    }
    sw[14] = 1.f; nact += 1.f;
    float wt = 1.0f / fmaxf(nact, 1.0f);

    // load bout (24 floats per lane, as 6 float4 groups)
    float bo[24], acc[24];
    const float4* bop = (const float4*)(g_bout + (size_t)token * HH);
#pragma unroll
    for (int i = 0; i < 6; i++) {
        float4 v = bop[lane + 32 * i];
        bo[4 * i] = v.x; bo[4 * i + 1] = v.y; bo[4 * i + 2] = v.z; bo[4 * i + 3] = v.w;
        acc[4 * i] = 0.f; acc[4 * i + 1] = 0.f; acc[4 * i + 2] = 0.f; acc[4 * i + 3] = 0.f;
    }

    for (int e = 0; e < EE; e++) {
        float wgt = sw[e] * wt;
        float t8[8];
#pragma unroll
        for (int r = 0; r < 8; r++) t8[r] = sT[w][e * LRK + r];
        float o[24];
        float sm = 0.f, sq = 0.f;
#pragma unroll
        for (int i = 0; i < 6; i++) {
            int f = lane + 32 * i;           // float4 group: rows j = 4f..4f+3
            const float4* bdp = (const float4*)(bd + ((size_t)e * HH + 4 * f) * LRK);
#pragma unroll
            for (int c = 0; c < 4; c++) {
                float4 p0 = bdp[2 * c];
                float4 p1 = bdp[2 * c + 1];
                float dv = p0.x * t8[0] + p0.y * t8[1] + p0.z * t8[2] + p0.w * t8[3]
                         + p1.x * t8[4] + p1.y * t8[5] + p1.z * t8[6] + p1.w * t8[7];
                float ov = bo[4 * i + c] + SCALF * dv;
                o[4 * i + c] = ov;
                sm += ov; sq += ov * ov;
            }
        }
#pragma unroll
        for (int off = 16; off; off >>= 1) {
            sm += __shfl_xor_sync(0xFFFFFFFFu, sm, off);
            sq += __shfl_xor_sync(0xFFFFFFFFu, sq, off);
        }
        float mean = sm * (1.0f / 768.0f);
        float var = sq * (1.0f / 768.0f) - mean * mean;
        float rn = rsqrtf(var + 1e-5f);
        float wr = wgt * rn;
#pragma unroll
        for (int i = 0; i < 24; i++) acc[i] += wr * (o[i] - mean);
    }

    const float4* rp = (const float4*)(g_res1 + (size_t)token * HH);
    float4* hp = (float4*)(g_h + (size_t)token * HH);
#pragma unroll
    for (int i = 0; i < 6; i++) {
        float4 r = rp[lane + 32 * i];
        hp[lane + 32 * i] = make_float4(acc[4 * i] + r.x, acc[4 * i + 1] + r.y,
                                        acc[4 * i + 2] + r.z, acc[4 * i + 3] + r.w);
    }
}

// ---------------- host launcher ----------------
extern "C" void kernel_launch(void* const* d_in, const int* in_sizes, int n_in,
                              void* d_out, int out_size) {
    const float* rf   = (const float*)d_in[0];
    const float* cls  = (const float*)d_in[1];
    const float* ln1g = (const float*)d_in[2];
    const float* ln1b = (const float*)d_in[3];
    const float* ln2g = (const float*)d_in[4];
    const float* ln2b = (const float*)d_in[5];
    const float* wq   = (const float*)d_in[6];
    const float* bq   = (const float*)d_in[7];
    const float* wk   = (const float*)d_in[8];
    const float* bk   = (const float*)d_in[9];
    const float* wv   = (const float*)d_in[10];
    const float* bv   = (const float*)d_in[11];
    const float* wo   = (const float*)d_in[12];
    const float* bo   = (const float*)d_in[13];
    const float* wi   = (const float*)d_in[14];
    const float* bi   = (const float*)d_in[15];
    const float* wof  = (const float*)d_in[16];
    const float* bof  = (const float*)d_in[17];
    const float* lnfg = (const float*)d_in[18];
    const float* lnfb = (const float*)d_in[19];
    const float* au   = (const float*)d_in[20];
    const float* bu   = (const float*)d_in[21];
    const float* ad   = (const float*)d_in[22];
    const float* bd   = (const float*)d_in[23];
    const float* cw1  = (const float*)d_in[24];
    const float* cb1  = (const float*)d_in[25];
    const float* clg  = (const float*)d_in[26];
    const float* clb  = (const float*)d_in[27];
    const float* cw2  = (const float*)d_in[28];
    const float* cb2  = (const float*)d_in[29];
    const float* maskp= (const float*)d_in[30];
    float* out = (float*)d_out;

    float *h, *q, *k, *v, *att, *res1, *nres, *hid, *bout, *u, *vv;
    cudaGetSymbolAddress((void**)&h,    g_h);
    cudaGetSymbolAddress((void**)&q,    g_q);
    cudaGetSymbolAddress((void**)&k,    g_k);
    cudaGetSymbolAddress((void**)&v,    g_v);
    cudaGetSymbolAddress((void**)&att,  g_att);
    cudaGetSymbolAddress((void**)&res1, g_res1);
    cudaGetSymbolAddress((void**)&nres, g_nres);
    cudaGetSymbolAddress((void**)&hid,  g_hid);
    cudaGetSymbolAddress((void**)&bout, g_bout);
    cudaGetSymbolAddress((void**)&u,    g_u);
    cudaGetSymbolAddress((void**)&vv,   g_vv);

    __nv_bfloat16 *nxh, *nxl, *nresh, *nresl, *ctxh, *ctxl, *hidh, *hidl;
    __nv_bfloat16 *wqh, *wql, *wkh, *wkl, *wvh, *wvl, *woh, *wol, *wih, *wil, *wofh, *wofl;
    cudaGetSymbolAddress((void**)&nxh,   g_nxh);
    cudaGetSymbolAddress((void**)&nxl,   g_nxl);
    cudaGetSymbolAddress((void**)&nresh, g_nresh);
    cudaGetSymbolAddress((void**)&nresl, g_nresl);
    cudaGetSymbolAddress((void**)&ctxh,  g_ctxh);
    cudaGetSymbolAddress((void**)&ctxl,  g_ctxl);
    cudaGetSymbolAddress((void**)&hidh,  g_hidh);
    cudaGetSymbolAddress((void**)&hidl,  g_hidl);
    cudaGetSymbolAddress((void**)&wqh,   g_wqh);
    cudaGetSymbolAddress((void**)&wql,   g_wql);
    cudaGetSymbolAddress((void**)&wkh,   g_wkh);
    cudaGetSymbolAddress((void**)&wkl,   g_wkl);
    cudaGetSymbolAddress((void**)&wvh,   g_wvh);
    cudaGetSymbolAddress((void**)&wvl,   g_wvl);
    cudaGetSymbolAddress((void**)&woh,   g_woh);
    cudaGetSymbolAddress((void**)&wol,   g_wol);
    cudaGetSymbolAddress((void**)&wih,   g_wih);
    cudaGetSymbolAddress((void**)&wil,   g_wil);
    cudaGetSymbolAddress((void**)&wofh,  g_wofh);
    cudaGetSymbolAddress((void**)&wofl,  g_wofl);

    cudaFuncSetAttribute(bgemm_kernel, cudaFuncAttributeMaxDynamicSharedMemorySize, SMEMB);
    cudaFuncSetAttribute(bgemm_qkv_kernel, cudaFuncAttributeMaxDynamicSharedMemorySize, SMEMB);

    wsplit_all_kernel<<<16384, 256>>>(wq, wk, wv, wo, wi, wof);

    dim3 b768(HH / 128, TN / 64);        // 6 x 60
    dim3 bqkv(HH / 128, TN / 64, 3);     // 6 x 60 x 3
    dim3 b3072(II / 128, TN / 64);       // 24 x 60
    dim3 gu(2, TN / 64, 2);
    dim3 gv(2, TN / 64, 4);
    int nel = TN * HH;
    int nblk = (nel + 255) / 256;
    int lnblk = TN / 8;                  // 480

    embed_kernel<<<nblk, 256>>>(rf, cls);

    for (int i = 0; i < LL; i++) {
        size_t woff  = (size_t)i * HH * HH;
        size_t wioff = (size_t)i * II * HH;
        int even = ((i & 1) == 0);
        ln_kernel<<<lnblk, 256>>>(h, nullptr, nullptr, nullptr, nxh, nxl,
                                  ln1g + i * HH, ln1b + i * HH, 1e-12f);
        QKV3 p;
        p.wh0 = wqh + woff; p.wl0 = wql + woff;
        p.wh1 = wkh + woff; p.wl1 = wkl + woff;
        p.wh2 = wvh + woff; p.wl2 = wvl + woff;
        p.b0 = bq + i * HH; p.b1 = bk + i * HH; p.b2 = bv + i * HH;
        p.c0 = q; p.c1 = k; p.c2 = v;
        bgemm_qkv_kernel<<<bqkv, 256, SMEMB>>>(nxh, nxl, p, HH, HH);
        attn_kernel<<<BQ * NHD, 256>>>();
        bgemm_kernel<<<b768, 256, SMEMB>>>(ctxh, ctxl, woh + woff, wol + woff, bo + i * HH,
                                           nullptr, att, nullptr, nullptr, HH, HH, 0);
        ln_kernel<<<lnblk, 256>>>(att, h, res1, even ? nres : nullptr, nresh, nresl,
                                  ln2g + i * HH, ln2b + i * HH, 1e-12f);
        bgemm_kernel<<<b3072, 256, SMEMB>>>(nresh, nresl, wih + wioff, wil + wioff, bi + i * II,
                                            nullptr, even ? hid : nullptr, hidh, hidl, II, HH, 1);
        if (!even) {
            bgemm_kernel<<<b768, 256, SMEMB>>>(hidh, hidl, wofh + wioff, wofl + wioff, bof + i * HH,
                                               res1, h, nullptr, nullptr, HH, II, 0);
        } else {
            int ei = i / 2;
            bgemm_kernel<<<b768, 256, SMEMB>>>(hidh, hidl, wofh + wioff, wofl + wioff, bof + i * HH,
                                               nullptr, bout, nullptr, nullptr, HH, II, 0);
            dim3 gc(BQ, DD);
            cls_kernel<<<gc, 256>>>(maskp,
                                    cw1 + (size_t)ei * DD * 384 * HH,
                                    cb1 + (size_t)ei * DD * 384,
                                    clg + (size_t)ei * DD * 384,
                                    clb + (size_t)ei * DD * 384,
                                    cw2 + (size_t)ei * DD * 384,
                                    cb2 + (size_t)ei * DD);
            dim3 gm(EE, LRK);
            m_kernel<<<gm, 256>>>(bu + (size_t)ei * EE * II * LRK,
                                  ad + (size_t)ei * EE * LRK * II);
            cudaMemsetAsync(u, 0, (size_t)TN * ELR * sizeof(float));
            cudaMemsetAsync(vv, 0, (size_t)TN * ELR * sizeof(float));
            gemm_kernel<<<gu, 256>>>(nres, au + (size_t)ei * EE * LRK * HH, u, ELR, HH, 2);
            gemm_kernel<<<gv, 256>>>(hid, ad + (size_t)ei * EE * LRK * II, vv, ELR, II, 4);
            comb_kernel<<<lnblk, 256>>>(bd + (size_t)ei * EE * HH * LRK, maskp);
        }
    }
    ln_kernel<<<lnblk, 256>>>(h, nullptr, nullptr, out, nullptr, nullptr, lnfg, lnfb, 1e-12f);
}

// round 12
// speedup vs baseline: 2.9629x; 1.0056x over previous
#include <cuda_runtime.h>
#include <cuda_bf16.h>
#include <math.h>
#include <stdint.h>

#define BQ 128
#define SS 30
#define HH 768
#define II 3072
#define LL 12
#define NHD 12
#define HD 64
#define EE 15
#define DD 14
#define RR 29
#define LRK 8
#define TN (BQ*SS)        // 3840 tokens
#define ELR (EE*LRK)      // 120
#define SCALF 2.0f

// ---------------- scratch (device globals; no allocation) ----------------
__device__ float g_h[TN*HH];
__device__ float g_q[TN*HH];
__device__ float g_k[TN*HH];
__device__ float g_v[TN*HH];
__device__ float g_att[TN*HH];
__device__ float g_res1[TN*HH];
__device__ float g_nres[TN*HH];
__device__ float g_hid[TN*II];
__device__ float g_bout[TN*HH];
__device__ float g_uv[2*TN*ELR];       // u | vv
__device__ float g_M[EE*LRK*LRK];
__device__ float g_gate[BQ*DD];

// bf16 hi/lo activation buffers
__device__ __nv_bfloat16 g_nxh[TN*HH],   g_nxl[TN*HH];
__device__ __nv_bfloat16 g_nresh[TN*HH], g_nresl[TN*HH];
__device__ __nv_bfloat16 g_ctxh[TN*HH],  g_ctxl[TN*HH];
__device__ __nv_bfloat16 g_hidh[TN*II],  g_hidl[TN*II];

// bf16 hi/lo weight buffers (split once per launch)
#define WSZ (LL*HH*HH)
#define WISZ (LL*II*HH)
__device__ __nv_bfloat16 g_wqh[WSZ],  g_wql[WSZ];
__device__ __nv_bfloat16 g_wkh[WSZ],  g_wkl[WSZ];
__device__ __nv_bfloat16 g_wvh[WSZ],  g_wvl[WSZ];
__device__ __nv_bfloat16 g_woh[WSZ],  g_wol[WSZ];
__device__ __nv_bfloat16 g_wih[WISZ], g_wil[WISZ];
__device__ __nv_bfloat16 g_wofh[WISZ], g_wofl[WISZ];

__device__ __forceinline__ float gelu_f(float x) {
    return 0.5f * x * (1.0f + erff(x * 0.70710678118654752f));
}

__device__ __forceinline__ uint32_t smaddr(const void* p) {
    uint32_t a;
    asm("{ .reg .u64 t; cvta.to.shared.u64 t, %1; cvt.u32.u64 %0, t; }" : "=r"(a) : "l"(p));
    return a;
}

#define LDSM4(r, a)                                                        \
    asm volatile("ldmatrix.sync.aligned.m8n8.x4.shared.b16 {%0,%1,%2,%3}, [%4];" \
        : "=r"((r)[0]), "=r"((r)[1]), "=r"((r)[2]), "=r"((r)[3]) : "r"(a))

#define MMABF(d, a, b)                                                     \
    asm volatile("mma.sync.aligned.m16n8k16.row.col.f32.bf16.bf16.f32 "    \
        "{%0,%1,%2,%3}, {%4,%5,%6,%7}, {%8,%9}, {%0,%1,%2,%3};"            \
        : "+f"((d)[0]), "+f"((d)[1]), "+f"((d)[2]), "+f"((d)[3])           \
        : "r"((a)[0]), "r"((a)[1]), "r"((a)[2]), "r"((a)[3]),              \
          "r"((b)[0]), "r"((b)[1]))

// ---------------- weight split (all 6 tensors, one launch) ----------------
#define WTOT (4*WSZ + 2*WISZ)
__global__ void wsplit_all_kernel(const float* __restrict__ wq, const float* __restrict__ wk,
                                  const float* __restrict__ wv, const float* __restrict__ wo,
                                  const float* __restrict__ wi, const float* __restrict__ wof) {
    int stride = gridDim.x * 256;
    for (long long i = blockIdx.x * 256 + threadIdx.x; i < WTOT; i += stride) {
        const float* s; __nv_bfloat16 *dh, *dl; long long j;
        if (i < (long long)WSZ)            { s = wq;  dh = g_wqh;  dl = g_wql;  j = i; }
        else if (i < 2LL*WSZ)              { s = wk;  dh = g_wkh;  dl = g_wkl;  j = i - WSZ; }
        else if (i < 3LL*WSZ)              { s = wv;  dh = g_wvh;  dl = g_wvl;  j = i - 2LL*WSZ; }
        else if (i < 4LL*WSZ)              { s = wo;  dh = g_woh;  dl = g_wol;  j = i - 3LL*WSZ; }
        else if (i < 4LL*WSZ + WISZ)       { s = wi;  dh = g_wih;  dl = g_wil;  j = i - 4LL*WSZ; }
        else                               { s = wof; dh = g_wofh; dl = g_wofl; j = i - 4LL*WSZ - WISZ; }
        float x = s[j];
        __nv_bfloat16 hv = __float2bfloat16_rn(x);
        dh[j] = hv;
        dl[j] = __float2bfloat16_rn(x - __bfloat162float(hv));
    }
}

// ---------------- embed ----------------
__global__ void embed_kernel(const float* __restrict__ rf, const float* __restrict__ cls) {
    int idx = blockIdx.x * 256 + threadIdx.x;
    if (idx >= TN * HH) return;
    int t = idx / HH, j = idx - t * HH;
    int s = t % SS, b = t / SS;
    g_h[idx] = (s == 0) ? cls[j] : rf[(b * RR + (s - 1)) * HH + j];
}

// ---------------- LayerNorm: warp per token, shuffle reductions ----------------
__global__ void ln_kernel(const float* __restrict__ a, const float* __restrict__ b,
                          float* __restrict__ res_out, float* __restrict__ norm_out,
                          __nv_bfloat16* __restrict__ oh, __nv_bfloat16* __restrict__ ol,
                          const float* __restrict__ g, const float* __restrict__ bb,
                          float eps) {
    int tid = threadIdx.x, lane = tid & 31, w = tid >> 5;
    int t = blockIdx.x * 8 + w;
    const float4* xa = (const float4*)(a + (size_t)t * HH);
    const float4* xb = b ? (const float4*)(b + (size_t)t * HH) : nullptr;
    float4 xv[6];
    float s = 0.f, sq = 0.f;
#pragma unroll
    for (int i = 0; i < 6; i++) {
        int f = lane + 32 * i;
        float4 v = xa[f];
        if (xb) { float4 u = xb[f]; v.x += u.x; v.y += u.y; v.z += u.z; v.w += u.w; }
        xv[i] = v;
        s += v.x + v.y + v.z + v.w;
        sq += v.x * v.x + v.y * v.y + v.z * v.z + v.w * v.w;
        if (res_out) ((float4*)(res_out + (size_t)t * HH))[f] = v;
    }
#pragma unroll
    for (int o = 16; o; o >>= 1) {
        s += __shfl_xor_sync(0xFFFFFFFFu, s, o);
        sq += __shfl_xor_sync(0xFFFFFFFFu, sq, o);
    }
    float mean = s * (1.0f / 768.0f);
    float var = sq * (1.0f / 768.0f) - mean * mean;
    float r = rsqrtf(var + eps);
#pragma unroll
    for (int i = 0; i < 6; i++) {
        int f = lane + 32 * i;
        float4 gv = ((const float4*)g)[f];
        float4 bv = ((const float4*)bb)[f];
        float y0 = (xv[i].x - mean) * r * gv.x + bv.x;
        float y1 = (xv[i].y - mean) * r * gv.y + bv.y;
        float y2 = (xv[i].z - mean) * r * gv.z + bv.z;
        float y3 = (xv[i].w - mean) * r * gv.w + bv.w;
        if (norm_out)
            ((float4*)(norm_out + (size_t)t * HH))[f] = make_float4(y0, y1, y2, y3);
        if (oh) {
            __nv_bfloat16 h0 = __float2bfloat16_rn(y0), h1 = __float2bfloat16_rn(y1);
            __nv_bfloat16 h2 = __float2bfloat16_rn(y2), h3 = __float2bfloat16_rn(y3);
            __nv_bfloat162* ohp = (__nv_bfloat162*)(oh + (size_t)t * HH);
            __nv_bfloat162* olp = (__nv_bfloat162*)(ol + (size_t)t * HH);
            ohp[2 * f] = __nv_bfloat162(h0, h1);
            ohp[2 * f + 1] = __nv_bfloat162(h2, h3);
            olp[2 * f] = __nv_bfloat162(__float2bfloat16_rn(y0 - __bfloat162float(h0)),
                                        __float2bfloat16_rn(y1 - __bfloat162float(h1)));
            olp[2 * f + 1] = __nv_bfloat162(__float2bfloat16_rn(y2 - __bfloat162float(h2)),
                                            __float2bfloat16_rn(y3 - __bfloat162float(h3)));
        }
    }
}

// ---------------- bf16 2-term split GEMM (mma.sync m16n8k16) ----------------
#define BKB 64
#define PITCH 144
#define SMA (64*PITCH)
#define SMW (128*PITCH)
#define STGSZ (2*SMA+2*SMW)
#define SMEMB (2*STGSZ)
__device__ __forceinline__ void bgemm_body(
    const __nv_bfloat16* __restrict__ Ah, const __nv_bfloat16* __restrict__ Al,
    const __nv_bfloat16* __restrict__ Wph, const __nv_bfloat16* __restrict__ Wpl,
    const float* __restrict__ bias, const float* __restrict__ add,
    float* __restrict__ C,
    __nv_bfloat16* __restrict__ OH, __nv_bfloat16* __restrict__ OL,
    int N, int K, int act, char* sm, int bm, int bn) {
    uint32_t sbase = smaddr(sm);
    int tid = threadIdx.x, lane = tid & 31, warp = tid >> 5;
    int wm = warp >> 2, wn = warp & 3;

    const __nv_bfloat16* src[12];
    uint32_t dst0[12];
#pragma unroll
    for (int i = 0; i < 12; i++) {
        int c = tid + i * 256;
        int buf, idx;
        if (c < 512) { buf = 0; idx = c; }
        else if (c < 1024) { buf = 1; idx = c - 512; }
        else if (c < 2048) { buf = 2; idx = c - 1024; }
        else { buf = 3; idx = c - 2048; }
        int row = idx >> 3;
        int seg = idx & 7;
        uint32_t soff = (buf == 0) ? 0u : (buf == 1) ? (uint32_t)SMA
                       : (buf == 2) ? (uint32_t)(2 * SMA) : (uint32_t)(2 * SMA + SMW);
        const __nv_bfloat16* g = (buf == 0) ? Ah : (buf == 1) ? Al : (buf == 2) ? Wph : Wpl;
        int grow = (buf < 2) ? (bm + row) : (bn + row);
        src[i] = g + (size_t)grow * K + seg * 8;
        dst0[i] = sbase + soff + (uint32_t)(row * PITCH + seg * 16);
    }
    int NCH = K / BKB;
#pragma unroll
    for (int i = 0; i < 12; i++)
        asm volatile("cp.async.cg.shared.global [%0], [%1], 16;" :: "r"(dst0[i]), "l"(src[i]));
    asm volatile("cp.async.commit_group;" ::: "memory");

    float acc[2][4][4];
#pragma unroll
    for (int mt = 0; mt < 2; mt++)
#pragma unroll
        for (int nt = 0; nt < 4; nt++)
#pragma unroll
            for (int r = 0; r < 4; r++) acc[mt][nt][r] = 0.f;

    for (int kc = 0; kc < NCH; kc++) {
        int s = kc & 1;
        if (kc + 1 < NCH) {
            uint32_t so = (uint32_t)(((kc + 1) & 1) * STGSZ);
#pragma unroll
            for (int i = 0; i < 12; i++)
                asm volatile("cp.async.cg.shared.global [%0], [%1], 16;"
                    :: "r"(dst0[i] + so), "l"(src[i] + (size_t)(kc + 1) * BKB));
            asm volatile("cp.async.commit_group;" ::: "memory");
            asm volatile("cp.async.wait_group 1;" ::: "memory");
        } else {
            asm volatile("cp.async.wait_group 0;" ::: "memory");
        }
        __syncthreads();
        uint32_t sb = sbase + (uint32_t)(s * STGSZ);
#pragma unroll
        for (int ks = 0; ks < 4; ks++) {
            uint32_t ah[2][4], alf[2][4], bh[4][2], bl[4][2];
#pragma unroll
            for (int mt = 0; mt < 2; mt++) {
                uint32_t ra = sb + (uint32_t)((wm * 32 + mt * 16 + (lane & 15)) * PITCH
                                              + ks * 32 + ((lane >> 4) << 4));
                LDSM4(ah[mt], ra);
                LDSM4(alf[mt], ra + SMA);
            }
#pragma unroll
            for (int np = 0; np < 2; np++) {
                uint32_t rb = sb + (uint32_t)(2 * SMA
                              + (wn * 32 + np * 16 + ((lane >> 4) << 3) + (lane & 7)) * PITCH
                              + ks * 32 + (((lane >> 3) & 1) << 4));
                uint32_t t0[4];
                LDSM4(t0, rb);
                bh[np * 2][0] = t0[0]; bh[np * 2][1] = t0[1];
                bh[np * 2 + 1][0] = t0[2]; bh[np * 2 + 1][1] = t0[3];
                LDSM4(t0, rb + SMW);
                bl[np * 2][0] = t0[0]; bl[np * 2][1] = t0[1];
                bl[np * 2 + 1][0] = t0[2]; bl[np * 2 + 1][1] = t0[3];
            }
            // product-major order: consecutive MMAs hit distinct accumulators
#pragma unroll
            for (int mt = 0; mt < 2; mt++)
#pragma unroll
                for (int nt = 0; nt < 4; nt++)
                    MMABF(acc[mt][nt], alf[mt], bh[nt]);
#pragma unroll
            for (int mt = 0; mt < 2; mt++)
#pragma unroll
                for (int nt = 0; nt < 4; nt++)
                    MMABF(acc[mt][nt], ah[mt], bl[nt]);
#pragma unroll
            for (int mt = 0; mt < 2; mt++)
#pragma unroll
                for (int nt = 0; nt < 4; nt++)
                    MMABF(acc[mt][nt], ah[mt], bh[nt]);
        }
        __syncthreads();
    }

#pragma unroll
    for (int mt = 0; mt < 2; mt++) {
#pragma unroll
        for (int nt = 0; nt < 4; nt++) {
            int col = bn + wn * 32 + nt * 8 + (lane & 3) * 2;
            float bv0 = 0.f, bv1 = 0.f;
            if (bias) { bv0 = bias[col]; bv1 = bias[col + 1]; }
#pragma unroll
            for (int hf = 0; hf < 2; hf++) {
                int row = bm + wm * 32 + mt * 16 + (lane >> 2) + hf * 8;
                float v0 = acc[mt][nt][hf * 2 + 0] + bv0;
                float v1 = acc[mt][nt][hf * 2 + 1] + bv1;
                if (act) { v0 = gelu_f(v0); v1 = gelu_f(v1); }
                if (add) {
                    v0 += add[(size_t)row * N + col];
                    v1 += add[(size_t)row * N + col + 1];
                }
                if (C) *(float2*)&C[(size_t)row * N + col] = make_float2(v0, v1);
                if (OH) {
                    __nv_bfloat16 h0 = __float2bfloat16_rn(v0);
                    __nv_bfloat16 h1 = __float2bfloat16_rn(v1);
                    __nv_bfloat16 l0 = __float2bfloat16_rn(v0 - __bfloat162float(h0));
                    __nv_bfloat16 l1 = __float2bfloat16_rn(v1 - __bfloat162float(h1));
                    *(__nv_bfloat162*)&OH[(size_t)row * N + col] = __nv_bfloat162(h0, h1);
                    *(__nv_bfloat162*)&OL[(size_t)row * N + col] = __nv_bfloat162(l0, l1);
                }
            }
        }
    }
}

__global__ void __launch_bounds__(256, 2)
bgemm_kernel(const __nv_bfloat16* __restrict__ Ah, const __nv_bfloat16* __restrict__ Al,
             const __nv_bfloat16* __restrict__ Wph, const __nv_bfloat16* __restrict__ Wpl,
             const float* __restrict__ bias, const float* __restrict__ add,
             float* __restrict__ C,
             __nv_bfloat16* __restrict__ OH, __nv_bfloat16* __restrict__ OL,
             int N, int K, int act) {
    extern __shared__ char sm[];
    bgemm_body(Ah, Al, Wph, Wpl, bias, add, C, OH, OL, N, K, act, sm,
               blockIdx.y * 64, blockIdx.x * 128);
}

struct QKV3 {
    const __nv_bfloat16 *wh0, *wl0, *wh1, *wl1, *wh2, *wl2;
    const float *b0, *b1, *b2;
    float *c0, *c1, *c2;
};

__global__ void __launch_bounds__(256, 2)
bgemm_qkv_kernel(const __nv_bfloat16* __restrict__ Ah, const __nv_bfloat16* __restrict__ Al,
                 QKV3 p, int N, int K) {
    extern __shared__ char sm[];
    int z = blockIdx.z;
    const __nv_bfloat16* wh = (z == 0) ? p.wh0 : (z == 1) ? p.wh1 : p.wh2;
    const __nv_bfloat16* wl = (z == 0) ? p.wl0 : (z == 1) ? p.wl1 : p.wl2;
    const float* bias = (z == 0) ? p.b0 : (z == 1) ? p.b1 : p.b2;
    float* C = (z == 0) ? p.c0 : (z == 1) ? p.c1 : p.c2;
    bgemm_body(Ah, Al, wh, wl, bias, nullptr, C, nullptr, nullptr, N, K, 0, sm,
               blockIdx.y * 64, blockIdx.x * 128);
}

// ---------------- fp32 SGEMM with optional split-K (skinny LoRA, N=120) ----------------
__global__ void gemm_kernel(const float* __restrict__ A, const float* __restrict__ W,
                            float* __restrict__ C, int N, int K, int nsplit) {
    __shared__ float As[16][64];
    __shared__ float Bs[16][64];
    int bm = blockIdx.y * 64, bn = blockIdx.x * 64;
    int kchunk = K / nsplit;
    int kbeg = blockIdx.z * kchunk;
    int kend = kbeg + kchunk;
    int tid = threadIdx.x;
    int tx = tid & 15, ty = tid >> 4;
    int lr = tid >> 2;
    int lc = (tid & 3) << 2;
    float acc[4][4] = {};
    const float* Aptr = A + (size_t)(bm + lr) * K + lc;
    int wrow = bn + lr;
    const float* Wptr = W + (size_t)wrow * K + lc;
    for (int k0 = kbeg; k0 < kend; k0 += 16) {
        float4 a4 = *(const float4*)(Aptr + k0);
        float4 b4 = (wrow < N) ? *(const float4*)(Wptr + k0) : make_float4(0.f, 0.f, 0.f, 0.f);
        As[lc + 0][lr] = a4.x; As[lc + 1][lr] = a4.y; As[lc + 2][lr] = a4.z; As[lc + 3][lr] = a4.w;
        Bs[lc + 0][lr] = b4.x; Bs[lc + 1][lr] = b4.y; Bs[lc + 2][lr] = b4.z; Bs[lc + 3][lr] = b4.w;
        __syncthreads();
#pragma unroll
        for (int kk = 0; kk < 16; kk++) {
            float4 ra = *(const float4*)&As[kk][ty << 2];
            float4 rb = *(const float4*)&Bs[kk][tx << 2];
            float raa[4] = {ra.x, ra.y, ra.z, ra.w};
            float rbb[4] = {rb.x, rb.y, rb.z, rb.w};
#pragma unroll
            for (int i = 0; i < 4; i++)
#pragma unroll
                for (int j = 0; j < 4; j++)
                    acc[i][j] += raa[i] * rbb[j];
        }
        __syncthreads();
    }
#pragma unroll
    for (int i = 0; i < 4; i++) {
        int m = bm + (ty << 2) + i;
#pragma unroll
        for (int j = 0; j < 4; j++) {
            int n = bn + (tx << 2) + j;
            if (n < N) {
                if (nsplit > 1) atomicAdd(&C[(size_t)m * N + n], acc[i][j]);
                else C[(size_t)m * N + n] = acc[i][j];
            }
        }
    }
}

// ---------------- attention ----------------
__global__ void attn_kernel() {
    int bh = blockIdx.x;
    int b = bh / NHD, hh = bh - b * NHD;
    __shared__ float sq[SS][HD], sk[SS][HD], sv[SS][HD], sc[SS][SS + 1];
    int tid = threadIdx.x;
    int base = b * SS;
    for (int i = tid; i < SS * HD; i += 256) {
        int s = i >> 6, d = i & 63;
        int gi = (base + s) * HH + hh * HD + d;
        sq[s][d] = g_q[gi]; sk[s][d] = g_k[gi]; sv[s][d] = g_v[gi];
    }
    __syncthreads();
    for (int i = tid; i < SS * SS; i += 256) {
        int r = i / SS, c = i - r * SS;
        float s = 0.f;
#pragma unroll
        for (int d = 0; d < HD; d++) s += sq[r][d] * sk[c][d];
        sc[r][c] = s * 0.125f;
    }
    __syncthreads();
    if (tid < SS) {
        float mx = -1e30f;
        for (int c = 0; c < SS; c++) mx = fmaxf(mx, sc[tid][c]);
        float sm = 0.f;
        for (int c = 0; c < SS; c++) { float e = expf(sc[tid][c] - mx); sc[tid][c] = e; sm += e; }
        float inv = 1.0f / sm;
        for (int c = 0; c < SS; c++) sc[tid][c] *= inv;
    }
    __syncthreads();
    for (int i = tid; i < SS * HD; i += 256) {
        int s = i >> 6, d = i & 63;
        float o = 0.f;
#pragma unroll
        for (int c = 0; c < SS; c++) o += sc[s][c] * sv[c][d];
        int gi = (base + s) * HH + hh * HD + d;
        __nv_bfloat16 hv = __float2bfloat16_rn(o);
        g_ctxh[gi] = hv;
        g_ctxl[gi] = __float2bfloat16_rn(o - __bfloat162float(hv));
    }
}

// ---------------- per-disease classifiers -> gate[b,d] ----------------
__global__ void cls_kernel(const float* __restrict__ mask,
                           const float* __restrict__ cw1, const float* __restrict__ cb1,
                           const float* __restrict__ clg, const float* __restrict__ clb,
                           const float* __restrict__ cw2, const float* __restrict__ cb2) {
    int b = blockIdx.x, d = blockIdx.y;
    int tid = threadIdx.x, lane = tid & 31, w = tid >> 5;
    __shared__ __align__(16) float pooled[HH];
    __shared__ float h1[384];
    __shared__ float r1[256], r2[256];
    float cnt = 0.f;
    for (int r = 0; r < RR; r++) cnt += (mask[r * DD + d] > 0.f) ? 1.f : 0.f;
    float inv = 1.0f / fmaxf(cnt, 1.0f);
    for (int j = tid; j < HH; j += 256) {
        float s = 0.f;
        for (int r = 0; r < RR; r++)
            if (mask[r * DD + d] > 0.f) s += g_att[(b * SS + 1 + r) * HH + j];
        pooled[j] = s * inv;
    }
    __syncthreads();
    for (int k = w; k < 384; k += 8) {
        const float4* row = (const float4*)(cw1 + ((size_t)d * 384 + k) * HH);
        const float4* pp = (const float4*)pooled;
        float s = 0.f;
#pragma unroll
        for (int i = 0; i < 6; i++) {
            int f = lane + 32 * i;
            float4 a = row[f];
            float4 p = pp[f];
            s += a.x * p.x + a.y * p.y + a.z * p.z + a.w * p.w;
        }
#pragma unroll
        for (int o = 16; o; o >>= 1) s += __shfl_xor_sync(0xFFFFFFFFu, s, o);
        if (lane == 0) h1[k] = s + cb1[d * 384 + k];
    }
    __syncthreads();
    float a = 0.f, sq = 0.f;
    for (int k = tid; k < 384; k += 256) { float v = h1[k]; a += v; sq += v * v; }
    r1[tid] = a; r2[tid] = sq;
    __syncthreads();
    for (int o = 128; o > 0; o >>= 1) {
        if (tid < o) { r1[tid] += r1[tid + o]; r2[tid] += r2[tid + o]; }
        __syncthreads();
    }
    float mean = r1[0] * (1.0f / 384.0f);
    float var = r2[0] * (1.0f / 384.0f) - mean * mean;
    float rn = rsqrtf(var + 1e-5f);
    __syncthreads();
    float p = 0.f;
    for (int k = tid; k < 384; k += 256) {
        float v = (h1[k] - mean) * rn * clg[d * 384 + k] + clb[d * 384 + k];
        v = gelu_f(v);
        p += v * cw2[d * 384 + k];
    }
    r1[tid] = p;
    __syncthreads();
    for (int o = 128; o > 0; o >>= 1) {
        if (tid < o) r1[tid] += r1[tid + o];
        __syncthreads();
    }
    if (tid == 0) {
        float pred = r1[0] + cb2[d];
        g_gate[b * DD + d] = (cnt > 0.f && pred > 0.f) ? 1.f : 0.f;
    }
}

// ---------------- M[e] = Bu_e^T @ Ad_e^T ----------------
__global__ void m_kernel(const float* __restrict__ bu, const float* __restrict__ ad) {
    int e = blockIdx.x, c = blockIdx.y;
    int tid = threadIdx.x;
    float s[LRK] = {};
    const float* bup = bu + (size_t)e * II * LRK;
    const float* adp = ad + ((size_t)e * LRK + c) * II;
    for (int i = tid; i < II; i += 256) {
        float a = adp[i];
        const float* bp = bup + (size_t)i * LRK;
#pragma unroll
        for (int r = 0; r < LRK; r++) s[r] += bp[r] * a;
    }
    __shared__ float red[256];
    for (int r = 0; r < LRK; r++) {
        red[tid] = s[r];
        __syncthreads();
        for (int o = 128; o > 0; o >>= 1) {
            if (tid < o) red[tid] += red[tid + o];
            __syncthreads();
        }
        if (tid == 0) g_M[(e * LRK + r) * LRK + c] = red[0];
        __syncthreads();
    }
}

// ---------------- expert mix: warp per token, fused next-layer LN1 ----------------
__global__ void comb_kernel(const float* __restrict__ bd, const float* __restrict__ mask,
                            const float* __restrict__ lng, const float* __restrict__ lnb) {
    int tid = threadIdx.x, lane = tid & 31, w = tid >> 5;
    int token = blockIdx.x * 8 + w;
    int b = token / SS, s = token - b * SS;
    __shared__ __align__(16) float sU[8][ELR];
    __shared__ __align__(16) float sT[8][ELR];

#pragma unroll
    for (int k = 0; k < 4; k++) {
        int er = lane + 32 * k;
        if (er < ELR) sU[w][er] = g_uv[(size_t)token * ELR + er];
    }
    __syncwarp();
#pragma unroll
    for (int k = 0; k < 4; k++) {
        int er = lane + 32 * k;
        if (er < ELR) {
            int e = er >> 3, r = er & 7;
            float acc = 0.f;
#pragma unroll
            for (int q = 0; q < LRK; q++)
                acc += sU[w][e * LRK + q] * g_M[(e * LRK + q) * LRK + r];
            sT[w][er] = g_uv[(size_t)(TN + token) * ELR + er] + SCALF * acc;
        }
    }
    __syncwarp();

    float sw[EE];
    float nact = 0.f;
#pragma unroll
    for (int e = 0; e < DD; e++) {
        float a = (s > 0 && mask[(s - 1) * DD + e] > 0.f) ? g_gate[b * DD + e] : 0.f;
        sw[e] = a; nact += a;
    }
    sw[14] = 1.f; nact += 1.f;
    float wt = 1.0f / fmaxf(nact, 1.0f);

    float bo[24], acc[24];
    const float4* bop = (const float4*)(g_bout + (size_t)token * HH);
#pragma unroll
    for (int i = 0; i < 6; i++) {
        float4 v = bop[lane + 32 * i];
        bo[4 * i] = v.x; bo[4 * i + 1] = v.y; bo[4 * i + 2] = v.z; bo[4 * i + 3] = v.w;
        acc[4 * i] = 0.f; acc[4 * i + 1] = 0.f; acc[4 * i + 2] = 0.f; acc[4 * i + 3] = 0.f;
    }

    for (int e = 0; e < EE; e++) {
        float wgt = sw[e] * wt;
        float t8[8];
#pragma unroll
        for (int r = 0; r < 8; r++) t8[r] = sT[w][e * LRK + r];
        float o[24];
        float sm = 0.f, sq = 0.f;
#pragma unroll
        for (int i = 0; i < 6; i++) {
            int f = lane + 32 * i;
            const float4* bdp = (const float4*)(bd + ((size_t)e * HH + 4 * f) * LRK);
#pragma unroll
            for (int c = 0; c < 4; c++) {
                float4 p0 = bdp[2 * c];
                float4 p1 = bdp[2 * c + 1];
                float dv = p0.x * t8[0] + p0.y * t8[1] + p0.z * t8[2] + p0.w * t8[3]
                         + p1.x * t8[4] + p1.y * t8[5] + p1.z * t8[6] + p1.w * t8[7];
                float ov = bo[4 * i + c] + SCALF * dv;
                o[4 * i + c] = ov;
                sm += ov; sq += ov * ov;
            }
        }
#pragma unroll
        for (int off = 16; off; off >>= 1) {
            sm += __shfl_xor_sync(0xFFFFFFFFu, sm, off);
            sq += __shfl_xor_sync(0xFFFFFFFFu, sq, off);
        }
        float mean = sm * (1.0f / 768.0f);
        float var = sq * (1.0f / 768.0f) - mean * mean;
        float rn = rsqrtf(var + 1e-5f);
        float wr = wgt * rn;
#pragma unroll
        for (int i = 0; i < 24; i++) acc[i] += wr * (o[i] - mean);
    }

    // h = acc + res1; fused LN1(next layer) on h -> nxh/nxl
    const float4* rp = (const float4*)(g_res1 + (size_t)token * HH);
    float4* hp = (float4*)(g_h + (size_t)token * HH);
    float hv4[24];
    float s2 = 0.f, sq2 = 0.f;
#pragma unroll
    for (int i = 0; i < 6; i++) {
        float4 r = rp[lane + 32 * i];
        float h0 = acc[4 * i] + r.x, h1 = acc[4 * i + 1] + r.y;
        float h2 = acc[4 * i + 2] + r.z, h3 = acc[4 * i + 3] + r.w;
        hp[lane + 32 * i] = make_float4(h0, h1, h2, h3);
        hv4[4 * i] = h0; hv4[4 * i + 1] = h1; hv4[4 * i + 2] = h2; hv4[4 * i + 3] = h3;
        s2 += h0 + h1 + h2 + h3;
        sq2 += h0 * h0 + h1 * h1 + h2 * h2 + h3 * h3;
    }
#pragma unroll
    for (int o = 16; o; o >>= 1) {
        s2 += __shfl_xor_sync(0xFFFFFFFFu, s2, o);
        sq2 += __shfl_xor_sync(0xFFFFFFFFu, sq2, o);
    }
    float mean = s2 * (1.0f / 768.0f);
    float var = sq2 * (1.0f / 768.0f) - mean * mean;
    float r = rsqrtf(var + 1e-12f);
    __nv_bfloat162* ohp = (__nv_bfloat162*)(g_nxh + (size_t)token * HH);
    __nv_bfloat162* olp = (__nv_bfloat162*)(g_nxl + (size_t)token * HH);
#pragma unroll
    for (int i = 0; i < 6; i++) {
        int f = lane + 32 * i;
        float4 gv = ((const float4*)lng)[f];
        float4 bv = ((const float4*)lnb)[f];
        float y0 = (hv4[4 * i] - mean) * r * gv.x + bv.x;
        float y1 = (hv4[4 * i + 1] - mean) * r * gv.y + bv.y;
        float y2 = (hv4[4 * i + 2] - mean) * r * gv.z + bv.z;
        float y3 = (hv4[4 * i + 3] - mean) * r * gv.w + bv.w;
        __nv_bfloat16 h0 = __float2bfloat16_rn(y0), h1 = __float2bfloat16_rn(y1);
        __nv_bfloat16 h2 = __float2bfloat16_rn(y2), h3 = __float2bfloat16_rn(y3);
        ohp[2 * f] = __nv_bfloat162(h0, h1);
        ohp[2 * f + 1] = __nv_bfloat162(h2, h3);
        olp[2 * f] = __nv_bfloat162(__float2bfloat16_rn(y0 - __bfloat162float(h0)),
                                    __float2bfloat16_rn(y1 - __bfloat162float(h1)));
        olp[2 * f + 1] = __nv_bfloat162(__float2bfloat16_rn(y2 - __bfloat162float(h2)),
                                        __float2bfloat16_rn(y3 - __bfloat162float(h3)));
    }
}

// ---------------- host launcher ----------------
extern "C" void kernel_launch(void* const* d_in, const int* in_sizes, int n_in,
                              void* d_out, int out_size) {
    const float* rf   = (const float*)d_in[0];
    const float* cls  = (const float*)d_in[1];
    const float* ln1g = (const float*)d_in[2];
    const float* ln1b = (const float*)d_in[3];
    const float* ln2g = (const float*)d_in[4];
    const float* ln2b = (const float*)d_in[5];
    const float* wq   = (const float*)d_in[6];
    const float* bq   = (const float*)d_in[7];
    const float* wk   = (const float*)d_in[8];
    const float* bk   = (const float*)d_in[9];
    const float* wv   = (const float*)d_in[10];
    const float* bv   = (const float*)d_in[11];
    const float* wo   = (const float*)d_in[12];
    const float* bo   = (const float*)d_in[13];
    const float* wi   = (const float*)d_in[14];
    const float* bi   = (const float*)d_in[15];
    const float* wof  = (const float*)d_in[16];
    const float* bof  = (const float*)d_in[17];
    const float* lnfg = (const float*)d_in[18];
    const float* lnfb = (const float*)d_in[19];
    const float* au   = (const float*)d_in[20];
    const float* bu   = (const float*)d_in[21];
    const float* ad   = (const float*)d_in[22];
    const float* bd   = (const float*)d_in[23];
    const float* cw1  = (const float*)d_in[24];
    const float* cb1  = (const float*)d_in[25];
    const float* clg  = (const float*)d_in[26];
    const float* clb  = (const float*)d_in[27];
    const float* cw2  = (const float*)d_in[28];
    const float* cb2  = (const float*)d_in[29];
    const float* maskp= (const float*)d_in[30];
    float* out = (float*)d_out;

    float *h, *q, *k, *v, *att, *res1, *nres, *hid, *bout, *uv;
    cudaGetSymbolAddress((void**)&h,    g_h);
    cudaGetSymbolAddress((void**)&q,    g_q);
    cudaGetSymbolAddress((void**)&k,    g_k);
    cudaGetSymbolAddress((void**)&v,    g_v);
    cudaGetSymbolAddress((void**)&att,  g_att);
    cudaGetSymbolAddress((void**)&res1, g_res1);
    cudaGetSymbolAddress((void**)&nres, g_nres);
    cudaGetSymbolAddress((void**)&hid,  g_hid);
    cudaGetSymbolAddress((void**)&bout, g_bout);
    cudaGetSymbolAddress((void**)&uv,   g_uv);

    __nv_bfloat16 *nxh, *nxl, *nresh, *nresl, *ctxh, *ctxl, *hidh, *hidl;
    __nv_bfloat16 *wqh, *wql, *wkh, *wkl, *wvh, *wvl, *woh, *wol, *wih, *wil, *wofh, *wofl;
    cudaGetSymbolAddress((void**)&nxh,   g_nxh);
    cudaGetSymbolAddress((void**)&nxl,   g_nxl);
    cudaGetSymbolAddress((void**)&nresh, g_nresh);
    cudaGetSymbolAddress((void**)&nresl, g_nresl);
    cudaGetSymbolAddress((void**)&ctxh,  g_ctxh);
    cudaGetSymbolAddress((void**)&ctxl,  g_ctxl);
    cudaGetSymbolAddress((void**)&hidh,  g_hidh);
    cudaGetSymbolAddress((void**)&hidl,  g_hidl);
    cudaGetSymbolAddress((void**)&wqh,   g_wqh);
    cudaGetSymbolAddress((void**)&wql,   g_wql);
    cudaGetSymbolAddress((void**)&wkh,   g_wkh);
    cudaGetSymbolAddress((void**)&wkl,   g_wkl);
    cudaGetSymbolAddress((void**)&wvh,   g_wvh);
    cudaGetSymbolAddress((void**)&wvl,   g_wvl);
    cudaGetSymbolAddress((void**)&woh,   g_woh);
    cudaGetSymbolAddress((void**)&wol,   g_wol);
    cudaGetSymbolAddress((void**)&wih,   g_wih);
    cudaGetSymbolAddress((void**)&wil,   g_wil);
    cudaGetSymbolAddress((void**)&wofh,  g_wofh);
    cudaGetSymbolAddress((void**)&wofl,  g_wofl);

    cudaFuncSetAttribute(bgemm_kernel, cudaFuncAttributeMaxDynamicSharedMemorySize, SMEMB);
    cudaFuncSetAttribute(bgemm_qkv_kernel, cudaFuncAttributeMaxDynamicSharedMemorySize, SMEMB);

    wsplit_all_kernel<<<16384, 256>>>(wq, wk, wv, wo, wi, wof);

    dim3 b768(HH / 128, TN / 64);        // 6 x 60
    dim3 bqkv(HH / 128, TN / 64, 3);     // 6 x 60 x 3
    dim3 b3072(II / 128, TN / 64);       // 24 x 60
    dim3 gu(2, TN / 64, 2);
    dim3 gv(2, TN / 64, 4);
    int nel = TN * HH;
    int nblk = (nel + 255) / 256;
    int lnblk = TN / 8;                  // 480

    embed_kernel<<<nblk, 256>>>(rf, cls);

    for (int i = 0; i < LL; i++) {
        size_t woff  = (size_t)i * HH * HH;
        size_t wioff = (size_t)i * II * HH;
        int even = ((i & 1) == 0);
        if (even) {
            // odd layers get nxh/nxl from fused comb; even layers need LN1 here
            ln_kernel<<<lnblk, 256>>>(h, nullptr, nullptr, nullptr, nxh, nxl,
                                      ln1g + i * HH, ln1b + i * HH, 1e-12f);
        }
        QKV3 p;
        p.wh0 = wqh + woff; p.wl0 = wql + woff;
        p.wh1 = wkh + woff; p.wl1 = wkl + woff;
        p.wh2 = wvh + woff; p.wl2 = wvl + woff;
        p.b0 = bq + i * HH; p.b1 = bk + i * HH; p.b2 = bv + i * HH;
        p.c0 = q; p.c1 = k; p.c2 = v;
        bgemm_qkv_kernel<<<bqkv, 256, SMEMB>>>(nxh, nxl, p, HH, HH);
        attn_kernel<<<BQ * NHD, 256>>>();
        bgemm_kernel<<<b768, 256, SMEMB>>>(ctxh, ctxl, woh + woff, wol + woff, bo + i * HH,
                                           nullptr, att, nullptr, nullptr, HH, HH, 0);
        ln_kernel<<<lnblk, 256>>>(att, h, res1, even ? nres : nullptr, nresh, nresl,
                                  ln2g + i * HH, ln2b + i * HH, 1e-12f);
        bgemm_kernel<<<b3072, 256, SMEMB>>>(nresh, nresl, wih + wioff, wil + wioff, bi + i * II,
                                            nullptr, even ? hid : nullptr, hidh, hidl, II, HH, 1);
        if (!even) {
            bgemm_kernel<<<b768, 256, SMEMB>>>(hidh, hidl, wofh + wioff, wofl + wioff, bof + i * HH,
                                               res1, h, nullptr, nullptr, HH, II, 0);
        } else {
            int ei = i / 2;
            bgemm_kernel<<<b768, 256, SMEMB>>>(hidh, hidl, wofh + wioff, wofl + wioff, bof + i * HH,
                                               nullptr, bout, nullptr, nullptr, HH, II, 0);
            dim3 gc(BQ, DD);
            cls_kernel<<<gc, 256>>>(maskp,
                                    cw1 + (size_t)ei * DD * 384 * HH,
                                    cb1 + (size_t)ei * DD * 384,
                                    clg + (size_t)ei * DD * 384,
                                    clb + (size_t)ei * DD * 384,
                                    cw2 + (size_t)ei * DD * 384,
                                    cb2 + (size_t)ei * DD);
            dim3 gm(EE, LRK);
            m_kernel<<<gm, 256>>>(bu + (size_t)ei * EE * II * LRK,
                                  ad + (size_t)ei * EE * LRK * II);
            cudaMemsetAsync(uv, 0, (size_t)2 * TN * ELR * sizeof(float));
            gemm_kernel<<<gu, 256>>>(nres, au + (size_t)ei * EE * LRK * HH, uv, ELR, HH, 2);
            gemm_kernel<<<gv, 256>>>(hid, ad + (size_t)ei * EE * LRK * II, uv + (size_t)TN * ELR, ELR, II, 4);
            // comb writes h AND fused LN1 for layer i+1
            comb_kernel<<<lnblk, 256>>>(bd + (size_t)ei * EE * HH * LRK, maskp,
                                        ln1g + (i + 1) * HH, ln1b + (i + 1) * HH);
        }
    }
    ln_kernel<<<lnblk, 256>>>(h, nullptr, nullptr, out, nullptr, nullptr, lnfg, lnfb, 1e-12f);
}

// round 14
// speedup vs baseline: 3.0359x; 1.0247x over previous
#include <cuda_runtime.h>
#include <cuda_bf16.h>
#include <math.h>
#include <stdint.h>

#define BQ 128
#define SS 30
#define HH 768
#define II 3072
#define LL 12
#define NHD 12
#define HD 64
#define EE 15
#define DD 14
#define RR 29
#define LRK 8
#define NE (LL/2)
#define TN (BQ*SS)        // 3840 tokens
#define ELR (EE*LRK)      // 120
#define SCALF 2.0f

// ---------------- scratch (device globals; no allocation) ----------------
__device__ float g_h[TN*HH];
__device__ float g_q[TN*HH];
__device__ float g_k[TN*HH];
__device__ float g_v[TN*HH];
__device__ float g_att[TN*HH];
__device__ float g_res1[TN*HH];
__device__ float g_nres[TN*HH];
__device__ float g_hid[TN*II];
__device__ float g_bout[TN*HH];
__device__ float g_uv[2*TN*ELR];       // u | vv
__device__ float g_M[NE*EE*LRK*LRK];
__device__ float g_gate[BQ*DD];

// bf16 hi/lo activation buffers
__device__ __nv_bfloat16 g_nxh[TN*HH],   g_nxl[TN*HH];
__device__ __nv_bfloat16 g_nresh[TN*HH], g_nresl[TN*HH];
__device__ __nv_bfloat16 g_ctxh[TN*HH],  g_ctxl[TN*HH];
__device__ __nv_bfloat16 g_hidh[TN*II],  g_hidl[TN*II];

// bf16 hi/lo weight buffers (split once per launch)
#define WSZ (LL*HH*HH)
#define WISZ (LL*II*HH)
__device__ __nv_bfloat16 g_wqh[WSZ],  g_wql[WSZ];
__device__ __nv_bfloat16 g_wkh[WSZ],  g_wkl[WSZ];
__device__ __nv_bfloat16 g_wvh[WSZ],  g_wvl[WSZ];
__device__ __nv_bfloat16 g_woh[WSZ],  g_wol[WSZ];
__device__ __nv_bfloat16 g_wih[WISZ], g_wil[WISZ];
__device__ __nv_bfloat16 g_wofh[WISZ], g_wofl[WISZ];

__device__ __forceinline__ float gelu_f(float x) {
    return 0.5f * x * (1.0f + erff(x * 0.70710678118654752f));
}

__device__ __forceinline__ uint32_t smaddr(const void* p) {
    uint32_t a;
    asm("{ .reg .u64 t; cvta.to.shared.u64 t, %1; cvt.u32.u64 %0, t; }" : "=r"(a) : "l"(p));
    return a;
}

#define LDSM4(r, a)                                                        \
    asm volatile("ldmatrix.sync.aligned.m8n8.x4.shared.b16 {%0,%1,%2,%3}, [%4];" \
        : "=r"((r)[0]), "=r"((r)[1]), "=r"((r)[2]), "=r"((r)[3]) : "r"(a))

#define MMABF(d, a, b)                                                     \
    asm volatile("mma.sync.aligned.m16n8k16.row.col.f32.bf16.bf16.f32 "    \
        "{%0,%1,%2,%3}, {%4,%5,%6,%7}, {%8,%9}, {%0,%1,%2,%3};"            \
        : "+f"((d)[0]), "+f"((d)[1]), "+f"((d)[2]), "+f"((d)[3])           \
        : "r"((a)[0]), "r"((a)[1]), "r"((a)[2]), "r"((a)[3]),              \
          "r"((b)[0]), "r"((b)[1]))

// ---------------- weight split (all 6 tensors, one launch) ----------------
#define WTOT (4*WSZ + 2*WISZ)
__global__ void wsplit_all_kernel(const float* __restrict__ wq, const float* __restrict__ wk,
                                  const float* __restrict__ wv, const float* __restrict__ wo,
                                  const float* __restrict__ wi, const float* __restrict__ wof) {
    int stride = gridDim.x * 256;
    for (long long i = blockIdx.x * 256 + threadIdx.x; i < WTOT; i += stride) {
        const float* s; __nv_bfloat16 *dh, *dl; long long j;
        if (i < (long long)WSZ)            { s = wq;  dh = g_wqh;  dl = g_wql;  j = i; }
        else if (i < 2LL*WSZ)              { s = wk;  dh = g_wkh;  dl = g_wkl;  j = i - WSZ; }
        else if (i < 3LL*WSZ)              { s = wv;  dh = g_wvh;  dl = g_wvl;  j = i - 2LL*WSZ; }
        else if (i < 4LL*WSZ)              { s = wo;  dh = g_woh;  dl = g_wol;  j = i - 3LL*WSZ; }
        else if (i < 4LL*WSZ + WISZ)       { s = wi;  dh = g_wih;  dl = g_wil;  j = i - 4LL*WSZ; }
        else                               { s = wof; dh = g_wofh; dl = g_wofl; j = i - 4LL*WSZ - WISZ; }
        float x = s[j];
        __nv_bfloat16 hv = __float2bfloat16_rn(x);
        dh[j] = hv;
        dl[j] = __float2bfloat16_rn(x - __bfloat162float(hv));
    }
}

// ---------------- embed ----------------
__global__ void embed_kernel(const float* __restrict__ rf, const float* __restrict__ cls) {
    int idx = blockIdx.x * 256 + threadIdx.x;
    if (idx >= TN * HH) return;
    int t = idx / HH, j = idx - t * HH;
    int s = t % SS, b = t / SS;
    g_h[idx] = (s == 0) ? cls[j] : rf[(b * RR + (s - 1)) * HH + j];
}

// ---------------- LayerNorm: warp per token, shuffle reductions ----------------
__global__ void ln_kernel(const float* __restrict__ a, const float* __restrict__ b,
                          float* __restrict__ res_out, float* __restrict__ norm_out,
                          __nv_bfloat16* __restrict__ oh, __nv_bfloat16* __restrict__ ol,
                          const float* __restrict__ g, const float* __restrict__ bb,
                          float eps) {
    int tid = threadIdx.x, lane = tid & 31, w = tid >> 5;
    int t = blockIdx.x * 8 + w;
    const float4* xa = (const float4*)(a + (size_t)t * HH);
    const float4* xb = b ? (const float4*)(b + (size_t)t * HH) : nullptr;
    float4 xv[6];
    float s = 0.f, sq = 0.f;
#pragma unroll
    for (int i = 0; i < 6; i++) {
        int f = lane + 32 * i;
        float4 v = xa[f];
        if (xb) { float4 u = xb[f]; v.x += u.x; v.y += u.y; v.z += u.z; v.w += u.w; }
        xv[i] = v;
        s += v.x + v.y + v.z + v.w;
        sq += v.x * v.x + v.y * v.y + v.z * v.z + v.w * v.w;
        if (res_out) ((float4*)(res_out + (size_t)t * HH))[f] = v;
    }
#pragma unroll
    for (int o = 16; o; o >>= 1) {
        s += __shfl_xor_sync(0xFFFFFFFFu, s, o);
        sq += __shfl_xor_sync(0xFFFFFFFFu, sq, o);
    }
    float mean = s * (1.0f / 768.0f);
    float var = sq * (1.0f / 768.0f) - mean * mean;
    float r = rsqrtf(var + eps);
#pragma unroll
    for (int i = 0; i < 6; i++) {
        int f = lane + 32 * i;
        float4 gv = ((const float4*)g)[f];
        float4 bv = ((const float4*)bb)[f];
        float y0 = (xv[i].x - mean) * r * gv.x + bv.x;
        float y1 = (xv[i].y - mean) * r * gv.y + bv.y;
        float y2 = (xv[i].z - mean) * r * gv.z + bv.z;
        float y3 = (xv[i].w - mean) * r * gv.w + bv.w;
        if (norm_out)
            ((float4*)(norm_out + (size_t)t * HH))[f] = make_float4(y0, y1, y2, y3);
        if (oh) {
            __nv_bfloat16 h0 = __float2bfloat16_rn(y0), h1 = __float2bfloat16_rn(y1);
            __nv_bfloat16 h2 = __float2bfloat16_rn(y2), h3 = __float2bfloat16_rn(y3);
            __nv_bfloat162* ohp = (__nv_bfloat162*)(oh + (size_t)t * HH);
            __nv_bfloat162* olp = (__nv_bfloat162*)(ol + (size_t)t * HH);
            ohp[2 * f] = __nv_bfloat162(h0, h1);
            ohp[2 * f + 1] = __nv_bfloat162(h2, h3);
            olp[2 * f] = __nv_bfloat162(__float2bfloat16_rn(y0 - __bfloat162float(h0)),
                                        __float2bfloat16_rn(y1 - __bfloat162float(h1)));
            olp[2 * f + 1] = __nv_bfloat162(__float2bfloat16_rn(y2 - __bfloat162float(h2)),
                                            __float2bfloat16_rn(y3 - __bfloat162float(h3)));
        }
    }
}

// ---------------- bf16 2-term split GEMM (mma.sync m16n8k16) ----------------
#define BKB 64
#define PITCH 144
#define SMA (64*PITCH)
#define SMW (128*PITCH)
#define STGSZ (2*SMA+2*SMW)
#define SMEMB (2*STGSZ)
__device__ __forceinline__ void bgemm_body(
    const __nv_bfloat16* __restrict__ Ah, const __nv_bfloat16* __restrict__ Al,
    const __nv_bfloat16* __restrict__ Wph, const __nv_bfloat16* __restrict__ Wpl,
    const float* __restrict__ bias, const float* __restrict__ add,
    float* __restrict__ C,
    __nv_bfloat16* __restrict__ OH, __nv_bfloat16* __restrict__ OL,
    int N, int K, int act, char* sm, int bm, int bn,
    int kc0, int kc1, int atomic) {
    uint32_t sbase = smaddr(sm);
    int tid = threadIdx.x, lane = tid & 31, warp = tid >> 5;
    int wm = warp >> 2, wn = warp & 3;

    const __nv_bfloat16* src[12];
    uint32_t dst0[12];
#pragma unroll
    for (int i = 0; i < 12; i++) {
        int c = tid + i * 256;
        int buf, idx;
        if (c < 512) { buf = 0; idx = c; }
        else if (c < 1024) { buf = 1; idx = c - 512; }
        else if (c < 2048) { buf = 2; idx = c - 1024; }
        else { buf = 3; idx = c - 2048; }
        int row = idx >> 3;
        int seg = idx & 7;
        uint32_t soff = (buf == 0) ? 0u : (buf == 1) ? (uint32_t)SMA
                       : (buf == 2) ? (uint32_t)(2 * SMA) : (uint32_t)(2 * SMA + SMW);
        const __nv_bfloat16* g = (buf == 0) ? Ah : (buf == 1) ? Al : (buf == 2) ? Wph : Wpl;
        int grow = (buf < 2) ? (bm + row) : (bn + row);
        src[i] = g + (size_t)grow * K + seg * 8 + (size_t)kc0 * BKB;
        dst0[i] = sbase + soff + (uint32_t)(row * PITCH + seg * 16);
    }
    int nch = kc1 - kc0;
#pragma unroll
    for (int i = 0; i < 12; i++)
        asm volatile("cp.async.cg.shared.global [%0], [%1], 16;" :: "r"(dst0[i]), "l"(src[i]));
    asm volatile("cp.async.commit_group;" ::: "memory");

    float acc[2][4][4];
#pragma unroll
    for (int mt = 0; mt < 2; mt++)
#pragma unroll
        for (int nt = 0; nt < 4; nt++)
#pragma unroll
            for (int r = 0; r < 4; r++) acc[mt][nt][r] = 0.f;

    for (int j = 0; j < nch; j++) {
        int s = j & 1;
        if (j + 1 < nch) {
            uint32_t so = (uint32_t)(((j + 1) & 1) * STGSZ);
#pragma unroll
            for (int i = 0; i < 12; i++)
                asm volatile("cp.async.cg.shared.global [%0], [%1], 16;"
                    :: "r"(dst0[i] + so), "l"(src[i] + (size_t)(j + 1) * BKB));
            asm volatile("cp.async.commit_group;" ::: "memory");
            asm volatile("cp.async.wait_group 1;" ::: "memory");
        } else {
            asm volatile("cp.async.wait_group 0;" ::: "memory");
        }
        __syncthreads();
        uint32_t sb = sbase + (uint32_t)(s * STGSZ);
#pragma unroll
        for (int ks = 0; ks < 4; ks++) {
            uint32_t ah[2][4], alf[2][4], bh[4][2], bl[4][2];
#pragma unroll
            for (int mt = 0; mt < 2; mt++) {
                uint32_t ra = sb + (uint32_t)((wm * 32 + mt * 16 + (lane & 15)) * PITCH
                                              + ks * 32 + ((lane >> 4) << 4));
                LDSM4(ah[mt], ra);
                LDSM4(alf[mt], ra + SMA);
            }
#pragma unroll
            for (int np = 0; np < 2; np++) {
                uint32_t rb = sb + (uint32_t)(2 * SMA
                              + (wn * 32 + np * 16 + ((lane >> 4) << 3) + (lane & 7)) * PITCH
                              + ks * 32 + (((lane >> 3) & 1) << 4));
                uint32_t t0[4];
                LDSM4(t0, rb);
                bh[np * 2][0] = t0[0]; bh[np * 2][1] = t0[1];
                bh[np * 2 + 1][0] = t0[2]; bh[np * 2 + 1][1] = t0[3];
                LDSM4(t0, rb + SMW);
                bl[np * 2][0] = t0[0]; bl[np * 2][1] = t0[1];
                bl[np * 2 + 1][0] = t0[2]; bl[np * 2 + 1][1] = t0[3];
            }
#pragma unroll
            for (int mt = 0; mt < 2; mt++)
#pragma unroll
                for (int nt = 0; nt < 4; nt++) {
                    MMABF(acc[mt][nt], alf[mt], bh[nt]);
                    MMABF(acc[mt][nt], ah[mt], bl[nt]);
                    MMABF(acc[mt][nt], ah[mt], bh[nt]);
                }
        }
        __syncthreads();
    }

#pragma unroll
    for (int mt = 0; mt < 2; mt++) {
#pragma unroll
        for (int nt = 0; nt < 4; nt++) {
            int col = bn + wn * 32 + nt * 8 + (lane & 3) * 2;
            float bv0 = 0.f, bv1 = 0.f;
            if (bias) { bv0 = bias[col]; bv1 = bias[col + 1]; }
#pragma unroll
            for (int hf = 0; hf < 2; hf++) {
                int row = bm + wm * 32 + mt * 16 + (lane >> 2) + hf * 8;
                float v0 = acc[mt][nt][hf * 2 + 0] + bv0;
                float v1 = acc[mt][nt][hf * 2 + 1] + bv1;
                if (act) { v0 = gelu_f(v0); v1 = gelu_f(v1); }
                if (add) {
                    v0 += add[(size_t)row * N + col];
                    v1 += add[(size_t)row * N + col + 1];
                }
                if (atomic) {
                    atomicAdd(&C[(size_t)row * N + col], v0);
                    atomicAdd(&C[(size_t)row * N + col + 1], v1);
                } else if (C) {
                    *(float2*)&C[(size_t)row * N + col] = make_float2(v0, v1);
                }
                if (OH) {
                    __nv_bfloat16 h0 = __float2bfloat16_rn(v0);
                    __nv_bfloat16 h1 = __float2bfloat16_rn(v1);
                    __nv_bfloat16 l0 = __float2bfloat16_rn(v0 - __bfloat162float(h0));
                    __nv_bfloat16 l1 = __float2bfloat16_rn(v1 - __bfloat162float(h1));
                    *(__nv_bfloat162*)&OH[(size_t)row * N + col] = __nv_bfloat162(h0, h1);
                    *(__nv_bfloat162*)&OL[(size_t)row * N + col] = __nv_bfloat162(l0, l1);
                }
            }
        }
    }
}

__global__ void __launch_bounds__(256, 2)
bgemm_kernel(const __nv_bfloat16* __restrict__ Ah, const __nv_bfloat16* __restrict__ Al,
             const __nv_bfloat16* __restrict__ Wph, const __nv_bfloat16* __restrict__ Wpl,
             const float* __restrict__ bias, const float* __restrict__ add,
             float* __restrict__ C,
             __nv_bfloat16* __restrict__ OH, __nv_bfloat16* __restrict__ OL,
             int N, int K, int act) {
    extern __shared__ char sm[];
    bgemm_body(Ah, Al, Wph, Wpl, bias, add, C, OH, OL, N, K, act, sm,
               blockIdx.y * 64, blockIdx.x * 128, 0, K / BKB, 0);
}

// split-K variant: grid.z slices of K, atomicAdd accumulation (C pre-zeroed).
// bias/add applied only by z==0.
__global__ void __launch_bounds__(256, 2)
bgemm_sk_kernel(const __nv_bfloat16* __restrict__ Ah, const __nv_bfloat16* __restrict__ Al,
                const __nv_bfloat16* __restrict__ Wph, const __nv_bfloat16* __restrict__ Wpl,
                const float* __restrict__ bias, const float* __restrict__ add,
                float* __restrict__ C, int N, int K, int nsplit) {
    extern __shared__ char sm[];
    int z = blockIdx.z;
    int chunks = K / BKB;
    int per = chunks / nsplit;
    const float* bz = (z == 0) ? bias : nullptr;
    const float* az = (z == 0) ? add : nullptr;
    bgemm_body(Ah, Al, Wph, Wpl, bz, az, C, nullptr, nullptr, N, K, 0, sm,
               blockIdx.y * 64, blockIdx.x * 128, z * per, (z + 1) * per, 1);
}

struct QKV3 {
    const __nv_bfloat16 *wh0, *wl0, *wh1, *wl1, *wh2, *wl2;
    const float *b0, *b1, *b2;
    float *c0, *c1, *c2;
};

__global__ void __launch_bounds__(256, 2)
bgemm_qkv_kernel(const __nv_bfloat16* __restrict__ Ah, const __nv_bfloat16* __restrict__ Al,
                 QKV3 p, int N, int K) {
    extern __shared__ char sm[];
    int z = blockIdx.z;
    const __nv_bfloat16* wh = (z == 0) ? p.wh0 : (z == 1) ? p.wh1 : p.wh2;
    const __nv_bfloat16* wl = (z == 0) ? p.wl0 : (z == 1) ? p.wl1 : p.wl2;
    const float* bias = (z == 0) ? p.b0 : (z == 1) ? p.b1 : p.b2;
    float* C = (z == 0) ? p.c0 : (z == 1) ? p.c1 : p.c2;
    bgemm_body(Ah, Al, wh, wl, bias, nullptr, C, nullptr, nullptr, N, K, 0, sm,
               blockIdx.y * 64, blockIdx.x * 128, 0, K / BKB, 0);
}

// ---------------- fp32 SGEMM with optional split-K (skinny LoRA, N=120) ----------------
__global__ void gemm_kernel(const float* __restrict__ A, const float* __restrict__ W,
                            float* __restrict__ C, int N, int K, int nsplit) {
    __shared__ float As[16][64];
    __shared__ float Bs[16][64];
    int bm = blockIdx.y * 64, bn = blockIdx.x * 64;
    int kchunk = K / nsplit;
    int kbeg = blockIdx.z * kchunk;
    int kend = kbeg + kchunk;
    int tid = threadIdx.x;
    int tx = tid & 15, ty = tid >> 4;
    int lr = tid >> 2;
    int lc = (tid & 3) << 2;
    float acc[4][4] = {};
    const float* Aptr = A + (size_t)(bm + lr) * K + lc;
    int wrow = bn + lr;
    const float* Wptr = W + (size_t)wrow * K + lc;
    for (int k0 = kbeg; k0 < kend; k0 += 16) {
        float4 a4 = *(const float4*)(Aptr + k0);
        float4 b4 = (wrow < N) ? *(const float4*)(Wptr + k0) : make_float4(0.f, 0.f, 0.f, 0.f);
        As[lc + 0][lr] = a4.x; As[lc + 1][lr] = a4.y; As[lc + 2][lr] = a4.z; As[lc + 3][lr] = a4.w;
        Bs[lc + 0][lr] = b4.x; Bs[lc + 1][lr] = b4.y; Bs[lc + 2][lr] = b4.z; Bs[lc + 3][lr] = b4.w;
        __syncthreads();
#pragma unroll
        for (int kk = 0; kk < 16; kk++) {
            float4 ra = *(const float4*)&As[kk][ty << 2];
            float4 rb = *(const float4*)&Bs[kk][tx << 2];
            float raa[4] = {ra.x, ra.y, ra.z, ra.w};
            float rbb[4] = {rb.x, rb.y, rb.z, rb.w};
#pragma unroll
            for (int i = 0; i < 4; i++)
#pragma unroll
                for (int j = 0; j < 4; j++)
                    acc[i][j] += raa[i] * rbb[j];
        }
        __syncthreads();
    }
#pragma unroll
    for (int i = 0; i < 4; i++) {
        int m = bm + (ty << 2) + i;
#pragma unroll
        for (int j = 0; j < 4; j++) {
            int n = bn + (tx << 2) + j;
            if (n < N) {
                if (nsplit > 1) atomicAdd(&C[(size_t)m * N + n], acc[i][j]);
                else C[(size_t)m * N + n] = acc[i][j];
            }
        }
    }
}

// ---------------- attention ----------------
__global__ void attn_kernel() {
    int bh = blockIdx.x;
    int b = bh / NHD, hh = bh - b * NHD;
    __shared__ float sq[SS][HD], sk[SS][HD], sv[SS][HD], sc[SS][SS + 1];
    int tid = threadIdx.x;
    int base = b * SS;
    for (int i = tid; i < SS * HD; i += 256) {
        int s = i >> 6, d = i & 63;
        int gi = (base + s) * HH + hh * HD + d;
        sq[s][d] = g_q[gi]; sk[s][d] = g_k[gi]; sv[s][d] = g_v[gi];
    }
    __syncthreads();
    for (int i = tid; i < SS * SS; i += 256) {
        int r = i / SS, c = i - r * SS;
        float s = 0.f;
#pragma unroll
        for (int d = 0; d < HD; d++) s += sq[r][d] * sk[c][d];
        sc[r][c] = s * 0.125f;
    }
    __syncthreads();
    if (tid < SS) {
        float mx = -1e30f;
        for (int c = 0; c < SS; c++) mx = fmaxf(mx, sc[tid][c]);
        float sm = 0.f;
        for (int c = 0; c < SS; c++) { float e = expf(sc[tid][c] - mx); sc[tid][c] = e; sm += e; }
        float inv = 1.0f / sm;
        for (int c = 0; c < SS; c++) sc[tid][c] *= inv;
    }
    __syncthreads();
    for (int i = tid; i < SS * HD; i += 256) {
        int s = i >> 6, d = i & 63;
        float o = 0.f;
#pragma unroll
        for (int c = 0; c < SS; c++) o += sc[s][c] * sv[c][d];
        int gi = (base + s) * HH + hh * HD + d;
        __nv_bfloat16 hv = __float2bfloat16_rn(o);
        g_ctxh[gi] = hv;
        g_ctxl[gi] = __float2bfloat16_rn(o - __bfloat162float(hv));
    }
}

// ---------------- per-disease classifiers -> gate[b,d] ----------------
__global__ void cls_kernel(const float* __restrict__ mask,
                           const float* __restrict__ cw1, const float* __restrict__ cb1,
                           const float* __restrict__ clg, const float* __restrict__ clb,
                           const float* __restrict__ cw2, const float* __restrict__ cb2) {
    int b = blockIdx.x, d = blockIdx.y;
    int tid = threadIdx.x, lane = tid & 31, w = tid >> 5;
    __shared__ __align__(16) float pooled[HH];
    __shared__ float h1[384];
    __shared__ float r1[256], r2[256];
    float cnt = 0.f;
    for (int r = 0; r < RR; r++) cnt += (mask[r * DD + d] > 0.f) ? 1.f : 0.f;
    float inv = 1.0f / fmaxf(cnt, 1.0f);
    for (int j = tid; j < HH; j += 256) {
        float s = 0.f;
        for (int r = 0; r < RR; r++)
            if (mask[r * DD + d] > 0.f) s += g_att[(b * SS + 1 + r) * HH + j];
        pooled[j] = s * inv;
    }
    __syncthreads();
    for (int k = w; k < 384; k += 8) {
        const float4* row = (const float4*)(cw1 + ((size_t)d * 384 + k) * HH);
        const float4* pp = (const float4*)pooled;
        float s = 0.f;
#pragma unroll
        for (int i = 0; i < 6; i++) {
            int f = lane + 32 * i;
            float4 a = row[f];
            float4 p = pp[f];
            s += a.x * p.x + a.y * p.y + a.z * p.z + a.w * p.w;
        }
#pragma unroll
        for (int o = 16; o; o >>= 1) s += __shfl_xor_sync(0xFFFFFFFFu, s, o);
        if (lane == 0) h1[k] = s + cb1[d * 384 + k];
    }
    __syncthreads();
    float a = 0.f, sq = 0.f;
    for (int k = tid; k < 384; k += 256) { float v = h1[k]; a += v; sq += v * v; }
    r1[tid] = a; r2[tid] = sq;
    __syncthreads();
    for (int o = 128; o > 0; o >>= 1) {
        if (tid < o) { r1[tid] += r1[tid + o]; r2[tid] += r2[tid + o]; }
        __syncthreads();
    }
    float mean = r1[0] * (1.0f / 384.0f);
    float var = r2[0] * (1.0f / 384.0f) - mean * mean;
    float rn = rsqrtf(var + 1e-5f);
    __syncthreads();
    float p = 0.f;
    for (int k = tid; k < 384; k += 256) {
        float v = (h1[k] - mean) * rn * clg[d * 384 + k] + clb[d * 384 + k];
        v = gelu_f(v);
        p += v * cw2[d * 384 + k];
    }
    r1[tid] = p;
    __syncthreads();
    for (int o = 128; o > 0; o >>= 1) {
        if (tid < o) r1[tid] += r1[tid + o];
        __syncthreads();
    }
    if (tid == 0) {
        float pred = r1[0] + cb2[d];
        g_gate[b * DD + d] = (cnt > 0.f && pred > 0.f) ? 1.f : 0.f;
    }
}

// ---------------- M[ei][e] = Bu^T @ Ad^T for ALL even layers (grid.z = ei) ----------------
__global__ void m_kernel(const float* __restrict__ bu, const float* __restrict__ ad) {
    int e = blockIdx.x, c = blockIdx.y, ei = blockIdx.z;
    int tid = threadIdx.x;
    float s[LRK] = {};
    const float* bup = bu + ((size_t)ei * EE + e) * II * LRK;
    const float* adp = ad + (((size_t)ei * EE + e) * LRK + c) * II;
    for (int i = tid; i < II; i += 256) {
        float a = adp[i];
        const float* bp = bup + (size_t)i * LRK;
#pragma unroll
        for (int r = 0; r < LRK; r++) s[r] += bp[r] * a;
    }
    __shared__ float red[256];
    for (int r = 0; r < LRK; r++) {
        red[tid] = s[r];
        __syncthreads();
        for (int o = 128; o > 0; o >>= 1) {
            if (tid < o) red[tid] += red[tid + o];
            __syncthreads();
        }
        if (tid == 0) g_M[((size_t)ei * EE + e) * LRK * LRK + r * LRK + c] = red[0];
        __syncthreads();
    }
}

// ---------------- expert mix: warp per token, fused next-layer LN1 ----------------
__global__ void comb_kernel(const float* __restrict__ bd, const float* __restrict__ mask,
                            const float* __restrict__ lng, const float* __restrict__ lnb,
                            const float* __restrict__ Mp) {
    int tid = threadIdx.x, lane = tid & 31, w = tid >> 5;
    int token = blockIdx.x * 8 + w;
    int b = token / SS, s = token - b * SS;
    __shared__ __align__(16) float sU[8][ELR];
    __shared__ __align__(16) float sT[8][ELR];

#pragma unroll
    for (int k = 0; k < 4; k++) {
        int er = lane + 32 * k;
        if (er < ELR) sU[w][er] = g_uv[(size_t)token * ELR + er];
    }
    __syncwarp();
#pragma unroll
    for (int k = 0; k < 4; k++) {
        int er = lane + 32 * k;
        if (er < ELR) {
            int e = er >> 3, r = er & 7;
            float acc = 0.f;
#pragma unroll
            for (int q = 0; q < LRK; q++)
                acc += sU[w][e * LRK + q] * Mp[(e * LRK + q) * LRK + r];
            sT[w][er] = g_uv[(size_t)(TN + token) * ELR + er] + SCALF * acc;
        }
    }
    __syncwarp();

    float sw[EE];
    float nact = 0.f;
#pragma unroll
    for (int e = 0; e < DD; e++) {
        float a = (s > 0 && mask[(s - 1) * DD + e] > 0.f) ? g_gate[b * DD + e] : 0.f;
        sw[e] = a; nact += a;
    }
    sw[14] = 1.f; nact += 1.f;
    float wt = 1.0f / fmaxf(nact, 1.0f);

    float bo[24], acc[24];
    const float4* bop = (const float4*)(g_bout + (size_t)token * HH);
#pragma unroll
    for (int i = 0; i < 6; i++) {
        float4 v = bop[lane + 32 * i];
        bo[4 * i] = v.x; bo[4 * i + 1] = v.y; bo[4 * i + 2] = v.z; bo[4 * i + 3] = v.w;
        acc[4 * i] = 0.f; acc[4 * i + 1] = 0.f; acc[4 * i + 2] = 0.f; acc[4 * i + 3] = 0.f;
    }

    for (int e = 0; e < EE; e++) {
        float wgt = sw[e] * wt;
        float t8[8];
#pragma unroll
        for (int r = 0; r < 8; r++) t8[r] = sT[w][e * LRK + r];
        float o[24];
        float sm = 0.f, sq = 0.f;
#pragma unroll
        for (int i = 0; i < 6; i++) {
            int f = lane + 32 * i;
            const float4* bdp = (const float4*)(bd + ((size_t)e * HH + 4 * f) * LRK);
#pragma unroll
            for (int c = 0; c < 4; c++) {
                float4 p0 = bdp[2 * c];
                float4 p1 = bdp[2 * c + 1];
                float dv = p0.x * t8[0] + p0.y * t8[1] + p0.z * t8[2] + p0.w * t8[3]
                         + p1.x * t8[4] + p1.y * t8[5] + p1.z * t8[6] + p1.w * t8[7];
                float ov = bo[4 * i + c] + SCALF * dv;
                o[4 * i + c] = ov;
                sm += ov; sq += ov * ov;
            }
        }
#pragma unroll
        for (int off = 16; off; off >>= 1) {
            sm += __shfl_xor_sync(0xFFFFFFFFu, sm, off);
            sq += __shfl_xor_sync(0xFFFFFFFFu, sq, off);
        }
        float mean = sm * (1.0f / 768.0f);
        float var = sq * (1.0f / 768.0f) - mean * mean;
        float rn = rsqrtf(var + 1e-5f);
        float wr = wgt * rn;
#pragma unroll
        for (int i = 0; i < 24; i++) acc[i] += wr * (o[i] - mean);
    }

    const float4* rp = (const float4*)(g_res1 + (size_t)token * HH);
    float4* hp = (float4*)(g_h + (size_t)token * HH);
    float hv4[24];
    float s2 = 0.f, sq2 = 0.f;
#pragma unroll
    for (int i = 0; i < 6; i++) {
        float4 r = rp[lane + 32 * i];
        float h0 = acc[4 * i] + r.x, h1 = acc[4 * i + 1] + r.y;
        float h2 = acc[4 * i + 2] + r.z, h3 = acc[4 * i + 3] + r.w;
        hp[lane + 32 * i] = make_float4(h0, h1, h2, h3);
        hv4[4 * i] = h0; hv4[4 * i + 1] = h1; hv4[4 * i + 2] = h2; hv4[4 * i + 3] = h3;
        s2 += h0 + h1 + h2 + h3;
        sq2 += h0 * h0 + h1 * h1 + h2 * h2 + h3 * h3;
    }
#pragma unroll
    for (int o = 16; o; o >>= 1) {
        s2 += __shfl_xor_sync(0xFFFFFFFFu, s2, o);
        sq2 += __shfl_xor_sync(0xFFFFFFFFu, sq2, o);
    }
    float mean = s2 * (1.0f / 768.0f);
    float var = sq2 * (1.0f / 768.0f) - mean * mean;
    float r = rsqrtf(var + 1e-12f);
    __nv_bfloat162* ohp = (__nv_bfloat162*)(g_nxh + (size_t)token * HH);
    __nv_bfloat162* olp = (__nv_bfloat162*)(g_nxl + (size_t)token * HH);
#pragma unroll
    for (int i = 0; i < 6; i++) {
        int f = lane + 32 * i;
        float4 gv = ((const float4*)lng)[f];
        float4 bv = ((const float4*)lnb)[f];
        float y0 = (hv4[4 * i] - mean) * r * gv.x + bv.x;
        float y1 = (hv4[4 * i + 1] - mean) * r * gv.y + bv.y;
        float y2 = (hv4[4 * i + 2] - mean) * r * gv.z + bv.z;
        float y3 = (hv4[4 * i + 3] - mean) * r * gv.w + bv.w;
        __nv_bfloat16 h0 = __float2bfloat16_rn(y0), h1 = __float2bfloat16_rn(y1);
        __nv_bfloat16 h2 = __float2bfloat16_rn(y2), h3 = __float2bfloat16_rn(y3);
        ohp[2 * f] = __nv_bfloat162(h0, h1);
        ohp[2 * f + 1] = __nv_bfloat162(h2, h3);
        olp[2 * f] = __nv_bfloat162(__float2bfloat16_rn(y0 - __bfloat162float(h0)),
                                    __float2bfloat16_rn(y1 - __bfloat162float(h1)));
        olp[2 * f + 1] = __nv_bfloat162(__float2bfloat16_rn(y2 - __bfloat162float(h2)),
                                        __float2bfloat16_rn(y3 - __bfloat162float(h3)));
    }
}

// ---------------- host launcher ----------------
extern "C" void kernel_launch(void* const* d_in, const int* in_sizes, int n_in,
                              void* d_out, int out_size) {
    const float* rf   = (const float*)d_in[0];
    const float* cls  = (const float*)d_in[1];
    const float* ln1g = (const float*)d_in[2];
    const float* ln1b = (const float*)d_in[3];
    const float* ln2g = (const float*)d_in[4];
    const float* ln2b = (const float*)d_in[5];
    const float* wq   = (const float*)d_in[6];
    const float* bq   = (const float*)d_in[7];
    const float* wk   = (const float*)d_in[8];
    const float* bk   = (const float*)d_in[9];
    const float* wv   = (const float*)d_in[10];
    const float* bv   = (const float*)d_in[11];
    const float* wo   = (const float*)d_in[12];
    const float* bo   = (const float*)d_in[13];
    const float* wi   = (const float*)d_in[14];
    const float* bi   = (const float*)d_in[15];
    const float* wof  = (const float*)d_in[16];
    const float* bof  = (const float*)d_in[17];
    const float* lnfg = (const float*)d_in[18];
    const float* lnfb = (const float*)d_in[19];
    const float* au   = (const float*)d_in[20];
    const float* bu   = (const float*)d_in[21];
    const float* ad   = (const float*)d_in[22];
    const float* bd   = (const float*)d_in[23];
    const float* cw1  = (const float*)d_in[24];
    const float* cb1  = (const float*)d_in[25];
    const float* clg  = (const float*)d_in[26];
    const float* clb  = (const float*)d_in[27];
    const float* cw2  = (const float*)d_in[28];
    const float* cb2  = (const float*)d_in[29];
    const float* maskp= (const float*)d_in[30];
    float* out = (float*)d_out;

    float *h, *q, *k, *v, *att, *res1, *nres, *hid, *bout, *uv, *Mbase;
    cudaGetSymbolAddress((void**)&h,    g_h);
    cudaGetSymbolAddress((void**)&q,    g_q);
    cudaGetSymbolAddress((void**)&k,    g_k);
    cudaGetSymbolAddress((void**)&v,    g_v);
    cudaGetSymbolAddress((void**)&att,  g_att);
    cudaGetSymbolAddress((void**)&res1, g_res1);
    cudaGetSymbolAddress((void**)&nres, g_nres);
    cudaGetSymbolAddress((void**)&hid,  g_hid);
    cudaGetSymbolAddress((void**)&bout, g_bout);
    cudaGetSymbolAddress((void**)&uv,   g_uv);
    cudaGetSymbolAddress((void**)&Mbase, g_M);

    __nv_bfloat16 *nxh, *nxl, *nresh, *nresl, *ctxh, *ctxl, *hidh, *hidl;
    __nv_bfloat16 *wqh, *wql, *wkh, *wkl, *wvh, *wvl, *woh, *wol, *wih, *wil, *wofh, *wofl;
    cudaGetSymbolAddress((void**)&nxh,   g_nxh);
    cudaGetSymbolAddress((void**)&nxl,   g_nxl);
    cudaGetSymbolAddress((void**)&nresh, g_nresh);
    cudaGetSymbolAddress((void**)&nresl, g_nresl);
    cudaGetSymbolAddress((void**)&ctxh,  g_ctxh);
    cudaGetSymbolAddress((void**)&ctxl,  g_ctxl);
    cudaGetSymbolAddress((void**)&hidh,  g_hidh);
    cudaGetSymbolAddress((void**)&hidl,  g_hidl);
    cudaGetSymbolAddress((void**)&wqh,   g_wqh);
    cudaGetSymbolAddress((void**)&wql,   g_wql);
    cudaGetSymbolAddress((void**)&wkh,   g_wkh);
    cudaGetSymbolAddress((void**)&wkl,   g_wkl);
    cudaGetSymbolAddress((void**)&wvh,   g_wvh);
    cudaGetSymbolAddress((void**)&wvl,   g_wvl);
    cudaGetSymbolAddress((void**)&woh,   g_woh);
    cudaGetSymbolAddress((void**)&wol,   g_wol);
    cudaGetSymbolAddress((void**)&wih,   g_wih);
    cudaGetSymbolAddress((void**)&wil,   g_wil);
    cudaGetSymbolAddress((void**)&wofh,  g_wofh);
    cudaGetSymbolAddress((void**)&wofl,  g_wofl);

    cudaFuncSetAttribute(bgemm_kernel, cudaFuncAttributeMaxDynamicSharedMemorySize, SMEMB);
    cudaFuncSetAttribute(bgemm_qkv_kernel, cudaFuncAttributeMaxDynamicSharedMemorySize, SMEMB);
    cudaFuncSetAttribute(bgemm_sk_kernel, cudaFuncAttributeMaxDynamicSharedMemorySize, SMEMB);

    wsplit_all_kernel<<<16384, 256>>>(wq, wk, wv, wo, wi, wof);
    // precompute all even-layer LoRA M matrices once
    dim3 gm(EE, LRK, NE);
    m_kernel<<<gm, 256>>>(bu, ad);

    dim3 b768(HH / 128, TN / 64);        // 6 x 60
    dim3 bqkv(HH / 128, TN / 64, 3);     // 6 x 60 x 3
    dim3 b3072(II / 128, TN / 64);       // 24 x 60
    dim3 bwof(HH / 128, TN / 64, 4);     // 6 x 60 x 4 (split-K)
    dim3 gu(2, TN / 64, 2);
    dim3 gv(2, TN / 64, 4);
    int nel = TN * HH;
    int nblk = (nel + 255) / 256;
    int lnblk = TN / 8;                  // 480

    embed_kernel<<<nblk, 256>>>(rf, cls);

    for (int i = 0; i < LL; i++) {
        size_t woff  = (size_t)i * HH * HH;
        size_t wioff = (size_t)i * II * HH;
        int even = ((i & 1) == 0);
        if (even) {
            ln_kernel<<<lnblk, 256>>>(h, nullptr, nullptr, nullptr, nxh, nxl,
                                      ln1g + i * HH, ln1b + i * HH, 1e-12f);
        }
        QKV3 p;
        p.wh0 = wqh + woff; p.wl0 = wql + woff;
        p.wh1 = wkh + woff; p.wl1 = wkl + woff;
        p.wh2 = wvh + woff; p.wl2 = wvl + woff;
        p.b0 = bq + i * HH; p.b1 = bk + i * HH; p.b2 = bv + i * HH;
        p.c0 = q; p.c1 = k; p.c2 = v;
        bgemm_qkv_kernel<<<bqkv, 256, SMEMB>>>(nxh, nxl, p, HH, HH);
        attn_kernel<<<BQ * NHD, 256>>>();
        bgemm_kernel<<<b768, 256, SMEMB>>>(ctxh, ctxl, woh + woff, wol + woff, bo + i * HH,
                                           nullptr, att, nullptr, nullptr, HH, HH, 0);
        ln_kernel<<<lnblk, 256>>>(att, h, res1, even ? nres : nullptr, nresh, nresl,
                                  ln2g + i * HH, ln2b + i * HH, 1e-12f);
        bgemm_kernel<<<b3072, 256, SMEMB>>>(nresh, nresl, wih + wioff, wil + wioff, bi + i * II,
                                            nullptr, even ? hid : nullptr, hidh, hidl, II, HH, 1);
        if (!even) {
            // wof split-K4: h = bof + res1 + hid @ wof^T  (atomic accumulate)
            cudaMemsetAsync(h, 0, (size_t)TN * HH * sizeof(float));
            bgemm_sk_kernel<<<bwof, 256, SMEMB>>>(hidh, hidl, wofh + wioff, wofl + wioff,
                                                  bof + i * HH, res1, h, HH, II, 4);
        } else {
            int ei = i / 2;
            cudaMemsetAsync(bout, 0, (size_t)TN * HH * sizeof(float));
            bgemm_sk_kernel<<<bwof, 256, SMEMB>>>(hidh, hidl, wofh + wioff, wofl + wioff,
                                                  bof + i * HH, nullptr, bout, HH, II, 4);
            dim3 gc(BQ, DD);
            cls_kernel<<<gc, 256>>>(maskp,
                                    cw1 + (size_t)ei * DD * 384 * HH,
                                    cb1 + (size_t)ei * DD * 384,
                                    clg + (size_t)ei * DD * 384,
                                    clb + (size_t)ei * DD * 384,
                                    cw2 + (size_t)ei * DD * 384,
                                    cb2 + (size_t)ei * DD);
            cudaMemsetAsync(uv, 0, (size_t)2 * TN * ELR * sizeof(float));
            gemm_kernel<<<gu, 256>>>(nres, au + (size_t)ei * EE * LRK * HH, uv, ELR, HH, 2);
            gemm_kernel<<<gv, 256>>>(hid, ad + (size_t)ei * EE * LRK * II, uv + (size_t)TN * ELR, ELR, II, 4);
            comb_kernel<<<lnblk, 256>>>(bd + (size_t)ei * EE * HH * LRK, maskp,
                                        ln1g + (i + 1) * HH, ln1b + (i + 1) * HH,
                                        Mbase + (size_t)ei * EE * LRK * LRK);
        }
    }
    ln_kernel<<<lnblk, 256>>>(h, nullptr, nullptr, out, nullptr, nullptr, lnfg, lnfb, 1e-12f);
}